// round 5
// baseline (speedup 1.0000x reference)
#include <cuda_runtime.h>

#define NROWS 100000
#define CH 256
#define BM 64
#define BK 8
#define ASTR (BM + 4)          // 68: 16B-aligned rows (68*4=272=17*16), conflict-free stores
#define NTHR 256
#define MBLK ((NROWS + BM - 1) / BM)
#define S_SLICES 37
#define ROWS_PER 2704

// ---------------- scratch (static device globals; no allocation) ------------
__device__ float g_h [(size_t)NROWS * CH];
__device__ float g_h2[(size_t)NROWS * CH];
__device__ float g_q [(size_t)NROWS * CH];
__device__ float g_k [(size_t)NROWS * CH];
__device__ float g_v [(size_t)NROWS * CH];
__device__ float g_part[(size_t)S_SLICES * CH * CH];
__device__ float g_kvs[CH * CH];
__device__ float g_scal[CH + 4];   // [0]=||q||^2 [1]=||k||^2 [4..259]=col-sums of k

__device__ __forceinline__ float wred(float v) {
#pragma unroll
  for (int o = 16; o > 0; o >>= 1) v += __shfl_xor_sync(0xffffffffu, v, o);
  return v;
}

// ---------------------------------------------------------------------------
// C[r, j] = sum_k A[r,k] * W[j,k] + bias[j]   (NT gemm, K = CH = 256, BN = 256)
// warp w owns rows m0 + w*8 .. +7 ; lane l owns cols l*8 .. +7
// ---------------------------------------------------------------------------
template<bool LNE, bool NORM, bool COLSUM>
__global__ void __launch_bounds__(NTHR) gemm_nt(
    const float* __restrict__ A, const float* __restrict__ W,
    const float* __restrict__ bias, float* __restrict__ C,
    const float* __restrict__ gamma, const float* __restrict__ beta,
    float* __restrict__ normAcc, float* __restrict__ colAcc)
{
  __shared__ float As[BK][ASTR];
  __shared__ float Bs[BK][CH];
  __shared__ float sCol[CH];
  __shared__ float sRed[8];

  const int tid = threadIdx.x, w = tid >> 5, l = tid & 31;
  const int m0 = blockIdx.x * BM;

  if (COLSUM && tid < CH) sCol[tid] = 0.f;

  const int arow = tid >> 2;
  const int akk  = (tid & 3) * 2;
  const bool aval = (m0 + arow) < NROWS;
  const float* Aptr = A + (size_t)(m0 + arow) * CH + akk;
  const float* Wptr = W + (size_t)tid * CH;

  float acc[8][8];
#pragma unroll
  for (int i = 0; i < 8; i++)
#pragma unroll
    for (int j = 0; j < 8; j++) acc[i][j] = 0.f;

  float2 aR = aval ? *(const float2*)Aptr : make_float2(0.f, 0.f);
  float4 bR0 = *(const float4*)(Wptr);
  float4 bR1 = *(const float4*)(Wptr + 4);

  for (int k0 = 0; k0 < CH; k0 += BK) {
    __syncthreads();
    As[akk][arow]     = aR.x;
    As[akk + 1][arow] = aR.y;
    Bs[0][tid] = bR0.x; Bs[1][tid] = bR0.y; Bs[2][tid] = bR0.z; Bs[3][tid] = bR0.w;
    Bs[4][tid] = bR1.x; Bs[5][tid] = bR1.y; Bs[6][tid] = bR1.z; Bs[7][tid] = bR1.w;
    __syncthreads();
    if (k0 + BK < CH) {
      aR  = aval ? *(const float2*)(Aptr + k0 + BK) : make_float2(0.f, 0.f);
      bR0 = *(const float4*)(Wptr + k0 + BK);
      bR1 = *(const float4*)(Wptr + k0 + BK + 4);
    }
#pragma unroll
    for (int kk = 0; kk < BK; kk++) {
      float a[8], b[8];
      float4 a0 = *(const float4*)&As[kk][w * 8];
      float4 a1 = *(const float4*)&As[kk][w * 8 + 4];
      a[0]=a0.x; a[1]=a0.y; a[2]=a0.z; a[3]=a0.w;
      a[4]=a1.x; a[5]=a1.y; a[6]=a1.z; a[7]=a1.w;
      float4 b0 = *(const float4*)&Bs[kk][l * 8];
      float4 b1 = *(const float4*)&Bs[kk][l * 8 + 4];
      b[0]=b0.x; b[1]=b0.y; b[2]=b0.z; b[3]=b0.w;
      b[4]=b1.x; b[5]=b1.y; b[6]=b1.z; b[7]=b1.w;
#pragma unroll
      for (int i = 0; i < 8; i++)
#pragma unroll
        for (int j = 0; j < 8; j++)
          acc[i][j] = fmaf(a[i], b[j], acc[i][j]);
    }
  }

  // ---------------- epilogue ----------------
  float bf[8];
  { float4 t0 = *(const float4*)&bias[l*8]; float4 t1 = *(const float4*)&bias[l*8+4];
    bf[0]=t0.x; bf[1]=t0.y; bf[2]=t0.z; bf[3]=t0.w;
    bf[4]=t1.x; bf[5]=t1.y; bf[6]=t1.z; bf[7]=t1.w; }
  float gf[8], btf[8];
  if (LNE) {
    float4 t0 = *(const float4*)&gamma[l*8]; float4 t1 = *(const float4*)&gamma[l*8+4];
    gf[0]=t0.x; gf[1]=t0.y; gf[2]=t0.z; gf[3]=t0.w;
    gf[4]=t1.x; gf[5]=t1.y; gf[6]=t1.z; gf[7]=t1.w;
    float4 u0 = *(const float4*)&beta[l*8];  float4 u1 = *(const float4*)&beta[l*8+4];
    btf[0]=u0.x; btf[1]=u0.y; btf[2]=u0.z; btf[3]=u0.w;
    btf[4]=u1.x; btf[5]=u1.y; btf[6]=u1.z; btf[7]=u1.w;
  }

  float nrm = 0.f;
  float colp[8];
#pragma unroll
  for (int j = 0; j < 8; j++) colp[j] = 0.f;

#pragma unroll
  for (int i = 0; i < 8; i++) {
    const int r = m0 + w * 8 + i;
    const bool valid = r < NROWS;
#pragma unroll
    for (int j = 0; j < 8; j++) acc[i][j] += bf[j];
    if (NORM && valid) {
#pragma unroll
      for (int j = 0; j < 8; j++) nrm = fmaf(acc[i][j], acc[i][j], nrm);
    }
    if (COLSUM && valid) {
#pragma unroll
      for (int j = 0; j < 8; j++) colp[j] += acc[i][j];
    }
    if (LNE) {
      float s1 = 0.f, s2 = 0.f;
#pragma unroll
      for (int j = 0; j < 8; j++) { s1 += acc[i][j]; s2 = fmaf(acc[i][j], acc[i][j], s2); }
      s1 = wred(s1); s2 = wred(s2);
      const float mu = s1 * (1.f / CH);
      const float rs = rsqrtf(s2 * (1.f / CH) - mu * mu + 1e-5f);
#pragma unroll
      for (int j = 0; j < 8; j++) {
        float vv = (acc[i][j] - mu) * rs * gf[j] + btf[j];
        acc[i][j] = fmaxf(vv, 0.f);
      }
    }
    if (valid) {
      float4 o0 = make_float4(acc[i][0], acc[i][1], acc[i][2], acc[i][3]);
      float4 o1 = make_float4(acc[i][4], acc[i][5], acc[i][6], acc[i][7]);
      *(float4*)&C[(size_t)r * CH + l * 8]     = o0;
      *(float4*)&C[(size_t)r * CH + l * 8 + 4] = o1;
    }
  }

  if (NORM) {
    float p = wred(nrm);
    if (l == 0) sRed[w] = p;
    __syncthreads();
    if (tid == 0) {
      float s = 0.f;
#pragma unroll
      for (int i = 0; i < 8; i++) s += sRed[i];
      atomicAdd(normAcc, s);
    }
  }
  if (COLSUM) {
#pragma unroll
    for (int j = 0; j < 8; j++) atomicAdd(&sCol[l * 8 + j], colp[j]);
    __syncthreads();
    if (tid < CH) atomicAdd(&colAcc[tid], sCol[tid]);
  }
}

// ---------------------------------------------------------------------------
// part[s][m][d] = sum over rows n in slice s of K[n,m] * V[n,d]
// ---------------------------------------------------------------------------
__global__ void __launch_bounds__(NTHR) kvs_kernel(
    const float* __restrict__ K, const float* __restrict__ V,
    float* __restrict__ part)
{
  __shared__ float As[BK][ASTR];
  __shared__ float Bs[BK][CH];

  const int tid = threadIdx.x, w = tid >> 5, l = tid & 31;
  const int m0 = blockIdx.x * BM;
  const int n0 = blockIdx.y * ROWS_PER;

  const int akk = tid >> 5;            // 0..7
  const int am  = (tid & 31) * 2;      // 0..62
  const int bkk = tid >> 5;
  const int bc  = (tid & 31) * 8;

  float acc[8][8];
#pragma unroll
  for (int i = 0; i < 8; i++)
#pragma unroll
    for (int j = 0; j < 8; j++) acc[i][j] = 0.f;

  float2 aR; float4 bR0, bR1;
  {
    int n = n0 + akk;
    aR  = (n < NROWS) ? *(const float2*)&K[(size_t)n * CH + m0 + am] : make_float2(0.f, 0.f);
    if (n < NROWS) { bR0 = *(const float4*)&V[(size_t)n * CH + bc];
                     bR1 = *(const float4*)&V[(size_t)n * CH + bc + 4]; }
    else { bR0 = make_float4(0,0,0,0); bR1 = make_float4(0,0,0,0); }
  }

  for (int k0 = 0; k0 < ROWS_PER; k0 += BK) {
    __syncthreads();
    As[akk][am]     = aR.x;
    As[akk][am + 1] = aR.y;
    *(float4*)&Bs[bkk][bc]     = bR0;
    *(float4*)&Bs[bkk][bc + 4] = bR1;
    __syncthreads();
    if (k0 + BK < ROWS_PER) {
      int n = n0 + k0 + BK + akk;
      aR = (n < NROWS) ? *(const float2*)&K[(size_t)n * CH + m0 + am] : make_float2(0.f, 0.f);
      int nb = n0 + k0 + BK + bkk;
      if (nb < NROWS) { bR0 = *(const float4*)&V[(size_t)nb * CH + bc];
                        bR1 = *(const float4*)&V[(size_t)nb * CH + bc + 4]; }
      else { bR0 = make_float4(0,0,0,0); bR1 = make_float4(0,0,0,0); }
    }
#pragma unroll
    for (int kk = 0; kk < BK; kk++) {
      float a[8], b[8];
      float4 a0 = *(const float4*)&As[kk][w * 8];
      float4 a1 = *(const float4*)&As[kk][w * 8 + 4];
      a[0]=a0.x; a[1]=a0.y; a[2]=a0.z; a[3]=a0.w;
      a[4]=a1.x; a[5]=a1.y; a[6]=a1.z; a[7]=a1.w;
      float4 b0 = *(const float4*)&Bs[kk][l * 8];
      float4 b1 = *(const float4*)&Bs[kk][l * 8 + 4];
      b[0]=b0.x; b[1]=b0.y; b[2]=b0.z; b[3]=b0.w;
      b[4]=b1.x; b[5]=b1.y; b[6]=b1.z; b[7]=b1.w;
#pragma unroll
      for (int i = 0; i < 8; i++)
#pragma unroll
        for (int j = 0; j < 8; j++)
          acc[i][j] = fmaf(a[i], b[j], acc[i][j]);
    }
  }

  float* dst = part + (size_t)blockIdx.y * CH * CH;
#pragma unroll
  for (int i = 0; i < 8; i++) {
    int m = m0 + w * 8 + i;
    float4 o0 = make_float4(acc[i][0], acc[i][1], acc[i][2], acc[i][3]);
    float4 o1 = make_float4(acc[i][4], acc[i][5], acc[i][6], acc[i][7]);
    *(float4*)&dst[(size_t)m * CH + l * 8]     = o0;
    *(float4*)&dst[(size_t)m * CH + l * 8 + 4] = o1;
  }
}

__global__ void kvs_reduce(const float* __restrict__ part, float* __restrict__ kvs) {
  int idx = blockIdx.x * blockDim.x + threadIdx.x;
  if (idx < CH * CH) {
    float s = 0.f;
#pragma unroll
    for (int ss = 0; ss < S_SLICES; ss++) s += part[(size_t)ss * CH * CH + idx];
    kvs[idx] = s;
  }
}

__global__ void zero_kernel(float* p, int n) {
  int i = blockIdx.x * blockDim.x + threadIdx.x;
  if (i < n) p[i] = 0.f;
}

// ---------------------------------------------------------------------------
// out = ReLU(LN(0.5*attn + 0.5*prev)),
// attn = (c * (Q@KVS) + n*V) / (c * (Q . ks_sum) + n),  c = rsqrt(||q||^2 ||k||^2)
// ---------------------------------------------------------------------------
__global__ void __launch_bounds__(NTHR) attn_kernel(
    const float* __restrict__ Q, const float* __restrict__ KVS,
    const float* __restrict__ V, const float* __restrict__ P,
    const float* __restrict__ scal,
    const float* __restrict__ gamma, const float* __restrict__ beta,
    float* __restrict__ Cout)
{
  __shared__ float As[BK][ASTR];
  __shared__ float Bs[BK][CH];

  const int tid = threadIdx.x, w = tid >> 5, l = tid & 31;
  const int m0 = blockIdx.x * BM;

  const int arow = tid >> 2;
  const int akk  = (tid & 3) * 2;
  const bool aval = (m0 + arow) < NROWS;
  const float* Aptr = Q + (size_t)(m0 + arow) * CH + akk;
  const int bkk = tid >> 5;
  const int bc  = (tid & 31) * 8;

  float acc[8][8];
#pragma unroll
  for (int i = 0; i < 8; i++)
#pragma unroll
    for (int j = 0; j < 8; j++) acc[i][j] = 0.f;

  float2 aR = aval ? *(const float2*)Aptr : make_float2(0.f, 0.f);
  float4 bR0 = *(const float4*)&KVS[(size_t)bkk * CH + bc];
  float4 bR1 = *(const float4*)&KVS[(size_t)bkk * CH + bc + 4];

  for (int k0 = 0; k0 < CH; k0 += BK) {
    __syncthreads();
    As[akk][arow]     = aR.x;
    As[akk + 1][arow] = aR.y;
    *(float4*)&Bs[bkk][bc]     = bR0;
    *(float4*)&Bs[bkk][bc + 4] = bR1;
    __syncthreads();
    if (k0 + BK < CH) {
      aR  = aval ? *(const float2*)(Aptr + k0 + BK) : make_float2(0.f, 0.f);
      bR0 = *(const float4*)&KVS[(size_t)(k0 + BK + bkk) * CH + bc];
      bR1 = *(const float4*)&KVS[(size_t)(k0 + BK + bkk) * CH + bc + 4];
    }
#pragma unroll
    for (int kk = 0; kk < BK; kk++) {
      float a[8], b[8];
      float4 a0 = *(const float4*)&As[kk][w * 8];
      float4 a1 = *(const float4*)&As[kk][w * 8 + 4];
      a[0]=a0.x; a[1]=a0.y; a[2]=a0.z; a[3]=a0.w;
      a[4]=a1.x; a[5]=a1.y; a[6]=a1.z; a[7]=a1.w;
      float4 b0 = *(const float4*)&Bs[kk][l * 8];
      float4 b1 = *(const float4*)&Bs[kk][l * 8 + 4];
      b[0]=b0.x; b[1]=b0.y; b[2]=b0.z; b[3]=b0.w;
      b[4]=b1.x; b[5]=b1.y; b[6]=b1.z; b[7]=b1.w;
#pragma unroll
      for (int i = 0; i < 8; i++)
#pragma unroll
        for (int j = 0; j < 8; j++)
          acc[i][j] = fmaf(a[i], b[j], acc[i][j]);
    }
  }

  // ---------------- epilogue ----------------
  const float cN = rsqrtf(scal[0] * scal[1]);
  const float nF = (float)NROWS;
  float ks[8];
#pragma unroll
  for (int j = 0; j < 8; j++) ks[j] = scal[4 + l * 8 + j];
  float gf[8], btf[8];
  {
    float4 t0 = *(const float4*)&gamma[l*8]; float4 t1 = *(const float4*)&gamma[l*8+4];
    gf[0]=t0.x; gf[1]=t0.y; gf[2]=t0.z; gf[3]=t0.w;
    gf[4]=t1.x; gf[5]=t1.y; gf[6]=t1.z; gf[7]=t1.w;
    float4 u0 = *(const float4*)&beta[l*8];  float4 u1 = *(const float4*)&beta[l*8+4];
    btf[0]=u0.x; btf[1]=u0.y; btf[2]=u0.z; btf[3]=u0.w;
    btf[4]=u1.x; btf[5]=u1.y; btf[6]=u1.z; btf[7]=u1.w;
  }

#pragma unroll
  for (int i = 0; i < 8; i++) {
    const int r = m0 + w * 8 + i;
    const bool valid = r < NROWS;
    float q8[8], v8[8], p8[8];
    if (valid) {
      float4 t0 = *(const float4*)&Q[(size_t)r * CH + l * 8];
      float4 t1 = *(const float4*)&Q[(size_t)r * CH + l * 8 + 4];
      q8[0]=t0.x; q8[1]=t0.y; q8[2]=t0.z; q8[3]=t0.w;
      q8[4]=t1.x; q8[5]=t1.y; q8[6]=t1.z; q8[7]=t1.w;
      float4 v0 = *(const float4*)&V[(size_t)r * CH + l * 8];
      float4 v1 = *(const float4*)&V[(size_t)r * CH + l * 8 + 4];
      v8[0]=v0.x; v8[1]=v0.y; v8[2]=v0.z; v8[3]=v0.w;
      v8[4]=v1.x; v8[5]=v1.y; v8[6]=v1.z; v8[7]=v1.w;
      float4 p0 = *(const float4*)&P[(size_t)r * CH + l * 8];
      float4 p1 = *(const float4*)&P[(size_t)r * CH + l * 8 + 4];
      p8[0]=p0.x; p8[1]=p0.y; p8[2]=p0.z; p8[3]=p0.w;
      p8[4]=p1.x; p8[5]=p1.y; p8[6]=p1.z; p8[7]=p1.w;
    } else {
#pragma unroll
      for (int j = 0; j < 8; j++) { q8[j]=0.f; v8[j]=0.f; p8[j]=0.f; }
    }
    float dp = 0.f;
#pragma unroll
    for (int j = 0; j < 8; j++) dp = fmaf(q8[j], ks[j], dp);
    dp = wred(dp);
    const float denom = fmaf(cN, dp, nF);
    const float inv = 1.f / denom;

    float hm[8];
#pragma unroll
    for (int j = 0; j < 8; j++) {
      float attn = (fmaf(cN, acc[i][j], nF * v8[j])) * inv;
      hm[j] = 0.5f * (attn + p8[j]);
    }
    float s1 = 0.f, s2 = 0.f;
#pragma unroll
    for (int j = 0; j < 8; j++) { s1 += hm[j]; s2 = fmaf(hm[j], hm[j], s2); }
    s1 = wred(s1); s2 = wred(s2);
    const float mu = s1 * (1.f / CH);
    const float rs = rsqrtf(s2 * (1.f / CH) - mu * mu + 1e-5f);
    if (valid) {
      float o[8];
#pragma unroll
      for (int j = 0; j < 8; j++)
        o[j] = fmaxf((hm[j] - mu) * rs * gf[j] + btf[j], 0.f);
      float4 o0 = make_float4(o[0], o[1], o[2], o[3]);
      float4 o1 = make_float4(o[4], o[5], o[6], o[7]);
      *(float4*)&Cout[(size_t)r * CH + l * 8]     = o0;
      *(float4*)&Cout[(size_t)r * CH + l * 8 + 4] = o1;
    }
  }
}

// ---------------------------------------------------------------------------
extern "C" void kernel_launch(void* const* d_in, const int* in_sizes, int n_in,
                              void* d_out, int out_size) {
  (void)in_sizes; (void)n_in; (void)out_size;
  const float* x    = (const float*)d_in[0];
  const float* fc_w = (const float*)d_in[1];
  const float* fc_b = (const float*)d_in[2];
  const float* Wq_w = (const float*)d_in[3];
  const float* Wq_b = (const float*)d_in[4];
  const float* Wk_w = (const float*)d_in[5];
  const float* Wk_b = (const float*)d_in[6];
  const float* Wv_w = (const float*)d_in[7];
  const float* Wv_b = (const float*)d_in[8];
  const float* ln_g = (const float*)d_in[9];
  const float* ln_b = (const float*)d_in[10];
  float* out = (float*)d_out;

  float *hA, *hB, *q, *k, *v, *part, *kvs, *scal;
  cudaGetSymbolAddress((void**)&hA,   g_h);
  cudaGetSymbolAddress((void**)&hB,   g_h2);
  cudaGetSymbolAddress((void**)&q,    g_q);
  cudaGetSymbolAddress((void**)&k,    g_k);
  cudaGetSymbolAddress((void**)&v,    g_v);
  cudaGetSymbolAddress((void**)&part, g_part);
  cudaGetSymbolAddress((void**)&kvs,  g_kvs);
  cudaGetSymbolAddress((void**)&scal, g_scal);

  // h0 = relu(LN(x @ fc_w^T + fc_b))
  gemm_nt<true, false, false><<<MBLK, NTHR>>>(
      x, fc_w, fc_b, hA, ln_g, ln_b, nullptr, nullptr);

  for (int L = 0; L < 2; L++) {
    const float* h = L ? hB : hA;
    float* ob = L ? out : hB;
    const size_t wo = (size_t)L * CH * CH;
    const size_t bo = (size_t)L * CH;

    zero_kernel<<<1, CH + 4>>>(scal, CH + 4);
    gemm_nt<false, true, false><<<MBLK, NTHR>>>(
        h, Wq_w + wo, Wq_b + bo, q, nullptr, nullptr, scal + 0, nullptr);
    gemm_nt<false, true, true><<<MBLK, NTHR>>>(
        h, Wk_w + wo, Wk_b + bo, k, nullptr, nullptr, scal + 1, scal + 4);
    gemm_nt<false, false, false><<<MBLK, NTHR>>>(
        h, Wv_w + wo, Wv_b + bo, v, nullptr, nullptr, nullptr, nullptr);
    kvs_kernel<<<dim3(CH / BM, S_SLICES), NTHR>>>(k, v, part);
    kvs_reduce<<<64, 1024>>>(part, kvs);
    attn_kernel<<<MBLK, NTHR>>>(
        q, kvs, v, h, scal, ln_g + (size_t)(L + 1) * CH, ln_b + (size_t)(L + 1) * CH, ob);
  }
}

// round 6
// speedup vs baseline: 1.1675x; 1.1675x over previous
#include <cuda_runtime.h>

#define NROWS 100000
#define CH 256
#define BM 64
#define BK 8
#define ASTR (BM + 4)          // 68: 16B-aligned rows (68*4=272=17*16)
#define NTHR 256
#define MBLK ((NROWS + BM - 1) / BM)
#define S_SLICES 37
#define ROWS_PER 2704

// ---------------- scratch (static device globals; no allocation) ------------
__device__ float g_h [(size_t)NROWS * CH];
__device__ float g_h2[(size_t)NROWS * CH];
__device__ float g_q [(size_t)NROWS * CH];
__device__ float g_k [(size_t)NROWS * CH];
__device__ float g_v [(size_t)NROWS * CH];
__device__ float g_part[(size_t)S_SLICES * CH * CH];
__device__ float g_kvs[CH * CH];
__device__ float g_scal[CH + 4];   // [0]=||q||^2 [1]=||k||^2 [4..259]=col-sums of k

__device__ __forceinline__ float wred(float v) {
#pragma unroll
  for (int o = 16; o > 0; o >>= 1) v += __shfl_xor_sync(0xffffffffu, v, o);
  return v;
}

// Column mapping: lane l owns cols [l*4, l*4+4) and [128+l*4, 128+l*4+4).
// Both b-side LDS.128 reads are then fully packed (contiguous 512B per warp).

// ---------------------------------------------------------------------------
// C[r, j] = sum_k A[r,k] * W[j,k] + bias[j]   (NT gemm, K = CH = 256, BN = 256)
// ---------------------------------------------------------------------------
template<bool LNE, bool NORM, bool COLSUM>
__global__ void __launch_bounds__(NTHR) gemm_nt(
    const float* __restrict__ A, const float* __restrict__ W,
    const float* __restrict__ bias, float* __restrict__ C,
    const float* __restrict__ gamma, const float* __restrict__ beta,
    float* __restrict__ normAcc, float* __restrict__ colAcc)
{
  __shared__ float As[BK][ASTR];
  __shared__ float Bs[BK][CH];
  __shared__ float sCol[CH];
  __shared__ float sRed[8];

  const int tid = threadIdx.x, w = tid >> 5, l = tid & 31;
  const int m0 = blockIdx.x * BM;
  const int c0 = l * 4;            // first column group
  const int c1 = 128 + l * 4;      // second column group

  if (COLSUM && tid < CH) sCol[tid] = 0.f;

  const int arow = tid >> 2;
  const int akk  = (tid & 3) * 2;
  const bool aval = (m0 + arow) < NROWS;
  const float* Aptr = A + (size_t)(m0 + arow) * CH + akk;
  const float* Wptr = W + (size_t)tid * CH;

  float acc[8][8];
#pragma unroll
  for (int i = 0; i < 8; i++)
#pragma unroll
    for (int j = 0; j < 8; j++) acc[i][j] = 0.f;

  float2 aR = aval ? *(const float2*)Aptr : make_float2(0.f, 0.f);
  float4 bR0 = *(const float4*)(Wptr);
  float4 bR1 = *(const float4*)(Wptr + 4);

  for (int k0 = 0; k0 < CH; k0 += BK) {
    __syncthreads();
    As[akk][arow]     = aR.x;
    As[akk + 1][arow] = aR.y;
    Bs[0][tid] = bR0.x; Bs[1][tid] = bR0.y; Bs[2][tid] = bR0.z; Bs[3][tid] = bR0.w;
    Bs[4][tid] = bR1.x; Bs[5][tid] = bR1.y; Bs[6][tid] = bR1.z; Bs[7][tid] = bR1.w;
    __syncthreads();
    if (k0 + BK < CH) {
      aR  = aval ? *(const float2*)(Aptr + k0 + BK) : make_float2(0.f, 0.f);
      bR0 = *(const float4*)(Wptr + k0 + BK);
      bR1 = *(const float4*)(Wptr + k0 + BK + 4);
    }
#pragma unroll
    for (int kk = 0; kk < BK; kk++) {
      float a[8], b[8];
      float4 a0 = *(const float4*)&As[kk][w * 8];
      float4 a1 = *(const float4*)&As[kk][w * 8 + 4];
      a[0]=a0.x; a[1]=a0.y; a[2]=a0.z; a[3]=a0.w;
      a[4]=a1.x; a[5]=a1.y; a[6]=a1.z; a[7]=a1.w;
      float4 b0 = *(const float4*)&Bs[kk][c0];
      float4 b1 = *(const float4*)&Bs[kk][c1];
      b[0]=b0.x; b[1]=b0.y; b[2]=b0.z; b[3]=b0.w;
      b[4]=b1.x; b[5]=b1.y; b[6]=b1.z; b[7]=b1.w;
#pragma unroll
      for (int i = 0; i < 8; i++)
#pragma unroll
        for (int j = 0; j < 8; j++)
          acc[i][j] = fmaf(a[i], b[j], acc[i][j]);
    }
  }

  // ---------------- epilogue ----------------
  float bf[8];
  { float4 t0 = *(const float4*)&bias[c0]; float4 t1 = *(const float4*)&bias[c1];
    bf[0]=t0.x; bf[1]=t0.y; bf[2]=t0.z; bf[3]=t0.w;
    bf[4]=t1.x; bf[5]=t1.y; bf[6]=t1.z; bf[7]=t1.w; }
  float gf[8], btf[8];
  if (LNE) {
    float4 t0 = *(const float4*)&gamma[c0]; float4 t1 = *(const float4*)&gamma[c1];
    gf[0]=t0.x; gf[1]=t0.y; gf[2]=t0.z; gf[3]=t0.w;
    gf[4]=t1.x; gf[5]=t1.y; gf[6]=t1.z; gf[7]=t1.w;
    float4 u0 = *(const float4*)&beta[c0];  float4 u1 = *(const float4*)&beta[c1];
    btf[0]=u0.x; btf[1]=u0.y; btf[2]=u0.z; btf[3]=u0.w;
    btf[4]=u1.x; btf[5]=u1.y; btf[6]=u1.z; btf[7]=u1.w;
  }

  float nrm = 0.f;
  float colp[8];
#pragma unroll
  for (int j = 0; j < 8; j++) colp[j] = 0.f;

#pragma unroll
  for (int i = 0; i < 8; i++) {
    const int r = m0 + w * 8 + i;
    const bool valid = r < NROWS;
#pragma unroll
    for (int j = 0; j < 8; j++) acc[i][j] += bf[j];
    if (NORM && valid) {
#pragma unroll
      for (int j = 0; j < 8; j++) nrm = fmaf(acc[i][j], acc[i][j], nrm);
    }
    if (COLSUM && valid) {
#pragma unroll
      for (int j = 0; j < 8; j++) colp[j] += acc[i][j];
    }
    if (LNE) {
      float s1 = 0.f, s2 = 0.f;
#pragma unroll
      for (int j = 0; j < 8; j++) { s1 += acc[i][j]; s2 = fmaf(acc[i][j], acc[i][j], s2); }
      s1 = wred(s1); s2 = wred(s2);
      const float mu = s1 * (1.f / CH);
      const float rs = rsqrtf(s2 * (1.f / CH) - mu * mu + 1e-5f);
#pragma unroll
      for (int j = 0; j < 8; j++) {
        float vv = (acc[i][j] - mu) * rs * gf[j] + btf[j];
        acc[i][j] = fmaxf(vv, 0.f);
      }
    }
    if (valid) {
      float4 o0 = make_float4(acc[i][0], acc[i][1], acc[i][2], acc[i][3]);
      float4 o1 = make_float4(acc[i][4], acc[i][5], acc[i][6], acc[i][7]);
      *(float4*)&C[(size_t)r * CH + c0] = o0;
      *(float4*)&C[(size_t)r * CH + c1] = o1;
    }
  }

  if (NORM) {
    float p = wred(nrm);
    if (l == 0) sRed[w] = p;
    __syncthreads();
    if (tid == 0) {
      float s = 0.f;
#pragma unroll
      for (int i = 0; i < 8; i++) s += sRed[i];
      atomicAdd(normAcc, s);
    }
  }
  if (COLSUM) {
#pragma unroll
    for (int j = 0; j < 4; j++) atomicAdd(&sCol[c0 + j], colp[j]);
#pragma unroll
    for (int j = 0; j < 4; j++) atomicAdd(&sCol[c1 + j], colp[4 + j]);
    __syncthreads();
    if (tid < CH) atomicAdd(&colAcc[tid], sCol[tid]);
  }
}

// ---------------------------------------------------------------------------
// part[s][m][d] = sum over rows n in slice s of K[n,m] * V[n,d]
// ---------------------------------------------------------------------------
__global__ void __launch_bounds__(NTHR) kvs_kernel(
    const float* __restrict__ K, const float* __restrict__ V,
    float* __restrict__ part)
{
  __shared__ float As[BK][ASTR];
  __shared__ float Bs[BK][CH];

  const int tid = threadIdx.x, w = tid >> 5, l = tid & 31;
  const int m0 = blockIdx.x * BM;
  const int n0 = blockIdx.y * ROWS_PER;
  const int c0 = l * 4;
  const int c1 = 128 + l * 4;

  const int akk = tid >> 5;            // 0..7
  const int am  = (tid & 31) * 2;      // 0..62
  const int bkk = tid >> 5;
  const int bc  = (tid & 31) * 8;

  float acc[8][8];
#pragma unroll
  for (int i = 0; i < 8; i++)
#pragma unroll
    for (int j = 0; j < 8; j++) acc[i][j] = 0.f;

  float2 aR; float4 bR0, bR1;
  {
    int n = n0 + akk;
    aR  = (n < NROWS) ? *(const float2*)&K[(size_t)n * CH + m0 + am] : make_float2(0.f, 0.f);
    if (n < NROWS) { bR0 = *(const float4*)&V[(size_t)n * CH + bc];
                     bR1 = *(const float4*)&V[(size_t)n * CH + bc + 4]; }
    else { bR0 = make_float4(0,0,0,0); bR1 = make_float4(0,0,0,0); }
  }

  for (int k0 = 0; k0 < ROWS_PER; k0 += BK) {
    __syncthreads();
    As[akk][am]     = aR.x;
    As[akk][am + 1] = aR.y;
    *(float4*)&Bs[bkk][bc]     = bR0;
    *(float4*)&Bs[bkk][bc + 4] = bR1;
    __syncthreads();
    if (k0 + BK < ROWS_PER) {
      int n = n0 + k0 + BK + akk;
      aR = (n < NROWS) ? *(const float2*)&K[(size_t)n * CH + m0 + am] : make_float2(0.f, 0.f);
      int nb = n0 + k0 + BK + bkk;
      if (nb < NROWS) { bR0 = *(const float4*)&V[(size_t)nb * CH + bc];
                        bR1 = *(const float4*)&V[(size_t)nb * CH + bc + 4]; }
      else { bR0 = make_float4(0,0,0,0); bR1 = make_float4(0,0,0,0); }
    }
#pragma unroll
    for (int kk = 0; kk < BK; kk++) {
      float a[8], b[8];
      float4 a0 = *(const float4*)&As[kk][w * 8];
      float4 a1 = *(const float4*)&As[kk][w * 8 + 4];
      a[0]=a0.x; a[1]=a0.y; a[2]=a0.z; a[3]=a0.w;
      a[4]=a1.x; a[5]=a1.y; a[6]=a1.z; a[7]=a1.w;
      float4 b0 = *(const float4*)&Bs[kk][c0];
      float4 b1 = *(const float4*)&Bs[kk][c1];
      b[0]=b0.x; b[1]=b0.y; b[2]=b0.z; b[3]=b0.w;
      b[4]=b1.x; b[5]=b1.y; b[6]=b1.z; b[7]=b1.w;
#pragma unroll
      for (int i = 0; i < 8; i++)
#pragma unroll
        for (int j = 0; j < 8; j++)
          acc[i][j] = fmaf(a[i], b[j], acc[i][j]);
    }
  }

  float* dst = part + (size_t)blockIdx.y * CH * CH;
#pragma unroll
  for (int i = 0; i < 8; i++) {
    int m = m0 + w * 8 + i;
    float4 o0 = make_float4(acc[i][0], acc[i][1], acc[i][2], acc[i][3]);
    float4 o1 = make_float4(acc[i][4], acc[i][5], acc[i][6], acc[i][7]);
    *(float4*)&dst[(size_t)m * CH + c0] = o0;
    *(float4*)&dst[(size_t)m * CH + c1] = o1;
  }
}

__global__ void kvs_reduce(const float* __restrict__ part, float* __restrict__ kvs) {
  int idx = blockIdx.x * blockDim.x + threadIdx.x;
  if (idx < CH * CH) {
    float s = 0.f;
#pragma unroll
    for (int ss = 0; ss < S_SLICES; ss++) s += part[(size_t)ss * CH * CH + idx];
    kvs[idx] = s;
  }
}

__global__ void zero_kernel(float* p, int n) {
  int i = blockIdx.x * blockDim.x + threadIdx.x;
  if (i < n) p[i] = 0.f;
}

// ---------------------------------------------------------------------------
// out = ReLU(LN(0.5*attn + 0.5*prev)),
// attn = (c * (Q@KVS) + n*V) / (c * (Q . ks_sum) + n),  c = rsqrt(||q||^2 ||k||^2)
// ---------------------------------------------------------------------------
__global__ void __launch_bounds__(NTHR) attn_kernel(
    const float* __restrict__ Q, const float* __restrict__ KVS,
    const float* __restrict__ V, const float* __restrict__ P,
    const float* __restrict__ scal,
    const float* __restrict__ gamma, const float* __restrict__ beta,
    float* __restrict__ Cout)
{
  __shared__ float As[BK][ASTR];
  __shared__ float Bs[BK][CH];

  const int tid = threadIdx.x, w = tid >> 5, l = tid & 31;
  const int m0 = blockIdx.x * BM;
  const int c0 = l * 4;
  const int c1 = 128 + l * 4;

  const int arow = tid >> 2;
  const int akk  = (tid & 3) * 2;
  const bool aval = (m0 + arow) < NROWS;
  const float* Aptr = Q + (size_t)(m0 + arow) * CH + akk;
  const int bkk = tid >> 5;
  const int bc  = (tid & 31) * 8;

  float acc[8][8];
#pragma unroll
  for (int i = 0; i < 8; i++)
#pragma unroll
    for (int j = 0; j < 8; j++) acc[i][j] = 0.f;

  float2 aR = aval ? *(const float2*)Aptr : make_float2(0.f, 0.f);
  float4 bR0 = *(const float4*)&KVS[(size_t)bkk * CH + bc];
  float4 bR1 = *(const float4*)&KVS[(size_t)bkk * CH + bc + 4];

  for (int k0 = 0; k0 < CH; k0 += BK) {
    __syncthreads();
    As[akk][arow]     = aR.x;
    As[akk + 1][arow] = aR.y;
    *(float4*)&Bs[bkk][bc]     = bR0;
    *(float4*)&Bs[bkk][bc + 4] = bR1;
    __syncthreads();
    if (k0 + BK < CH) {
      aR  = aval ? *(const float2*)(Aptr + k0 + BK) : make_float2(0.f, 0.f);
      bR0 = *(const float4*)&KVS[(size_t)(k0 + BK + bkk) * CH + bc];
      bR1 = *(const float4*)&KVS[(size_t)(k0 + BK + bkk) * CH + bc + 4];
    }
#pragma unroll
    for (int kk = 0; kk < BK; kk++) {
      float a[8], b[8];
      float4 a0 = *(const float4*)&As[kk][w * 8];
      float4 a1 = *(const float4*)&As[kk][w * 8 + 4];
      a[0]=a0.x; a[1]=a0.y; a[2]=a0.z; a[3]=a0.w;
      a[4]=a1.x; a[5]=a1.y; a[6]=a1.z; a[7]=a1.w;
      float4 b0 = *(const float4*)&Bs[kk][c0];
      float4 b1 = *(const float4*)&Bs[kk][c1];
      b[0]=b0.x; b[1]=b0.y; b[2]=b0.z; b[3]=b0.w;
      b[4]=b1.x; b[5]=b1.y; b[6]=b1.z; b[7]=b1.w;
#pragma unroll
      for (int i = 0; i < 8; i++)
#pragma unroll
        for (int j = 0; j < 8; j++)
          acc[i][j] = fmaf(a[i], b[j], acc[i][j]);
    }
  }

  // ---------------- epilogue ----------------
  const float cN = rsqrtf(scal[0] * scal[1]);
  const float nF = (float)NROWS;
  float ks[8];
  { float4 t0 = *(const float4*)&scal[4 + c0]; float4 t1 = *(const float4*)&scal[4 + c1];
    ks[0]=t0.x; ks[1]=t0.y; ks[2]=t0.z; ks[3]=t0.w;
    ks[4]=t1.x; ks[5]=t1.y; ks[6]=t1.z; ks[7]=t1.w; }
  float gf[8], btf[8];
  {
    float4 t0 = *(const float4*)&gamma[c0]; float4 t1 = *(const float4*)&gamma[c1];
    gf[0]=t0.x; gf[1]=t0.y; gf[2]=t0.z; gf[3]=t0.w;
    gf[4]=t1.x; gf[5]=t1.y; gf[6]=t1.z; gf[7]=t1.w;
    float4 u0 = *(const float4*)&beta[c0];  float4 u1 = *(const float4*)&beta[c1];
    btf[0]=u0.x; btf[1]=u0.y; btf[2]=u0.z; btf[3]=u0.w;
    btf[4]=u1.x; btf[5]=u1.y; btf[6]=u1.z; btf[7]=u1.w;
  }

#pragma unroll
  for (int i = 0; i < 8; i++) {
    const int r = m0 + w * 8 + i;
    const bool valid = r < NROWS;
    float q8[8], v8[8], p8[8];
    if (valid) {
      float4 t0 = *(const float4*)&Q[(size_t)r * CH + c0];
      float4 t1 = *(const float4*)&Q[(size_t)r * CH + c1];
      q8[0]=t0.x; q8[1]=t0.y; q8[2]=t0.z; q8[3]=t0.w;
      q8[4]=t1.x; q8[5]=t1.y; q8[6]=t1.z; q8[7]=t1.w;
      float4 v0 = *(const float4*)&V[(size_t)r * CH + c0];
      float4 v1 = *(const float4*)&V[(size_t)r * CH + c1];
      v8[0]=v0.x; v8[1]=v0.y; v8[2]=v0.z; v8[3]=v0.w;
      v8[4]=v1.x; v8[5]=v1.y; v8[6]=v1.z; v8[7]=v1.w;
      float4 p0 = *(const float4*)&P[(size_t)r * CH + c0];
      float4 p1 = *(const float4*)&P[(size_t)r * CH + c1];
      p8[0]=p0.x; p8[1]=p0.y; p8[2]=p0.z; p8[3]=p0.w;
      p8[4]=p1.x; p8[5]=p1.y; p8[6]=p1.z; p8[7]=p1.w;
    } else {
#pragma unroll
      for (int j = 0; j < 8; j++) { q8[j]=0.f; v8[j]=0.f; p8[j]=0.f; }
    }
    float dp = 0.f;
#pragma unroll
    for (int j = 0; j < 8; j++) dp = fmaf(q8[j], ks[j], dp);
    dp = wred(dp);
    const float denom = fmaf(cN, dp, nF);
    const float inv = 1.f / denom;

    float hm[8];
#pragma unroll
    for (int j = 0; j < 8; j++) {
      float attn = (fmaf(cN, acc[i][j], nF * v8[j])) * inv;
      hm[j] = 0.5f * (attn + p8[j]);
    }
    float s1 = 0.f, s2 = 0.f;
#pragma unroll
    for (int j = 0; j < 8; j++) { s1 += hm[j]; s2 = fmaf(hm[j], hm[j], s2); }
    s1 = wred(s1); s2 = wred(s2);
    const float mu = s1 * (1.f / CH);
    const float rs = rsqrtf(s2 * (1.f / CH) - mu * mu + 1e-5f);
    if (valid) {
      float o[8];
#pragma unroll
      for (int j = 0; j < 8; j++)
        o[j] = fmaxf((hm[j] - mu) * rs * gf[j] + btf[j], 0.f);
      float4 o0 = make_float4(o[0], o[1], o[2], o[3]);
      float4 o1 = make_float4(o[4], o[5], o[6], o[7]);
      *(float4*)&Cout[(size_t)r * CH + c0] = o0;
      *(float4*)&Cout[(size_t)r * CH + c1] = o1;
    }
  }
}

// ---------------------------------------------------------------------------
extern "C" void kernel_launch(void* const* d_in, const int* in_sizes, int n_in,
                              void* d_out, int out_size) {
  (void)in_sizes; (void)n_in; (void)out_size;
  const float* x    = (const float*)d_in[0];
  const float* fc_w = (const float*)d_in[1];
  const float* fc_b = (const float*)d_in[2];
  const float* Wq_w = (const float*)d_in[3];
  const float* Wq_b = (const float*)d_in[4];
  const float* Wk_w = (const float*)d_in[5];
  const float* Wk_b = (const float*)d_in[6];
  const float* Wv_w = (const float*)d_in[7];
  const float* Wv_b = (const float*)d_in[8];
  const float* ln_g = (const float*)d_in[9];
  const float* ln_b = (const float*)d_in[10];
  float* out = (float*)d_out;

  float *hA, *hB, *q, *k, *v, *part, *kvs, *scal;
  cudaGetSymbolAddress((void**)&hA,   g_h);
  cudaGetSymbolAddress((void**)&hB,   g_h2);
  cudaGetSymbolAddress((void**)&q,    g_q);
  cudaGetSymbolAddress((void**)&k,    g_k);
  cudaGetSymbolAddress((void**)&v,    g_v);
  cudaGetSymbolAddress((void**)&part, g_part);
  cudaGetSymbolAddress((void**)&kvs,  g_kvs);
  cudaGetSymbolAddress((void**)&scal, g_scal);

  // h0 = relu(LN(x @ fc_w^T + fc_b))
  gemm_nt<true, false, false><<<MBLK, NTHR>>>(
      x, fc_w, fc_b, hA, ln_g, ln_b, nullptr, nullptr);

  for (int L = 0; L < 2; L++) {
    const float* h = L ? hB : hA;
    float* ob = L ? out : hB;
    const size_t wo = (size_t)L * CH * CH;
    const size_t bo = (size_t)L * CH;

    zero_kernel<<<1, CH + 4>>>(scal, CH + 4);
    gemm_nt<false, true, false><<<MBLK, NTHR>>>(
        h, Wq_w + wo, Wq_b + bo, q, nullptr, nullptr, scal + 0, nullptr);
    gemm_nt<false, true, true><<<MBLK, NTHR>>>(
        h, Wk_w + wo, Wk_b + bo, k, nullptr, nullptr, scal + 1, scal + 4);
    gemm_nt<false, false, false><<<MBLK, NTHR>>>(
        h, Wv_w + wo, Wv_b + bo, v, nullptr, nullptr, nullptr, nullptr);
    kvs_kernel<<<dim3(CH / BM, S_SLICES), NTHR>>>(k, v, part);
    kvs_reduce<<<64, 1024>>>(part, kvs);
    attn_kernel<<<MBLK, NTHR>>>(
        q, kvs, v, h, scal, ln_g + (size_t)(L + 1) * CH, ln_b + (size_t)(L + 1) * CH, ob);
  }
}

// round 8
// speedup vs baseline: 1.8051x; 1.5462x over previous
#include <cuda_runtime.h>
#include <cuda_bf16.h>
#include <cstdint>

#define NROWS 100000
#define CH 256
#define NTHR 256
// ---- SIMT kvs params ----
#define BM 64
#define BK 8
#define ASTR (BM + 4)
#define S_SLICES 37
#define ROWS_PER 2704
// ---- MMA gemm params ----
#define TM 128
#define TGRID ((NROWS + TM - 1) / TM)   // 782
#define STR 40                          // bf16 row stride in smem (80B, 16B-aligned, ldmatrix conflict-free)
#define AB (128 * STR * 2)              // 10240 B per A matrix (hi or lo)
#define WB (256 * STR * 2)              // 20480 B per W matrix
#define BUFB (2 * AB + 2 * WB)          // 61440 B per stage
#define SCR (2 * BUFB)                  // scratch offset
#define SMEM_SZ (SCR + 4096)

// ---------------- scratch (static device globals; no allocation) ------------
__device__ float g_h [(size_t)NROWS * CH];
__device__ float g_h2[(size_t)NROWS * CH];
__device__ float g_q [(size_t)NROWS * CH];
__device__ float g_k [(size_t)NROWS * CH];
__device__ float g_v [(size_t)NROWS * CH];
__device__ float g_part[(size_t)S_SLICES * CH * CH];
__device__ float g_scal[CH + 4];   // [0]=||q||^2 [1]=||k||^2 [4..259]=col-sums of k
__device__ float g_dp[NROWS];
__device__ __nv_bfloat16 g_xh[(size_t)NROWS * CH], g_xl[(size_t)NROWS * CH];
__device__ __nv_bfloat16 g_ahh[(size_t)NROWS * CH], g_ahl[(size_t)NROWS * CH];
__device__ __nv_bfloat16 g_bhh[(size_t)NROWS * CH], g_bhl[(size_t)NROWS * CH];
__device__ __nv_bfloat16 g_qh[(size_t)NROWS * CH], g_ql[(size_t)NROWS * CH];
__device__ __nv_bfloat16 g_wh[7 * 65536], g_wl[7 * 65536];
__device__ __nv_bfloat16 g_bth[65536], g_btl[65536];

// ---------------- helpers ---------------------------------------------------
__device__ __forceinline__ uint32_t smem_u32(const void* p) {
  uint32_t a;
  asm("{ .reg .u64 t; cvta.to.shared.u64 t, %1; cvt.u32.u64 %0, t; }" : "=r"(a) : "l"(p));
  return a;
}
#define CP16(dst, src) \
  asm volatile("cp.async.cg.shared.global [%0], [%1], 16;" :: "r"(dst), "l"(src))
#define CP_COMMIT() asm volatile("cp.async.commit_group;" ::: "memory")
#define CP_WAIT(n) asm volatile("cp.async.wait_group %0;" :: "n"(n) : "memory")

__device__ __forceinline__ void ldm_x4(uint32_t* r, uint32_t addr) {
  asm volatile("ldmatrix.sync.aligned.m8n8.x4.shared.b16 {%0,%1,%2,%3}, [%4];"
               : "=r"(r[0]), "=r"(r[1]), "=r"(r[2]), "=r"(r[3]) : "r"(addr));
}
__device__ __forceinline__ void ldm_x2(uint32_t* r, uint32_t addr) {
  asm volatile("ldmatrix.sync.aligned.m8n8.x2.shared.b16 {%0,%1}, [%2];"
               : "=r"(r[0]), "=r"(r[1]) : "r"(addr));
}
__device__ __forceinline__ void mma_bf16(float* c, const uint32_t* a, const uint32_t* b) {
  asm volatile(
      "mma.sync.aligned.m16n8k16.row.col.f32.bf16.bf16.f32 "
      "{%0,%1,%2,%3}, {%4,%5,%6,%7}, {%8,%9}, {%0,%1,%2,%3};"
      : "+f"(c[0]), "+f"(c[1]), "+f"(c[2]), "+f"(c[3])
      : "r"(a[0]), "r"(a[1]), "r"(a[2]), "r"(a[3]), "r"(b[0]), "r"(b[1]));
}
__device__ __forceinline__ float wredf(float v) {
#pragma unroll
  for (int o = 16; o > 0; o >>= 1) v += __shfl_xor_sync(0xffffffffu, v, o);
  return v;
}
__device__ __forceinline__ unsigned short bfb(__nv_bfloat16 h) {
  return *reinterpret_cast<unsigned short*>(&h);
}
__device__ __forceinline__ void packhl(float v0, float v1, uint32_t& hi, uint32_t& lo) {
  __nv_bfloat16 h0 = __float2bfloat16(v0), h1 = __float2bfloat16(v1);
  __nv_bfloat16 l0 = __float2bfloat16(v0 - __bfloat162float(h0));
  __nv_bfloat16 l1 = __float2bfloat16(v1 - __bfloat162float(h1));
  hi = (uint32_t)bfb(h0) | ((uint32_t)bfb(h1) << 16);
  lo = (uint32_t)bfb(l0) | ((uint32_t)bfb(l1) << 16);
}

// ---------------------------------------------------------------------------
__global__ void split_kernel(const float* __restrict__ src,
                             __nv_bfloat16* __restrict__ hi,
                             __nv_bfloat16* __restrict__ lo, int n) {
  int i = blockIdx.x * blockDim.x + threadIdx.x;
  if (i < n) {
    float x = src[i];
    __nv_bfloat16 h = __float2bfloat16(x);
    hi[i] = h;
    lo[i] = __float2bfloat16(x - __bfloat162float(h));
  }
}
__global__ void zero_kernel(float* p, int n) {
  int i = blockIdx.x * blockDim.x + threadIdx.x;
  if (i < n) p[i] = 0.f;
}

// dp[r] = q[r,:] . ks_sum
__global__ void __launch_bounds__(NTHR) dp_kernel(const float* __restrict__ Q,
                                                  const float* __restrict__ scal,
                                                  float* __restrict__ dp) {
  int tid = threadIdx.x, w = tid >> 5, l = tid & 31;
  int rsub = l >> 3, cseg = l & 7;
  int r = blockIdx.x * 32 + w * 4 + rsub;
  float s = 0.f;
  if (r < NROWS) {
    const float4* q4 = (const float4*)(Q + (size_t)r * CH + cseg * 32);
    const float4* k4 = (const float4*)(scal + 4 + cseg * 32);
#pragma unroll
    for (int i = 0; i < 8; i++) {
      float4 a = q4[i], b = k4[i];
      s += a.x * b.x + a.y * b.y + a.z * b.z + a.w * b.w;
    }
  }
#pragma unroll
  for (int o = 4; o > 0; o >>= 1) s += __shfl_xor_sync(0xffffffffu, s, o);
  if (cseg == 0 && r < NROWS) dp[r] = s;
}

// ---------------------------------------------------------------------------
// MMA GEMM: C[128,256] = A[128,256] @ W[256,256]^T, bf16-split, fp32 acc regs.
// ---------------------------------------------------------------------------
#define EPI_LN   0
#define EPI_Q    1
#define EPI_K    2
#define EPI_V    3
#define EPI_ATTN 4

#define ACCV(jr, nt, c) acc[(jr) >> 1][nt][(((jr) & 1) << 1) + (c)]

template<int EPI>
__global__ void __launch_bounds__(NTHR, 1) gemm_mma(
    const __nv_bfloat16* __restrict__ Ah, const __nv_bfloat16* __restrict__ Al,
    const __nv_bfloat16* __restrict__ Wh, const __nv_bfloat16* __restrict__ Wl,
    const float* __restrict__ bias,
    float* __restrict__ Cf, __nv_bfloat16* __restrict__ Chi, __nv_bfloat16* __restrict__ Clo,
    const float* __restrict__ gamma, const float* __restrict__ beta,
    float* __restrict__ normAcc, float* __restrict__ colAcc,
    const float* __restrict__ scal, const float* __restrict__ dpv,
    const float* __restrict__ Vf, const float* __restrict__ Pf)
{
  extern __shared__ char smem[];
  const uint32_t sb = smem_u32(smem);
  const int tid = threadIdx.x, w = tid >> 5, l = tid & 31;
  const int wrow = w >> 1, wcol = w & 1;
  const int m0 = blockIdx.x * TM;

  float* sS1  = (float*)(smem + SCR);
  float* sS2  = (float*)(smem + SCR + 1024);
  float* sCol = (float*)(smem + SCR + 2048);
  float* sRed = (float*)(smem + SCR + 3072);
  if (EPI == EPI_K) sCol[tid] = 0.f;

  float acc[2][16][4];
#pragma unroll
  for (int a = 0; a < 2; a++)
#pragma unroll
    for (int b = 0; b < 16; b++)
#pragma unroll
      for (int c = 0; c < 4; c++) acc[a][b][c] = 0.f;

  // cp.async one chunk (32 k-cols) into stage buf
  auto issue = [&](int ch, int buf) {
    const uint32_t base = sb + buf * BUFB;
    const int k0 = ch * 32;
#pragma unroll
    for (int t = 0; t < 2; t++) {
      int idx = tid + t * 256;
      int row = idx >> 2, seg = idx & 3;
      int gr = m0 + row; if (gr > NROWS - 1) gr = NROWS - 1;
      size_t g = (size_t)gr * CH + k0 + seg * 8;
      uint32_t so = row * 80 + seg * 16;
      CP16(base + so, Ah + g);
      CP16(base + AB + so, Al + g);
    }
#pragma unroll
    for (int t = 0; t < 4; t++) {
      int idx = tid + t * 256;
      int row = idx >> 2, seg = idx & 3;
      size_t g = (size_t)row * CH + k0 + seg * 8;
      uint32_t so = row * 80 + seg * 16;
      CP16(base + 2 * AB + so, Wh + g);
      CP16(base + 2 * AB + WB + so, Wl + g);
    }
  };

  issue(0, 0); CP_COMMIT();
#pragma unroll
  for (int ch = 0; ch < 8; ch++) {
    if (ch < 7) { issue(ch + 1, (ch + 1) & 1); CP_COMMIT(); CP_WAIT(1); }
    else CP_WAIT(0);
    __syncthreads();
    const uint32_t base = sb + (ch & 1) * BUFB;
#pragma unroll
    for (int kt = 0; kt < 2; kt++) {
      uint32_t ah[2][4], al_[2][4];
#pragma unroll
      for (int mt = 0; mt < 2; mt++) {
        int row = wrow * 32 + mt * 16 + (l & 15);
        int col = kt * 16 + ((l >> 4) << 3);
        uint32_t off = row * 80 + col * 2;
        ldm_x4(ah[mt], base + off);
        ldm_x4(al_[mt], base + AB + off);
      }
#pragma unroll
      for (int nt = 0; nt < 16; nt++) {
        int n = wcol * 128 + nt * 8 + (l & 7);
        int col = kt * 16 + ((l >> 3) & 1) * 8;
        uint32_t off = n * 80 + col * 2;
        uint32_t bh[2], bl[2];
        ldm_x2(bh, base + 2 * AB + off);
        ldm_x2(bl, base + 2 * AB + WB + off);
#pragma unroll
        for (int mt = 0; mt < 2; mt++) {
          mma_bf16(acc[mt][nt], ah[mt], bh);
          mma_bf16(acc[mt][nt], ah[mt], bl);
          mma_bf16(acc[mt][nt], al_[mt], bh);
        }
      }
    }
    __syncthreads();
  }

  // ---------------- epilogue on register accumulators -----------------------
  const int qlane = l >> 2;
  const int cbase = wcol * 128 + (l & 3) * 2;

  if (EPI == EPI_Q || EPI == EPI_K || EPI == EPI_V) {
    float nrm = 0.f;
#pragma unroll
    for (int nt = 0; nt < 16; nt++) {
      const int col = cbase + nt * 8;
      float2 bs = *(const float2*)(bias + col);
      float cs0 = 0.f, cs1 = 0.f;
#pragma unroll
      for (int jr = 0; jr < 4; jr++) {
        int r = m0 + wrow * 32 + (jr >> 1) * 16 + (jr & 1) * 8 + qlane;
        bool valid = r < NROWS;
        float v0 = ACCV(jr, nt, 0) + bs.x;
        float v1 = ACCV(jr, nt, 1) + bs.y;
        if (valid) {
          if (EPI == EPI_Q || EPI == EPI_K) nrm = fmaf(v0, v0, fmaf(v1, v1, nrm));
          if (EPI == EPI_K) { cs0 += v0; cs1 += v1; }
          *(float2*)(Cf + (size_t)r * CH + col) = make_float2(v0, v1);
          if (EPI == EPI_Q) {
            uint32_t hi, lo;
            packhl(v0, v1, hi, lo);
            *(uint32_t*)(Chi + (size_t)r * CH + col) = hi;
            *(uint32_t*)(Clo + (size_t)r * CH + col) = lo;
          }
        }
      }
      if (EPI == EPI_K) {
#pragma unroll
        for (int o = 4; o < 32; o <<= 1) {
          cs0 += __shfl_xor_sync(0xffffffffu, cs0, o);
          cs1 += __shfl_xor_sync(0xffffffffu, cs1, o);
        }
        if (qlane == 0) { atomicAdd(&sCol[col], cs0); atomicAdd(&sCol[col + 1], cs1); }
      }
    }
    if (EPI == EPI_Q || EPI == EPI_K) {
      float p = wredf(nrm);
      if (l == 0) sRed[w] = p;
      __syncthreads();
      if (tid == 0) {
        float s = 0.f;
#pragma unroll
        for (int i = 0; i < 8; i++) s += sRed[i];
        atomicAdd(normAcc, s);
      }
      if (EPI == EPI_K) atomicAdd(&colAcc[tid], sCol[tid]);
    }
  } else {
    // EPI_LN / EPI_ATTN: transform, row stats, LN+ReLU, store fp32 + hi/lo
    const float nF = (float)NROWS;
    float cN = 0.f;
    if (EPI == EPI_ATTN) cN = rsqrtf(scal[0] * scal[1]);
    // pass A: overwrite acc with pre-LN value, accumulate row sums
#pragma unroll
    for (int jr = 0; jr < 4; jr++) {
      const int lrow = wrow * 32 + (jr >> 1) * 16 + (jr & 1) * 8 + qlane;
      const int r = m0 + lrow;
      const bool valid = r < NROWS;
      float invr = 0.f;
      if (EPI == EPI_ATTN) invr = 1.f / fmaf(cN, valid ? dpv[r] : 0.f, nF);
      float s1 = 0.f, s2 = 0.f;
#pragma unroll
      for (int nt = 0; nt < 16; nt++) {
        const int col = cbase + nt * 8;
        if (EPI == EPI_LN) {
          float2 bs = *(const float2*)(bias + col);
          float y0 = ACCV(jr, nt, 0) + bs.x;
          float y1 = ACCV(jr, nt, 1) + bs.y;
          ACCV(jr, nt, 0) = y0; ACCV(jr, nt, 1) = y1;
          s1 += y0 + y1; s2 = fmaf(y0, y0, fmaf(y1, y1, s2));
        } else {
          float2 vv = valid ? *(const float2*)(Vf + (size_t)r * CH + col) : make_float2(0.f, 0.f);
          float2 pp = valid ? *(const float2*)(Pf + (size_t)r * CH + col) : make_float2(0.f, 0.f);
          float h0 = 0.5f * (fmaf(cN, ACCV(jr, nt, 0), nF * vv.x) * invr + pp.x);
          float h1 = 0.5f * (fmaf(cN, ACCV(jr, nt, 1), nF * vv.y) * invr + pp.y);
          ACCV(jr, nt, 0) = h0; ACCV(jr, nt, 1) = h1;
          s1 += h0 + h1; s2 = fmaf(h0, h0, fmaf(h1, h1, s2));
        }
      }
#pragma unroll
      for (int o = 1; o < 4; o <<= 1) {
        s1 += __shfl_xor_sync(0xffffffffu, s1, o);
        s2 += __shfl_xor_sync(0xffffffffu, s2, o);
      }
      if ((l & 3) == 0) { sS1[wcol * 128 + lrow] = s1; sS2[wcol * 128 + lrow] = s2; }
    }
    __syncthreads();
    // pass B
#pragma unroll
    for (int jr = 0; jr < 4; jr++) {
      const int lrow = wrow * 32 + (jr >> 1) * 16 + (jr & 1) * 8 + qlane;
      const int r = m0 + lrow;
      const bool valid = r < NROWS;
      const float s1 = sS1[lrow] + sS1[128 + lrow];
      const float s2 = sS2[lrow] + sS2[128 + lrow];
      const float mu = s1 * (1.f / CH);
      const float rs = rsqrtf(s2 * (1.f / CH) - mu * mu + 1e-5f);
#pragma unroll
      for (int nt = 0; nt < 16; nt++) {
        const int col = cbase + nt * 8;
        float2 gg = *(const float2*)(gamma + col);
        float2 bb = *(const float2*)(beta + col);
        float o0 = fmaxf((ACCV(jr, nt, 0) - mu) * rs * gg.x + bb.x, 0.f);
        float o1 = fmaxf((ACCV(jr, nt, 1) - mu) * rs * gg.y + bb.y, 0.f);
        if (valid) {
          *(float2*)(Cf + (size_t)r * CH + col) = make_float2(o0, o1);
          uint32_t hi, lo;
          packhl(o0, o1, hi, lo);
          *(uint32_t*)(Chi + (size_t)r * CH + col) = hi;
          *(uint32_t*)(Clo + (size_t)r * CH + col) = lo;
        }
      }
    }
  }
}

// ---------------------------------------------------------------------------
// SIMT kvs: part[s][m][d] = sum over rows n in slice s of K[n,m] * V[n,d]
// ---------------------------------------------------------------------------
__global__ void __launch_bounds__(NTHR) kvs_kernel(
    const float* __restrict__ K, const float* __restrict__ V,
    float* __restrict__ part)
{
  __shared__ float As[BK][ASTR];
  __shared__ float Bs[BK][CH];

  const int tid = threadIdx.x, w = tid >> 5, l = tid & 31;
  const int m0 = blockIdx.x * BM;
  const int n0 = blockIdx.y * ROWS_PER;
  const int c0 = l * 4;
  const int c1 = 128 + l * 4;

  const int akk = tid >> 5;
  const int am  = (tid & 31) * 2;
  const int bkk = tid >> 5;
  const int bc  = (tid & 31) * 8;

  float acc[8][8];
#pragma unroll
  for (int i = 0; i < 8; i++)
#pragma unroll
    for (int j = 0; j < 8; j++) acc[i][j] = 0.f;

  float2 aR; float4 bR0, bR1;
  {
    int n = n0 + akk;
    aR  = (n < NROWS) ? *(const float2*)&K[(size_t)n * CH + m0 + am] : make_float2(0.f, 0.f);
    if (n < NROWS) { bR0 = *(const float4*)&V[(size_t)n * CH + bc];
                     bR1 = *(const float4*)&V[(size_t)n * CH + bc + 4]; }
    else { bR0 = make_float4(0,0,0,0); bR1 = make_float4(0,0,0,0); }
  }

  for (int k0 = 0; k0 < ROWS_PER; k0 += BK) {
    __syncthreads();
    As[akk][am]     = aR.x;
    As[akk][am + 1] = aR.y;
    *(float4*)&Bs[bkk][bc]     = bR0;
    *(float4*)&Bs[bkk][bc + 4] = bR1;
    __syncthreads();
    if (k0 + BK < ROWS_PER) {
      int n = n0 + k0 + BK + akk;
      aR = (n < NROWS) ? *(const float2*)&K[(size_t)n * CH + m0 + am] : make_float2(0.f, 0.f);
      if (n < NROWS) { bR0 = *(const float4*)&V[(size_t)n * CH + bc];
                       bR1 = *(const float4*)&V[(size_t)n * CH + bc + 4]; }
      else { bR0 = make_float4(0,0,0,0); bR1 = make_float4(0,0,0,0); }
    }
#pragma unroll
    for (int kk = 0; kk < BK; kk++) {
      float a[8], b[8];
      float4 a0 = *(const float4*)&As[kk][w * 8];
      float4 a1 = *(const float4*)&As[kk][w * 8 + 4];
      a[0]=a0.x; a[1]=a0.y; a[2]=a0.z; a[3]=a0.w;
      a[4]=a1.x; a[5]=a1.y; a[6]=a1.z; a[7]=a1.w;
      float4 b0 = *(const float4*)&Bs[kk][c0];
      float4 b1 = *(const float4*)&Bs[kk][c1];
      b[0]=b0.x; b[1]=b0.y; b[2]=b0.z; b[3]=b0.w;
      b[4]=b1.x; b[5]=b1.y; b[6]=b1.z; b[7]=b1.w;
#pragma unroll
      for (int i = 0; i < 8; i++)
#pragma unroll
        for (int j = 0; j < 8; j++)
          acc[i][j] = fmaf(a[i], b[j], acc[i][j]);
    }
  }

  float* dst = part + (size_t)blockIdx.y * CH * CH;
#pragma unroll
  for (int i = 0; i < 8; i++) {
    int m = m0 + w * 8 + i;
    float4 o0 = make_float4(acc[i][0], acc[i][1], acc[i][2], acc[i][3]);
    float4 o1 = make_float4(acc[i][4], acc[i][5], acc[i][6], acc[i][7]);
    *(float4*)&dst[(size_t)m * CH + c0] = o0;
    *(float4*)&dst[(size_t)m * CH + c1] = o1;
  }
}

// reduce partials; write TRANSPOSED hi/lo bf16: bt[d*256+m] = kvs[m][d]
__global__ void kvs_reduce(const float* __restrict__ part,
                           __nv_bfloat16* __restrict__ bth,
                           __nv_bfloat16* __restrict__ btl) {
  int idx = blockIdx.x * blockDim.x + threadIdx.x;
  if (idx < CH * CH) {
    int d = idx >> 8, m = idx & 255;
    float s = 0.f;
#pragma unroll
    for (int ss = 0; ss < S_SLICES; ss++) s += part[(size_t)ss * CH * CH + m * CH + d];
    __nv_bfloat16 h = __float2bfloat16(s);
    bth[idx] = h;
    btl[idx] = __float2bfloat16(s - __bfloat162float(h));
  }
}

// ---------------------------------------------------------------------------
extern "C" void kernel_launch(void* const* d_in, const int* in_sizes, int n_in,
                              void* d_out, int out_size) {
  (void)in_sizes; (void)n_in; (void)out_size;
  const float* x    = (const float*)d_in[0];
  const float* fc_w = (const float*)d_in[1];
  const float* fc_b = (const float*)d_in[2];
  const float* Wq_w = (const float*)d_in[3];
  const float* Wq_b = (const float*)d_in[4];
  const float* Wk_w = (const float*)d_in[5];
  const float* Wk_b = (const float*)d_in[6];
  const float* Wv_w = (const float*)d_in[7];
  const float* Wv_b = (const float*)d_in[8];
  const float* ln_g = (const float*)d_in[9];
  const float* ln_b = (const float*)d_in[10];
  float* out = (float*)d_out;

  float *hA, *hB, *q, *k, *v, *part, *scal, *dp;
  __nv_bfloat16 *xh, *xl, *ahh, *ahl, *bhh, *bhl, *qh, *ql, *wh, *wl, *bth, *btl;
  cudaGetSymbolAddress((void**)&hA, g_h);
  cudaGetSymbolAddress((void**)&hB, g_h2);
  cudaGetSymbolAddress((void**)&q, g_q);
  cudaGetSymbolAddress((void**)&k, g_k);
  cudaGetSymbolAddress((void**)&v, g_v);
  cudaGetSymbolAddress((void**)&part, g_part);
  cudaGetSymbolAddress((void**)&scal, g_scal);
  cudaGetSymbolAddress((void**)&dp, g_dp);
  cudaGetSymbolAddress((void**)&xh, g_xh);  cudaGetSymbolAddress((void**)&xl, g_xl);
  cudaGetSymbolAddress((void**)&ahh, g_ahh); cudaGetSymbolAddress((void**)&ahl, g_ahl);
  cudaGetSymbolAddress((void**)&bhh, g_bhh); cudaGetSymbolAddress((void**)&bhl, g_bhl);
  cudaGetSymbolAddress((void**)&qh, g_qh);  cudaGetSymbolAddress((void**)&ql, g_ql);
  cudaGetSymbolAddress((void**)&wh, g_wh);  cudaGetSymbolAddress((void**)&wl, g_wl);
  cudaGetSymbolAddress((void**)&bth, g_bth); cudaGetSymbolAddress((void**)&btl, g_btl);

  cudaFuncSetAttribute(gemm_mma<EPI_LN>,   cudaFuncAttributeMaxDynamicSharedMemorySize, SMEM_SZ);
  cudaFuncSetAttribute(gemm_mma<EPI_Q>,    cudaFuncAttributeMaxDynamicSharedMemorySize, SMEM_SZ);
  cudaFuncSetAttribute(gemm_mma<EPI_K>,    cudaFuncAttributeMaxDynamicSharedMemorySize, SMEM_SZ);
  cudaFuncSetAttribute(gemm_mma<EPI_V>,    cudaFuncAttributeMaxDynamicSharedMemorySize, SMEM_SZ);
  cudaFuncSetAttribute(gemm_mma<EPI_ATTN>, cudaFuncAttributeMaxDynamicSharedMemorySize, SMEM_SZ);

  // split weights: [0]=fc, [1..3]=Wq0,Wk0,Wv0, [4..6]=Wq1,Wk1,Wv1
  const int WSZ = CH * CH;
  split_kernel<<<WSZ / 256, 256>>>(fc_w, wh, wl, WSZ);
  for (int L = 0; L < 2; L++) {
    split_kernel<<<WSZ / 256, 256>>>(Wq_w + (size_t)L * WSZ, wh + (1 + 3 * L) * WSZ, wl + (1 + 3 * L) * WSZ, WSZ);
    split_kernel<<<WSZ / 256, 256>>>(Wk_w + (size_t)L * WSZ, wh + (2 + 3 * L) * WSZ, wl + (2 + 3 * L) * WSZ, WSZ);
    split_kernel<<<WSZ / 256, 256>>>(Wv_w + (size_t)L * WSZ, wh + (3 + 3 * L) * WSZ, wl + (3 + 3 * L) * WSZ, WSZ);
  }
  split_kernel<<<(NROWS * CH + 255) / 256, 256>>>(x, xh, xl, NROWS * CH);

  // h0 = relu(LN(x @ fc_w^T + fc_b)); writes fp32 + hi/lo
  gemm_mma<EPI_LN><<<TGRID, NTHR, SMEM_SZ>>>(
      xh, xl, wh, wl, fc_b, hA, ahh, ahl, ln_g, ln_b,
      nullptr, nullptr, nullptr, nullptr, nullptr, nullptr);

  for (int L = 0; L < 2; L++) {
    const __nv_bfloat16* hh = L ? bhh : ahh;
    const __nv_bfloat16* hl = L ? bhl : ahl;
    const float* hP = L ? hB : hA;
    float* ob = L ? out : hB;
    const size_t bo = (size_t)L * CH;

    zero_kernel<<<1, CH + 4>>>(scal, CH + 4);
    gemm_mma<EPI_Q><<<TGRID, NTHR, SMEM_SZ>>>(
        hh, hl, wh + (1 + 3 * L) * WSZ, wl + (1 + 3 * L) * WSZ, Wq_b + bo,
        q, qh, ql, nullptr, nullptr, scal + 0, nullptr, nullptr, nullptr, nullptr, nullptr);
    gemm_mma<EPI_K><<<TGRID, NTHR, SMEM_SZ>>>(
        hh, hl, wh + (2 + 3 * L) * WSZ, wl + (2 + 3 * L) * WSZ, Wk_b + bo,
        k, nullptr, nullptr, nullptr, nullptr, scal + 1, scal + 4, nullptr, nullptr, nullptr, nullptr);
    gemm_mma<EPI_V><<<TGRID, NTHR, SMEM_SZ>>>(
        hh, hl, wh + (3 + 3 * L) * WSZ, wl + (3 + 3 * L) * WSZ, Wv_b + bo,
        v, nullptr, nullptr, nullptr, nullptr, nullptr, nullptr, nullptr, nullptr, nullptr, nullptr);
    dp_kernel<<<(NROWS + 31) / 32, NTHR>>>(q, scal, dp);
    kvs_kernel<<<dim3(CH / BM, S_SLICES), NTHR>>>(k, v, part);
    kvs_reduce<<<64, 1024>>>(part, bth, btl);
    gemm_mma<EPI_ATTN><<<TGRID, NTHR, SMEM_SZ>>>(
        qh, ql, bth, btl, nullptr, ob, bhh, bhl,
        ln_g + (size_t)(L + 1) * CH, ln_b + (size_t)(L + 1) * CH,
        nullptr, nullptr, scal, dp, v, hP);
  }
}

// round 9
// speedup vs baseline: 2.3796x; 1.3182x over previous
#include <cuda_runtime.h>
#include <cuda_bf16.h>
#include <cstdint>

#define NROWS 100000
#define CH 256
#define NTHR 256
// ---- MMA gemm params ----
#define TM 128
#define TGRID ((NROWS + TM - 1) / TM)   // 782
#define AB (128 * 80)                   // 10240 B per A matrix (hi or lo), 80B rows
#define WB (256 * 80)                   // 20480 B per W matrix
#define BUFB (2 * AB + 2 * WB)          // 61440 B per stage
#define SCR (2 * BUFB)
#define SMEM_SZ (SCR + 4096)
// ---- kvs MMA params ----
#define NSLICE 73
#define SLICE_CHUNKS 43                 // 43*32 = 1376 rows per slice; 73*1376 >= 100000
#define KA_STR 272                      // A tile row stride bytes (128 bf16 + pad)
#define KB_STR 528                      // B tile row stride bytes (256 bf16 + pad)
#define KAB (32 * KA_STR)               // 8704
#define KBB (32 * KB_STR)               // 16896
#define KBUF (2 * KAB + 2 * KBB)        // 51200 per stage
#define KSMEM (2 * KBUF)                // 102400

// ---------------- scratch (static device globals; no allocation) ------------
__device__ float g_h [(size_t)NROWS * CH];
__device__ float g_h2[(size_t)NROWS * CH];
__device__ float g_q [(size_t)NROWS * CH];
__device__ float g_v [(size_t)NROWS * CH];
__device__ float g_part[(size_t)NSLICE * CH * CH];
__device__ float g_scal[CH + 4];   // [0]=||q||^2 [1]=||k||^2 [4..259]=col-sums of k
__device__ float g_dp[NROWS];
__device__ __nv_bfloat16 g_xh[(size_t)NROWS * CH], g_xl[(size_t)NROWS * CH];
__device__ __nv_bfloat16 g_ahh[(size_t)NROWS * CH], g_ahl[(size_t)NROWS * CH];
__device__ __nv_bfloat16 g_bhh[(size_t)NROWS * CH], g_bhl[(size_t)NROWS * CH];
__device__ __nv_bfloat16 g_qh[(size_t)NROWS * CH], g_ql[(size_t)NROWS * CH];
__device__ __nv_bfloat16 g_kh[(size_t)NROWS * CH], g_kl[(size_t)NROWS * CH];
__device__ __nv_bfloat16 g_vh[(size_t)NROWS * CH], g_vl[(size_t)NROWS * CH];
__device__ __nv_bfloat16 g_wh[7 * 65536], g_wl[7 * 65536];
__device__ __nv_bfloat16 g_bth[65536], g_btl[65536];

// ---------------- helpers ---------------------------------------------------
__device__ __forceinline__ uint32_t smem_u32(const void* p) {
  uint32_t a;
  asm("{ .reg .u64 t; cvta.to.shared.u64 t, %1; cvt.u32.u64 %0, t; }" : "=r"(a) : "l"(p));
  return a;
}
#define CP16(dst, src) \
  asm volatile("cp.async.cg.shared.global [%0], [%1], 16;" :: "r"(dst), "l"(src))
#define CP16Z(dst, src, vb) \
  asm volatile("cp.async.cg.shared.global [%0], [%1], 16, %2;" :: "r"(dst), "l"(src), "r"(vb))
#define CP_COMMIT() asm volatile("cp.async.commit_group;" ::: "memory")
#define CP_WAIT(n) asm volatile("cp.async.wait_group %0;" :: "n"(n) : "memory")

__device__ __forceinline__ void ldm_x4(uint32_t* r, uint32_t addr) {
  asm volatile("ldmatrix.sync.aligned.m8n8.x4.shared.b16 {%0,%1,%2,%3}, [%4];"
               : "=r"(r[0]), "=r"(r[1]), "=r"(r[2]), "=r"(r[3]) : "r"(addr));
}
__device__ __forceinline__ void ldm_x2(uint32_t* r, uint32_t addr) {
  asm volatile("ldmatrix.sync.aligned.m8n8.x2.shared.b16 {%0,%1}, [%2];"
               : "=r"(r[0]), "=r"(r[1]) : "r"(addr));
}
__device__ __forceinline__ void ldm_x4t(uint32_t* r, uint32_t addr) {
  asm volatile("ldmatrix.sync.aligned.m8n8.x4.trans.shared.b16 {%0,%1,%2,%3}, [%4];"
               : "=r"(r[0]), "=r"(r[1]), "=r"(r[2]), "=r"(r[3]) : "r"(addr));
}
__device__ __forceinline__ void ldm_x2t(uint32_t* r, uint32_t addr) {
  asm volatile("ldmatrix.sync.aligned.m8n8.x2.trans.shared.b16 {%0,%1}, [%2];"
               : "=r"(r[0]), "=r"(r[1]) : "r"(addr));
}
__device__ __forceinline__ void mma_bf16(float* c, const uint32_t* a, const uint32_t* b) {
  asm volatile(
      "mma.sync.aligned.m16n8k16.row.col.f32.bf16.bf16.f32 "
      "{%0,%1,%2,%3}, {%4,%5,%6,%7}, {%8,%9}, {%0,%1,%2,%3};"
      : "+f"(c[0]), "+f"(c[1]), "+f"(c[2]), "+f"(c[3])
      : "r"(a[0]), "r"(a[1]), "r"(a[2]), "r"(a[3]), "r"(b[0]), "r"(b[1]));
}
__device__ __forceinline__ float wredf(float v) {
#pragma unroll
  for (int o = 16; o > 0; o >>= 1) v += __shfl_xor_sync(0xffffffffu, v, o);
  return v;
}
__device__ __forceinline__ unsigned short bfb(__nv_bfloat16 h) {
  return *reinterpret_cast<unsigned short*>(&h);
}
__device__ __forceinline__ void packhl(float v0, float v1, uint32_t& hi, uint32_t& lo) {
  __nv_bfloat16 h0 = __float2bfloat16(v0), h1 = __float2bfloat16(v1);
  __nv_bfloat16 l0 = __float2bfloat16(v0 - __bfloat162float(h0));
  __nv_bfloat16 l1 = __float2bfloat16(v1 - __bfloat162float(h1));
  hi = (uint32_t)bfb(h0) | ((uint32_t)bfb(h1) << 16);
  lo = (uint32_t)bfb(l0) | ((uint32_t)bfb(l1) << 16);
}

// ---------------------------------------------------------------------------
__global__ void split_kernel(const float* __restrict__ src,
                             __nv_bfloat16* __restrict__ hi,
                             __nv_bfloat16* __restrict__ lo, int n) {
  int i = blockIdx.x * blockDim.x + threadIdx.x;
  if (i < n) {
    float x = src[i];
    __nv_bfloat16 h = __float2bfloat16(x);
    hi[i] = h;
    lo[i] = __float2bfloat16(x - __bfloat162float(h));
  }
}
__global__ void zero_kernel(float* p, int n) {
  int i = blockIdx.x * blockDim.x + threadIdx.x;
  if (i < n) p[i] = 0.f;
}

// dp[r] = q[r,:] . ks_sum
__global__ void __launch_bounds__(NTHR) dp_kernel(const float* __restrict__ Q,
                                                  const float* __restrict__ scal,
                                                  float* __restrict__ dp) {
  int tid = threadIdx.x, w = tid >> 5, l = tid & 31;
  int rsub = l >> 3, cseg = l & 7;
  int r = blockIdx.x * 32 + w * 4 + rsub;
  float s = 0.f;
  if (r < NROWS) {
    const float4* q4 = (const float4*)(Q + (size_t)r * CH + cseg * 32);
    const float4* k4 = (const float4*)(scal + 4 + cseg * 32);
#pragma unroll
    for (int i = 0; i < 8; i++) {
      float4 a = q4[i], b = k4[i];
      s += a.x * b.x + a.y * b.y + a.z * b.z + a.w * b.w;
    }
  }
#pragma unroll
  for (int o = 4; o > 0; o >>= 1) s += __shfl_xor_sync(0xffffffffu, s, o);
  if (cseg == 0 && r < NROWS) dp[r] = s;
}

// ---------------------------------------------------------------------------
// MMA GEMM: C[128,256] = A[128,256] @ W[256,256]^T, bf16-split, fp32 acc regs.
// ---------------------------------------------------------------------------
#define EPI_LN   0
#define EPI_Q    1
#define EPI_K    2
#define EPI_V    3
#define EPI_ATTN 4

#define ACCV(jr, nt, c) acc[(jr) >> 1][nt][(((jr) & 1) << 1) + (c)]

template<int EPI>
__global__ void __launch_bounds__(NTHR, 1) gemm_mma(
    const __nv_bfloat16* __restrict__ Ah, const __nv_bfloat16* __restrict__ Al,
    const __nv_bfloat16* __restrict__ Wh, const __nv_bfloat16* __restrict__ Wl,
    const float* __restrict__ bias,
    float* __restrict__ Cf, __nv_bfloat16* __restrict__ Chi, __nv_bfloat16* __restrict__ Clo,
    const float* __restrict__ gamma, const float* __restrict__ beta,
    float* __restrict__ normAcc, float* __restrict__ colAcc,
    const float* __restrict__ scal, const float* __restrict__ dpv,
    const float* __restrict__ Vf, const float* __restrict__ Pf)
{
  extern __shared__ char smem[];
  const uint32_t sb = smem_u32(smem);
  const int tid = threadIdx.x, w = tid >> 5, l = tid & 31;
  const int wrow = w >> 1, wcol = w & 1;
  const int m0 = blockIdx.x * TM;

  float* sS1  = (float*)(smem + SCR);
  float* sS2  = (float*)(smem + SCR + 1024);
  float* sCol = (float*)(smem + SCR + 2048);
  float* sRed = (float*)(smem + SCR + 3072);
  if (EPI == EPI_K) sCol[tid] = 0.f;

  float acc[2][16][4];
#pragma unroll
  for (int a = 0; a < 2; a++)
#pragma unroll
    for (int b = 0; b < 16; b++)
#pragma unroll
      for (int c = 0; c < 4; c++) acc[a][b][c] = 0.f;

  auto issue = [&](int ch, int buf) {
    const uint32_t base = sb + buf * BUFB;
    const int k0 = ch * 32;
#pragma unroll
    for (int t = 0; t < 2; t++) {
      int idx = tid + t * 256;
      int row = idx >> 2, seg = idx & 3;
      int gr = m0 + row; if (gr > NROWS - 1) gr = NROWS - 1;
      size_t g = (size_t)gr * CH + k0 + seg * 8;
      uint32_t so = row * 80 + seg * 16;
      CP16(base + so, Ah + g);
      CP16(base + AB + so, Al + g);
    }
#pragma unroll
    for (int t = 0; t < 4; t++) {
      int idx = tid + t * 256;
      int row = idx >> 2, seg = idx & 3;
      size_t g = (size_t)row * CH + k0 + seg * 8;
      uint32_t so = row * 80 + seg * 16;
      CP16(base + 2 * AB + so, Wh + g);
      CP16(base + 2 * AB + WB + so, Wl + g);
    }
  };

  issue(0, 0); CP_COMMIT();
#pragma unroll
  for (int ch = 0; ch < 8; ch++) {
    if (ch < 7) { issue(ch + 1, (ch + 1) & 1); CP_COMMIT(); CP_WAIT(1); }
    else CP_WAIT(0);
    __syncthreads();
    const uint32_t base = sb + (ch & 1) * BUFB;
#pragma unroll
    for (int kt = 0; kt < 2; kt++) {
      uint32_t ah[2][4], al_[2][4];
#pragma unroll
      for (int mt = 0; mt < 2; mt++) {
        int row = wrow * 32 + mt * 16 + (l & 15);
        int col = kt * 16 + ((l >> 4) << 3);
        uint32_t off = row * 80 + col * 2;
        ldm_x4(ah[mt], base + off);
        ldm_x4(al_[mt], base + AB + off);
      }
#pragma unroll
      for (int nt = 0; nt < 16; nt++) {
        int n = wcol * 128 + nt * 8 + (l & 7);
        int col = kt * 16 + ((l >> 3) & 1) * 8;
        uint32_t off = n * 80 + col * 2;
        uint32_t bh[2], bl[2];
        ldm_x2(bh, base + 2 * AB + off);
        ldm_x2(bl, base + 2 * AB + WB + off);
#pragma unroll
        for (int mt = 0; mt < 2; mt++) {
          mma_bf16(acc[mt][nt], ah[mt], bh);
          mma_bf16(acc[mt][nt], ah[mt], bl);
          mma_bf16(acc[mt][nt], al_[mt], bh);
        }
      }
    }
    __syncthreads();
  }

  // ---------------- epilogue -------------------------------------------------
  const int qlane = l >> 2;
  const int cbase = wcol * 128 + (l & 3) * 2;

  if (EPI == EPI_Q || EPI == EPI_K || EPI == EPI_V) {
    float nrm = 0.f;
#pragma unroll
    for (int nt = 0; nt < 16; nt++) {
      const int col = cbase + nt * 8;
      float2 bs = *(const float2*)(bias + col);
      float cs0 = 0.f, cs1 = 0.f;
#pragma unroll
      for (int jr = 0; jr < 4; jr++) {
        int r = m0 + wrow * 32 + (jr >> 1) * 16 + (jr & 1) * 8 + qlane;
        bool valid = r < NROWS;
        float v0 = ACCV(jr, nt, 0) + bs.x;
        float v1 = ACCV(jr, nt, 1) + bs.y;
        if (valid) {
          if (EPI == EPI_Q || EPI == EPI_K) nrm = fmaf(v0, v0, fmaf(v1, v1, nrm));
          if (EPI == EPI_K) { cs0 += v0; cs1 += v1; }
          if (EPI != EPI_K) *(float2*)(Cf + (size_t)r * CH + col) = make_float2(v0, v1);
          uint32_t hi, lo;
          packhl(v0, v1, hi, lo);
          *(uint32_t*)(Chi + (size_t)r * CH + col) = hi;
          *(uint32_t*)(Clo + (size_t)r * CH + col) = lo;
        }
      }
      if (EPI == EPI_K) {
#pragma unroll
        for (int o = 4; o < 32; o <<= 1) {
          cs0 += __shfl_xor_sync(0xffffffffu, cs0, o);
          cs1 += __shfl_xor_sync(0xffffffffu, cs1, o);
        }
        if (qlane == 0) { atomicAdd(&sCol[col], cs0); atomicAdd(&sCol[col + 1], cs1); }
      }
    }
    if (EPI == EPI_Q || EPI == EPI_K) {
      float p = wredf(nrm);
      if (l == 0) sRed[w] = p;
      __syncthreads();
      if (tid == 0) {
        float s = 0.f;
#pragma unroll
        for (int i = 0; i < 8; i++) s += sRed[i];
        atomicAdd(normAcc, s);
      }
      if (EPI == EPI_K) atomicAdd(&colAcc[tid], sCol[tid]);
    }
  } else {
    const float nF = (float)NROWS;
    float cN = 0.f;
    if (EPI == EPI_ATTN) cN = rsqrtf(scal[0] * scal[1]);
#pragma unroll
    for (int jr = 0; jr < 4; jr++) {
      const int lrow = wrow * 32 + (jr >> 1) * 16 + (jr & 1) * 8 + qlane;
      const int r = m0 + lrow;
      const bool valid = r < NROWS;
      float invr = 0.f;
      if (EPI == EPI_ATTN) invr = 1.f / fmaf(cN, valid ? dpv[r] : 0.f, nF);
      float s1 = 0.f, s2 = 0.f;
#pragma unroll
      for (int nt = 0; nt < 16; nt++) {
        const int col = cbase + nt * 8;
        if (EPI == EPI_LN) {
          float2 bs = *(const float2*)(bias + col);
          float y0 = ACCV(jr, nt, 0) + bs.x;
          float y1 = ACCV(jr, nt, 1) + bs.y;
          ACCV(jr, nt, 0) = y0; ACCV(jr, nt, 1) = y1;
          s1 += y0 + y1; s2 = fmaf(y0, y0, fmaf(y1, y1, s2));
        } else {
          float2 vv = valid ? *(const float2*)(Vf + (size_t)r * CH + col) : make_float2(0.f, 0.f);
          float2 pp = valid ? *(const float2*)(Pf + (size_t)r * CH + col) : make_float2(0.f, 0.f);
          float h0 = 0.5f * (fmaf(cN, ACCV(jr, nt, 0), nF * vv.x) * invr + pp.x);
          float h1 = 0.5f * (fmaf(cN, ACCV(jr, nt, 1), nF * vv.y) * invr + pp.y);
          ACCV(jr, nt, 0) = h0; ACCV(jr, nt, 1) = h1;
          s1 += h0 + h1; s2 = fmaf(h0, h0, fmaf(h1, h1, s2));
        }
      }
#pragma unroll
      for (int o = 1; o < 4; o <<= 1) {
        s1 += __shfl_xor_sync(0xffffffffu, s1, o);
        s2 += __shfl_xor_sync(0xffffffffu, s2, o);
      }
      if ((l & 3) == 0) { sS1[wcol * 128 + lrow] = s1; sS2[wcol * 128 + lrow] = s2; }
    }
    __syncthreads();
#pragma unroll
    for (int jr = 0; jr < 4; jr++) {
      const int lrow = wrow * 32 + (jr >> 1) * 16 + (jr & 1) * 8 + qlane;
      const int r = m0 + lrow;
      const bool valid = r < NROWS;
      const float s1 = sS1[lrow] + sS1[128 + lrow];
      const float s2 = sS2[lrow] + sS2[128 + lrow];
      const float mu = s1 * (1.f / CH);
      const float rs = rsqrtf(s2 * (1.f / CH) - mu * mu + 1e-5f);
#pragma unroll
      for (int nt = 0; nt < 16; nt++) {
        const int col = cbase + nt * 8;
        float2 gg = *(const float2*)(gamma + col);
        float2 bb = *(const float2*)(beta + col);
        float o0 = fmaxf((ACCV(jr, nt, 0) - mu) * rs * gg.x + bb.x, 0.f);
        float o1 = fmaxf((ACCV(jr, nt, 1) - mu) * rs * gg.y + bb.y, 0.f);
        if (valid) {
          *(float2*)(Cf + (size_t)r * CH + col) = make_float2(o0, o1);
          uint32_t hi, lo;
          packhl(o0, o1, hi, lo);
          *(uint32_t*)(Chi + (size_t)r * CH + col) = hi;
          *(uint32_t*)(Clo + (size_t)r * CH + col) = lo;
        }
      }
    }
  }
}

// ---------------------------------------------------------------------------
// MMA kvs: part[s][m][d] = sum over slice-s rows n of K[n,m]*V[n,d]
// A = K^T (trans-loaded), B = V^T (trans-loaded), bf16-split, fp32 acc.
// ---------------------------------------------------------------------------
__global__ void __launch_bounds__(NTHR, 1) gemm_kvs(
    const __nv_bfloat16* __restrict__ Kh, const __nv_bfloat16* __restrict__ Kl,
    const __nv_bfloat16* __restrict__ Vh, const __nv_bfloat16* __restrict__ Vl,
    float* __restrict__ part)
{
  extern __shared__ char smem[];
  const uint32_t sb = smem_u32(smem);
  const int tid = threadIdx.x, w = tid >> 5, l = tid & 31;
  const int wrow = w >> 1, wcol = w & 1;
  const int m0 = blockIdx.x * 128;
  const int n0 = blockIdx.y * (SLICE_CHUNKS * 32);

  float acc[2][16][4];
#pragma unroll
  for (int a = 0; a < 2; a++)
#pragma unroll
    for (int b = 0; b < 16; b++)
#pragma unroll
      for (int c = 0; c < 4; c++) acc[a][b][c] = 0.f;

  auto issue = [&](int ch, int buf) {
    const uint32_t base = sb + buf * KBUF;
    const int nb = n0 + ch * 32;
    // A: K rows (32 n) x 128 m-cols, hi+lo
#pragma unroll
    for (int t = 0; t < 2; t++) {
      int idx = tid + t * 256;
      int row = idx >> 4, seg = idx & 15;
      int gn = nb + row;
      uint32_t vb = (gn < NROWS) ? 16u : 0u;
      if (gn > NROWS - 1) gn = NROWS - 1;
      size_t g = (size_t)gn * CH + m0 + seg * 8;
      uint32_t so = row * KA_STR + seg * 16;
      CP16Z(base + so, Kh + g, vb);
      CP16Z(base + KAB + so, Kl + g, vb);
    }
    // B: V rows (32 n) x 256 d, hi+lo
#pragma unroll
    for (int t = 0; t < 4; t++) {
      int idx = tid + t * 256;
      int row = idx >> 5, seg = idx & 31;
      int gn = nb + row;
      uint32_t vb = (gn < NROWS) ? 16u : 0u;
      if (gn > NROWS - 1) gn = NROWS - 1;
      size_t g = (size_t)gn * CH + seg * 8;
      uint32_t so = row * KB_STR + seg * 16;
      CP16Z(base + 2 * KAB + so, Vh + g, vb);
      CP16Z(base + 2 * KAB + KBB + so, Vl + g, vb);
    }
  };

  issue(0, 0); CP_COMMIT();
  for (int ch = 0; ch < SLICE_CHUNKS; ch++) {
    if (ch < SLICE_CHUNKS - 1) { issue(ch + 1, (ch + 1) & 1); CP_COMMIT(); CP_WAIT(1); }
    else CP_WAIT(0);
    __syncthreads();
    const uint32_t base = sb + (ch & 1) * KBUF;
#pragma unroll
    for (int kt = 0; kt < 2; kt++) {
      const int k0 = kt * 16;
      uint32_t ah[2][4], al_[2][4];
#pragma unroll
      for (int mt = 0; mt < 2; mt++) {
        // A-trans x4: tiles (k0,m0),(k0,m+8),(k8,m0),(k8,m+8)
        int krow = k0 + (l & 7) + ((l >> 4) << 3);
        int mcol = wrow * 32 + mt * 16 + ((l >> 3) & 1) * 8;
        uint32_t off = krow * KA_STR + mcol * 2;
        ldm_x4t(ah[mt], base + off);
        ldm_x4t(al_[mt], base + KAB + off);
      }
#pragma unroll
      for (int nt = 0; nt < 16; nt++) {
        int d0 = wcol * 128 + nt * 8;
        int krow = k0 + (l & 7) + ((l >> 3) & 1) * 8;
        uint32_t off = krow * KB_STR + d0 * 2;
        uint32_t bh[2], bl[2];
        ldm_x2t(bh, base + 2 * KAB + off);
        ldm_x2t(bl, base + 2 * KAB + KBB + off);
#pragma unroll
        for (int mt = 0; mt < 2; mt++) {
          mma_bf16(acc[mt][nt], ah[mt], bh);
          mma_bf16(acc[mt][nt], ah[mt], bl);
          mma_bf16(acc[mt][nt], al_[mt], bh);
        }
      }
    }
    __syncthreads();
  }

  // write partial tile [128 m x 256 d] for this slice
  float* dst = part + (size_t)blockIdx.y * (CH * CH);
  const int qlane = l >> 2;
  const int cbase = wcol * 128 + (l & 3) * 2;
#pragma unroll
  for (int jr = 0; jr < 4; jr++) {
    int m = m0 + wrow * 32 + (jr >> 1) * 16 + (jr & 1) * 8 + qlane;
#pragma unroll
    for (int nt = 0; nt < 16; nt++) {
      int d = cbase + nt * 8;
      *(float2*)(dst + (size_t)m * CH + d) = make_float2(ACCV(jr, nt, 0), ACCV(jr, nt, 1));
    }
  }
}

// sum slices; write TRANSPOSED hi/lo bf16: bt[d*256+m] = kvs[m][d]
__global__ void kvs_reduce(const float* __restrict__ part,
                           __nv_bfloat16* __restrict__ bth,
                           __nv_bfloat16* __restrict__ btl) {
  int idx = blockIdx.x * blockDim.x + threadIdx.x;
  if (idx < CH * CH) {
    int m = idx >> 8, d = idx & 255;   // coalesced reads over part rows
    float s = 0.f;
#pragma unroll
    for (int ss = 0; ss < NSLICE; ss++) s += part[(size_t)ss * CH * CH + idx];
    __nv_bfloat16 h = __float2bfloat16(s);
    __nv_bfloat16 lo = __float2bfloat16(s - __bfloat162float(h));
    bth[d * CH + m] = h;
    btl[d * CH + m] = lo;
  }
}

// ---------------------------------------------------------------------------
extern "C" void kernel_launch(void* const* d_in, const int* in_sizes, int n_in,
                              void* d_out, int out_size) {
  (void)in_sizes; (void)n_in; (void)out_size;
  const float* x    = (const float*)d_in[0];
  const float* fc_w = (const float*)d_in[1];
  const float* fc_b = (const float*)d_in[2];
  const float* Wq_w = (const float*)d_in[3];
  const float* Wq_b = (const float*)d_in[4];
  const float* Wk_w = (const float*)d_in[5];
  const float* Wk_b = (const float*)d_in[6];
  const float* Wv_w = (const float*)d_in[7];
  const float* Wv_b = (const float*)d_in[8];
  const float* ln_g = (const float*)d_in[9];
  const float* ln_b = (const float*)d_in[10];
  float* out = (float*)d_out;

  float *hA, *hB, *q, *v, *part, *scal, *dp;
  __nv_bfloat16 *xh, *xl, *ahh, *ahl, *bhh, *bhl, *qh, *ql, *kh, *kl, *vh, *vl, *wh, *wl, *bth, *btl;
  cudaGetSymbolAddress((void**)&hA, g_h);
  cudaGetSymbolAddress((void**)&hB, g_h2);
  cudaGetSymbolAddress((void**)&q, g_q);
  cudaGetSymbolAddress((void**)&v, g_v);
  cudaGetSymbolAddress((void**)&part, g_part);
  cudaGetSymbolAddress((void**)&scal, g_scal);
  cudaGetSymbolAddress((void**)&dp, g_dp);
  cudaGetSymbolAddress((void**)&xh, g_xh);  cudaGetSymbolAddress((void**)&xl, g_xl);
  cudaGetSymbolAddress((void**)&ahh, g_ahh); cudaGetSymbolAddress((void**)&ahl, g_ahl);
  cudaGetSymbolAddress((void**)&bhh, g_bhh); cudaGetSymbolAddress((void**)&bhl, g_bhl);
  cudaGetSymbolAddress((void**)&qh, g_qh);  cudaGetSymbolAddress((void**)&ql, g_ql);
  cudaGetSymbolAddress((void**)&kh, g_kh);  cudaGetSymbolAddress((void**)&kl, g_kl);
  cudaGetSymbolAddress((void**)&vh, g_vh);  cudaGetSymbolAddress((void**)&vl, g_vl);
  cudaGetSymbolAddress((void**)&wh, g_wh);  cudaGetSymbolAddress((void**)&wl, g_wl);
  cudaGetSymbolAddress((void**)&bth, g_bth); cudaGetSymbolAddress((void**)&btl, g_btl);

  cudaFuncSetAttribute(gemm_mma<EPI_LN>,   cudaFuncAttributeMaxDynamicSharedMemorySize, SMEM_SZ);
  cudaFuncSetAttribute(gemm_mma<EPI_Q>,    cudaFuncAttributeMaxDynamicSharedMemorySize, SMEM_SZ);
  cudaFuncSetAttribute(gemm_mma<EPI_K>,    cudaFuncAttributeMaxDynamicSharedMemorySize, SMEM_SZ);
  cudaFuncSetAttribute(gemm_mma<EPI_V>,    cudaFuncAttributeMaxDynamicSharedMemorySize, SMEM_SZ);
  cudaFuncSetAttribute(gemm_mma<EPI_ATTN>, cudaFuncAttributeMaxDynamicSharedMemorySize, SMEM_SZ);
  cudaFuncSetAttribute(gemm_kvs, cudaFuncAttributeMaxDynamicSharedMemorySize, KSMEM);

  const int WSZ = CH * CH;
  split_kernel<<<WSZ / 256, 256>>>(fc_w, wh, wl, WSZ);
  for (int L = 0; L < 2; L++) {
    split_kernel<<<WSZ / 256, 256>>>(Wq_w + (size_t)L * WSZ, wh + (1 + 3 * L) * WSZ, wl + (1 + 3 * L) * WSZ, WSZ);
    split_kernel<<<WSZ / 256, 256>>>(Wk_w + (size_t)L * WSZ, wh + (2 + 3 * L) * WSZ, wl + (2 + 3 * L) * WSZ, WSZ);
    split_kernel<<<WSZ / 256, 256>>>(Wv_w + (size_t)L * WSZ, wh + (3 + 3 * L) * WSZ, wl + (3 + 3 * L) * WSZ, WSZ);
  }
  split_kernel<<<(NROWS * CH + 255) / 256, 256>>>(x, xh, xl, NROWS * CH);

  gemm_mma<EPI_LN><<<TGRID, NTHR, SMEM_SZ>>>(
      xh, xl, wh, wl, fc_b, hA, ahh, ahl, ln_g, ln_b,
      nullptr, nullptr, nullptr, nullptr, nullptr, nullptr);

  for (int L = 0; L < 2; L++) {
    const __nv_bfloat16* hh = L ? bhh : ahh;
    const __nv_bfloat16* hl = L ? bhl : ahl;
    const float* hP = L ? hB : hA;
    float* ob = L ? out : hB;
    const size_t bo = (size_t)L * CH;

    zero_kernel<<<1, CH + 4>>>(scal, CH + 4);
    gemm_mma<EPI_Q><<<TGRID, NTHR, SMEM_SZ>>>(
        hh, hl, wh + (1 + 3 * L) * WSZ, wl + (1 + 3 * L) * WSZ, Wq_b + bo,
        q, qh, ql, nullptr, nullptr, scal + 0, nullptr, nullptr, nullptr, nullptr, nullptr);
    gemm_mma<EPI_K><<<TGRID, NTHR, SMEM_SZ>>>(
        hh, hl, wh + (2 + 3 * L) * WSZ, wl + (2 + 3 * L) * WSZ, Wk_b + bo,
        nullptr, kh, kl, nullptr, nullptr, scal + 1, scal + 4, nullptr, nullptr, nullptr, nullptr);
    gemm_mma<EPI_V><<<TGRID, NTHR, SMEM_SZ>>>(
        hh, hl, wh + (3 + 3 * L) * WSZ, wl + (3 + 3 * L) * WSZ, Wv_b + bo,
        v, vh, vl, nullptr, nullptr, nullptr, nullptr, nullptr, nullptr, nullptr, nullptr);
    dp_kernel<<<(NROWS + 31) / 32, NTHR>>>(q, scal, dp);
    gemm_kvs<<<dim3(2, NSLICE), NTHR, KSMEM>>>(kh, kl, vh, vl, part);
    kvs_reduce<<<64, 1024>>>(part, bth, btl);
    gemm_mma<EPI_ATTN><<<TGRID, NTHR, SMEM_SZ>>>(
        qh, ql, bth, btl, nullptr, ob, bhh, bhl,
        ln_g + (size_t)(L + 1) * CH, ln_b + (size_t)(L + 1) * CH,
        nullptr, nullptr, scal, dp, v, hP);
  }
}

// round 10
// speedup vs baseline: 2.4944x; 1.0482x over previous
#include <cuda_runtime.h>
#include <cuda_bf16.h>
#include <cstdint>

#define NROWS 100000
#define CH 256
#define NTHR 256
// ---- MMA gemm params ----
#define TM 128
#define TGRID ((NROWS + TM - 1) / TM)   // 782
#define AB (128 * 80)
#define WB (256 * 80)
#define BUFB (2 * AB + 2 * WB)
#define SCR (2 * BUFB)
#define SMEM_SZ (SCR + 4096)
// ---- kvs MMA params ----
#define NSLICE 73
#define SLICE_CHUNKS 43
#define KA_STR 272
#define KB_STR 528
#define KAB (32 * KA_STR)
#define KBB (32 * KB_STR)
#define KBUF (2 * KAB + 2 * KBB)        // 51200 per stage
#define KSMEM (3 * KBUF)                // 3-stage pipeline

// ---------------- scratch -----------------------------------------------------
__device__ float g_h [(size_t)NROWS * CH];
__device__ float g_h2[(size_t)NROWS * CH];
__device__ float g_v [(size_t)NROWS * CH];
__device__ float g_part[(size_t)NSLICE * CH * CH];
__device__ float g_scal[CH + 4];
__device__ float g_dp[NROWS];
__device__ __nv_bfloat16 g_xh[(size_t)NROWS * CH], g_xl[(size_t)NROWS * CH];
__device__ __nv_bfloat16 g_ahh[(size_t)NROWS * CH], g_ahl[(size_t)NROWS * CH];
__device__ __nv_bfloat16 g_bhh[(size_t)NROWS * CH], g_bhl[(size_t)NROWS * CH];
__device__ __nv_bfloat16 g_qh[(size_t)NROWS * CH], g_ql[(size_t)NROWS * CH];
__device__ __nv_bfloat16 g_kh[(size_t)NROWS * CH], g_kl[(size_t)NROWS * CH];
__device__ __nv_bfloat16 g_vh[(size_t)NROWS * CH], g_vl[(size_t)NROWS * CH];
__device__ __nv_bfloat16 g_wh[7 * 65536], g_wl[7 * 65536];
__device__ __nv_bfloat16 g_bth[65536], g_btl[65536];

// ---------------- helpers ------------------------------------------------------
__device__ __forceinline__ uint32_t smem_u32(const void* p) {
  uint32_t a;
  asm("{ .reg .u64 t; cvta.to.shared.u64 t, %1; cvt.u32.u64 %0, t; }" : "=r"(a) : "l"(p));
  return a;
}
#define CP16(dst, src) \
  asm volatile("cp.async.cg.shared.global [%0], [%1], 16;" :: "r"(dst), "l"(src))
#define CP16Z(dst, src, vb) \
  asm volatile("cp.async.cg.shared.global [%0], [%1], 16, %2;" :: "r"(dst), "l"(src), "r"(vb))
#define CP_COMMIT() asm volatile("cp.async.commit_group;" ::: "memory")
#define CP_WAIT(n) asm volatile("cp.async.wait_group %0;" :: "n"(n) : "memory")

__device__ __forceinline__ void ldm_x4(uint32_t* r, uint32_t addr) {
  asm volatile("ldmatrix.sync.aligned.m8n8.x4.shared.b16 {%0,%1,%2,%3}, [%4];"
               : "=r"(r[0]), "=r"(r[1]), "=r"(r[2]), "=r"(r[3]) : "r"(addr));
}
__device__ __forceinline__ void ldm_x4t(uint32_t* r, uint32_t addr) {
  asm volatile("ldmatrix.sync.aligned.m8n8.x4.trans.shared.b16 {%0,%1,%2,%3}, [%4];"
               : "=r"(r[0]), "=r"(r[1]), "=r"(r[2]), "=r"(r[3]) : "r"(addr));
}
__device__ __forceinline__ void mma_bf16(float* c, const uint32_t* a, const uint32_t* b) {
  asm volatile(
      "mma.sync.aligned.m16n8k16.row.col.f32.bf16.bf16.f32 "
      "{%0,%1,%2,%3}, {%4,%5,%6,%7}, {%8,%9}, {%0,%1,%2,%3};"
      : "+f"(c[0]), "+f"(c[1]), "+f"(c[2]), "+f"(c[3])
      : "r"(a[0]), "r"(a[1]), "r"(a[2]), "r"(a[3]), "r"(b[0]), "r"(b[1]));
}
__device__ __forceinline__ float wredf(float v) {
#pragma unroll
  for (int o = 16; o > 0; o >>= 1) v += __shfl_xor_sync(0xffffffffu, v, o);
  return v;
}
__device__ __forceinline__ unsigned short bfb(__nv_bfloat16 h) {
  return *reinterpret_cast<unsigned short*>(&h);
}
__device__ __forceinline__ void packhl(float v0, float v1, uint32_t& hi, uint32_t& lo) {
  __nv_bfloat16 h0 = __float2bfloat16(v0), h1 = __float2bfloat16(v1);
  __nv_bfloat16 l0 = __float2bfloat16(v0 - __bfloat162float(h0));
  __nv_bfloat16 l1 = __float2bfloat16(v1 - __bfloat162float(h1));
  hi = (uint32_t)bfb(h0) | ((uint32_t)bfb(h1) << 16);
  lo = (uint32_t)bfb(l0) | ((uint32_t)bfb(l1) << 16);
}
__device__ __forceinline__ float2 bf2f2(uint32_t u) {
  __nv_bfloat162 b = *reinterpret_cast<__nv_bfloat162*>(&u);
  return __bfloat1622float2(b);
}

// ---------------------------------------------------------------------------
__global__ void split_kernel(const float* __restrict__ src,
                             __nv_bfloat16* __restrict__ hi,
                             __nv_bfloat16* __restrict__ lo, int n) {
  int i = blockIdx.x * blockDim.x + threadIdx.x;
  if (i < n) {
    float x = src[i];
    __nv_bfloat16 h = __float2bfloat16(x);
    hi[i] = h;
    lo[i] = __float2bfloat16(x - __bfloat162float(h));
  }
}
__global__ void zero_kernel(float* p, int n) {
  int i = blockIdx.x * blockDim.x + threadIdx.x;
  if (i < n) p[i] = 0.f;
}

// dp[r] = q[r,:] . ks_sum  (q reconstructed from hi+lo bf16)
__global__ void __launch_bounds__(NTHR) dp_kernel(const __nv_bfloat16* __restrict__ Qh,
                                                  const __nv_bfloat16* __restrict__ Ql,
                                                  const float* __restrict__ scal,
                                                  float* __restrict__ dp) {
  int tid = threadIdx.x, w = tid >> 5, l = tid & 31;
  int rsub = l >> 3, cseg = l & 7;
  int r = blockIdx.x * 32 + w * 4 + rsub;
  float s = 0.f;
  if (r < NROWS) {
    const uint4* qh4 = (const uint4*)(Qh + (size_t)r * CH + cseg * 32);
    const uint4* ql4 = (const uint4*)(Ql + (size_t)r * CH + cseg * 32);
    const float4* k4 = (const float4*)(scal + 4 + cseg * 32);
#pragma unroll
    for (int i = 0; i < 4; i++) {
      uint4 H = qh4[i], L = ql4[i];
      float4 ka = k4[2 * i], kb = k4[2 * i + 1];
      float2 h0 = bf2f2(H.x), l0 = bf2f2(L.x);
      float2 h1 = bf2f2(H.y), l1 = bf2f2(L.y);
      float2 h2 = bf2f2(H.z), l2 = bf2f2(L.z);
      float2 h3 = bf2f2(H.w), l3 = bf2f2(L.w);
      s += (h0.x + l0.x) * ka.x + (h0.y + l0.y) * ka.y;
      s += (h1.x + l1.x) * ka.z + (h1.y + l1.y) * ka.w;
      s += (h2.x + l2.x) * kb.x + (h2.y + l2.y) * kb.y;
      s += (h3.x + l3.x) * kb.z + (h3.y + l3.y) * kb.w;
    }
  }
#pragma unroll
  for (int o = 4; o > 0; o >>= 1) s += __shfl_xor_sync(0xffffffffu, s, o);
  if (cseg == 0 && r < NROWS) dp[r] = s;
}

// ---------------------------------------------------------------------------
// MMA GEMM: C[128,256] = A[128,256] @ W[256,256]^T, bf16-split, fp32 acc.
// ---------------------------------------------------------------------------
#define EPI_LN   0
#define EPI_Q    1
#define EPI_K    2
#define EPI_V    3
#define EPI_ATTN 4

#define ACCV(jr, nt, c) acc[(jr) >> 1][nt][(((jr) & 1) << 1) + (c)]

template<int EPI>
__global__ void __launch_bounds__(NTHR, 1) gemm_mma(
    const __nv_bfloat16* __restrict__ Ah, const __nv_bfloat16* __restrict__ Al,
    const __nv_bfloat16* __restrict__ Wh, const __nv_bfloat16* __restrict__ Wl,
    const float* __restrict__ bias,
    float* __restrict__ Cf, __nv_bfloat16* __restrict__ Chi, __nv_bfloat16* __restrict__ Clo,
    const float* __restrict__ gamma, const float* __restrict__ beta,
    float* __restrict__ normAcc, float* __restrict__ colAcc,
    const float* __restrict__ scal, const float* __restrict__ dpv,
    const float* __restrict__ Vf, const float* __restrict__ Pf)
{
  extern __shared__ char smem[];
  const uint32_t sb = smem_u32(smem);
  const int tid = threadIdx.x, w = tid >> 5, l = tid & 31;
  const int wrow = w >> 1, wcol = w & 1;
  const int m0 = blockIdx.x * TM;

  float* sS1  = (float*)(smem + SCR);
  float* sS2  = (float*)(smem + SCR + 1024);
  float* sCol = (float*)(smem + SCR + 2048);
  float* sRed = (float*)(smem + SCR + 3072);
  if (EPI == EPI_K) sCol[tid] = 0.f;

  float acc[2][16][4];
#pragma unroll
  for (int a = 0; a < 2; a++)
#pragma unroll
    for (int b = 0; b < 16; b++)
#pragma unroll
      for (int c = 0; c < 4; c++) acc[a][b][c] = 0.f;

  auto issue = [&](int ch, int buf) {
    const uint32_t base = sb + buf * BUFB;
    const int k0 = ch * 32;
#pragma unroll
    for (int t = 0; t < 2; t++) {
      int idx = tid + t * 256;
      int row = idx >> 2, seg = idx & 3;
      int gr = m0 + row; if (gr > NROWS - 1) gr = NROWS - 1;
      size_t g = (size_t)gr * CH + k0 + seg * 8;
      uint32_t so = row * 80 + seg * 16;
      CP16(base + so, Ah + g);
      CP16(base + AB + so, Al + g);
    }
#pragma unroll
    for (int t = 0; t < 4; t++) {
      int idx = tid + t * 256;
      int row = idx >> 2, seg = idx & 3;
      size_t g = (size_t)row * CH + k0 + seg * 8;
      uint32_t so = row * 80 + seg * 16;
      CP16(base + 2 * AB + so, Wh + g);
      CP16(base + 2 * AB + WB + so, Wl + g);
    }
  };

  issue(0, 0); CP_COMMIT();
#pragma unroll
  for (int ch = 0; ch < 8; ch++) {
    if (ch < 7) { issue(ch + 1, (ch + 1) & 1); CP_COMMIT(); CP_WAIT(1); }
    else CP_WAIT(0);
    __syncthreads();
    const uint32_t base = sb + (ch & 1) * BUFB;
#pragma unroll
    for (int kt = 0; kt < 2; kt++) {
      uint32_t ah[2][4], al_[2][4];
#pragma unroll
      for (int mt = 0; mt < 2; mt++) {
        int row = wrow * 32 + mt * 16 + (l & 15);
        int col = kt * 16 + ((l >> 4) << 3);
        uint32_t off = row * 80 + col * 2;
        ldm_x4(ah[mt], base + off);
        ldm_x4(al_[mt], base + AB + off);
      }
#pragma unroll
      for (int ntp = 0; ntp < 8; ntp++) {
        int n = wcol * 128 + ntp * 16 + ((l >> 4) << 3) + (l & 7);
        int col = kt * 16 + ((l >> 3) & 1) * 8;
        uint32_t off = n * 80 + col * 2;
        uint32_t bh4[4], bl4[4];
        ldm_x4(bh4, base + 2 * AB + off);
        ldm_x4(bl4, base + 2 * AB + WB + off);
#pragma unroll
        for (int mt = 0; mt < 2; mt++) {
          mma_bf16(acc[mt][2 * ntp],     ah[mt],  bh4);
          mma_bf16(acc[mt][2 * ntp],     ah[mt],  bl4);
          mma_bf16(acc[mt][2 * ntp],     al_[mt], bh4);
          mma_bf16(acc[mt][2 * ntp + 1], ah[mt],  bh4 + 2);
          mma_bf16(acc[mt][2 * ntp + 1], ah[mt],  bl4 + 2);
          mma_bf16(acc[mt][2 * ntp + 1], al_[mt], bh4 + 2);
        }
      }
    }
    __syncthreads();
  }

  // ---------------- epilogue -------------------------------------------------
  const int qlane = l >> 2;
  const int cbase = wcol * 128 + (l & 3) * 2;

  if (EPI == EPI_Q || EPI == EPI_K || EPI == EPI_V) {
    float nrm = 0.f;
#pragma unroll
    for (int nt = 0; nt < 16; nt++) {
      const int col = cbase + nt * 8;
      float2 bs = *(const float2*)(bias + col);
      float cs0 = 0.f, cs1 = 0.f;
#pragma unroll
      for (int jr = 0; jr < 4; jr++) {
        int r = m0 + wrow * 32 + (jr >> 1) * 16 + (jr & 1) * 8 + qlane;
        bool valid = r < NROWS;
        float v0 = ACCV(jr, nt, 0) + bs.x;
        float v1 = ACCV(jr, nt, 1) + bs.y;
        if (valid) {
          if (EPI == EPI_Q || EPI == EPI_K) nrm = fmaf(v0, v0, fmaf(v1, v1, nrm));
          if (EPI == EPI_K) { cs0 += v0; cs1 += v1; }
          if (EPI == EPI_V) *(float2*)(Cf + (size_t)r * CH + col) = make_float2(v0, v1);
          uint32_t hi, lo;
          packhl(v0, v1, hi, lo);
          *(uint32_t*)(Chi + (size_t)r * CH + col) = hi;
          *(uint32_t*)(Clo + (size_t)r * CH + col) = lo;
        }
      }
      if (EPI == EPI_K) {
#pragma unroll
        for (int o = 4; o < 32; o <<= 1) {
          cs0 += __shfl_xor_sync(0xffffffffu, cs0, o);
          cs1 += __shfl_xor_sync(0xffffffffu, cs1, o);
        }
        if (qlane == 0) { atomicAdd(&sCol[col], cs0); atomicAdd(&sCol[col + 1], cs1); }
      }
    }
    if (EPI == EPI_Q || EPI == EPI_K) {
      float p = wredf(nrm);
      if (l == 0) sRed[w] = p;
      __syncthreads();
      if (tid == 0) {
        float s = 0.f;
#pragma unroll
        for (int i = 0; i < 8; i++) s += sRed[i];
        atomicAdd(normAcc, s);
      }
      if (EPI == EPI_K) atomicAdd(&colAcc[tid], sCol[tid]);
    }
  } else {
    const float nF = (float)NROWS;
    float cN = 0.f;
    if (EPI == EPI_ATTN) cN = rsqrtf(scal[0] * scal[1]);
#pragma unroll
    for (int jr = 0; jr < 4; jr++) {
      const int lrow = wrow * 32 + (jr >> 1) * 16 + (jr & 1) * 8 + qlane;
      const int r = m0 + lrow;
      const bool valid = r < NROWS;
      float invr = 0.f;
      if (EPI == EPI_ATTN) invr = 1.f / fmaf(cN, valid ? dpv[r] : 0.f, nF);
      float s1 = 0.f, s2 = 0.f;
#pragma unroll
      for (int nt = 0; nt < 16; nt++) {
        const int col = cbase + nt * 8;
        if (EPI == EPI_LN) {
          float2 bs = *(const float2*)(bias + col);
          float y0 = ACCV(jr, nt, 0) + bs.x;
          float y1 = ACCV(jr, nt, 1) + bs.y;
          ACCV(jr, nt, 0) = y0; ACCV(jr, nt, 1) = y1;
          s1 += y0 + y1; s2 = fmaf(y0, y0, fmaf(y1, y1, s2));
        } else {
          float2 vv = valid ? *(const float2*)(Vf + (size_t)r * CH + col) : make_float2(0.f, 0.f);
          float2 pp = valid ? *(const float2*)(Pf + (size_t)r * CH + col) : make_float2(0.f, 0.f);
          float h0 = 0.5f * (fmaf(cN, ACCV(jr, nt, 0), nF * vv.x) * invr + pp.x);
          float h1 = 0.5f * (fmaf(cN, ACCV(jr, nt, 1), nF * vv.y) * invr + pp.y);
          ACCV(jr, nt, 0) = h0; ACCV(jr, nt, 1) = h1;
          s1 += h0 + h1; s2 = fmaf(h0, h0, fmaf(h1, h1, s2));
        }
      }
#pragma unroll
      for (int o = 1; o < 4; o <<= 1) {
        s1 += __shfl_xor_sync(0xffffffffu, s1, o);
        s2 += __shfl_xor_sync(0xffffffffu, s2, o);
      }
      if ((l & 3) == 0) { sS1[wcol * 128 + lrow] = s1; sS2[wcol * 128 + lrow] = s2; }
    }
    __syncthreads();
#pragma unroll
    for (int jr = 0; jr < 4; jr++) {
      const int lrow = wrow * 32 + (jr >> 1) * 16 + (jr & 1) * 8 + qlane;
      const int r = m0 + lrow;
      const bool valid = r < NROWS;
      const float s1 = sS1[lrow] + sS1[128 + lrow];
      const float s2 = sS2[lrow] + sS2[128 + lrow];
      const float mu = s1 * (1.f / CH);
      const float rs = rsqrtf(s2 * (1.f / CH) - mu * mu + 1e-5f);
#pragma unroll
      for (int nt = 0; nt < 16; nt++) {
        const int col = cbase + nt * 8;
        float2 gg = *(const float2*)(gamma + col);
        float2 bb = *(const float2*)(beta + col);
        float o0 = fmaxf((ACCV(jr, nt, 0) - mu) * rs * gg.x + bb.x, 0.f);
        float o1 = fmaxf((ACCV(jr, nt, 1) - mu) * rs * gg.y + bb.y, 0.f);
        if (valid) {
          *(float2*)(Cf + (size_t)r * CH + col) = make_float2(o0, o1);
          uint32_t hi, lo;
          packhl(o0, o1, hi, lo);
          *(uint32_t*)(Chi + (size_t)r * CH + col) = hi;
          *(uint32_t*)(Clo + (size_t)r * CH + col) = lo;
        }
      }
    }
  }
}

// ---------------------------------------------------------------------------
// MMA kvs: part[s][m][d] = sum over slice-s rows n of K[n,m]*V[n,d]
// 3-stage cp.async pipeline, trans ldmatrix, bf16-split.
// ---------------------------------------------------------------------------
__global__ void __launch_bounds__(NTHR, 1) gemm_kvs(
    const __nv_bfloat16* __restrict__ Kh, const __nv_bfloat16* __restrict__ Kl,
    const __nv_bfloat16* __restrict__ Vh, const __nv_bfloat16* __restrict__ Vl,
    float* __restrict__ part)
{
  extern __shared__ char smem[];
  const uint32_t sb = smem_u32(smem);
  const int tid = threadIdx.x, w = tid >> 5, l = tid & 31;
  const int wrow = w >> 1, wcol = w & 1;
  const int m0 = blockIdx.x * 128;
  const int n0 = blockIdx.y * (SLICE_CHUNKS * 32);

  float acc[2][16][4];
#pragma unroll
  for (int a = 0; a < 2; a++)
#pragma unroll
    for (int b = 0; b < 16; b++)
#pragma unroll
      for (int c = 0; c < 4; c++) acc[a][b][c] = 0.f;

  auto issue = [&](int ch, int buf) {
    const uint32_t base = sb + buf * KBUF;
    const int nb = n0 + ch * 32;
#pragma unroll
    for (int t = 0; t < 2; t++) {
      int idx = tid + t * 256;
      int row = idx >> 4, seg = idx & 15;
      int gn = nb + row;
      uint32_t vb = (gn < NROWS) ? 16u : 0u;
      if (gn > NROWS - 1) gn = NROWS - 1;
      size_t g = (size_t)gn * CH + m0 + seg * 8;
      uint32_t so = row * KA_STR + seg * 16;
      CP16Z(base + so, Kh + g, vb);
      CP16Z(base + KAB + so, Kl + g, vb);
    }
#pragma unroll
    for (int t = 0; t < 4; t++) {
      int idx = tid + t * 256;
      int row = idx >> 5, seg = idx & 31;
      int gn = nb + row;
      uint32_t vb = (gn < NROWS) ? 16u : 0u;
      if (gn > NROWS - 1) gn = NROWS - 1;
      size_t g = (size_t)gn * CH + seg * 8;
      uint32_t so = row * KB_STR + seg * 16;
      CP16Z(base + 2 * KAB + so, Vh + g, vb);
      CP16Z(base + 2 * KAB + KBB + so, Vl + g, vb);
    }
  };

  issue(0, 0); CP_COMMIT();
  issue(1, 1); CP_COMMIT();
  for (int ch = 0; ch < SLICE_CHUNKS; ch++) {
    if (ch + 1 < SLICE_CHUNKS) CP_WAIT(1); else CP_WAIT(0);
    __syncthreads();
    if (ch + 2 < SLICE_CHUNKS) { issue(ch + 2, (ch + 2) % 3); CP_COMMIT(); }
    const uint32_t base = sb + (ch % 3) * KBUF;
#pragma unroll
    for (int kt = 0; kt < 2; kt++) {
      const int k0 = kt * 16;
      uint32_t ah[2][4], al_[2][4];
#pragma unroll
      for (int mt = 0; mt < 2; mt++) {
        int krow = k0 + (l & 7) + ((l >> 4) << 3);
        int mcol = wrow * 32 + mt * 16 + ((l >> 3) & 1) * 8;
        uint32_t off = krow * KA_STR + mcol * 2;
        ldm_x4t(ah[mt], base + off);
        ldm_x4t(al_[mt], base + KAB + off);
      }
#pragma unroll
      for (int ntp = 0; ntp < 8; ntp++) {
        int d0 = wcol * 128 + ntp * 16 + ((l >> 4) << 3);
        int krow = k0 + (l & 7) + ((l >> 3) & 1) * 8;
        uint32_t off = krow * KB_STR + d0 * 2;
        uint32_t bh4[4], bl4[4];
        ldm_x4t(bh4, base + 2 * KAB + off);
        ldm_x4t(bl4, base + 2 * KAB + KBB + off);
#pragma unroll
        for (int mt = 0; mt < 2; mt++) {
          mma_bf16(acc[mt][2 * ntp],     ah[mt],  bh4);
          mma_bf16(acc[mt][2 * ntp],     ah[mt],  bl4);
          mma_bf16(acc[mt][2 * ntp],     al_[mt], bh4);
          mma_bf16(acc[mt][2 * ntp + 1], ah[mt],  bh4 + 2);
          mma_bf16(acc[mt][2 * ntp + 1], ah[mt],  bl4 + 2);
          mma_bf16(acc[mt][2 * ntp + 1], al_[mt], bh4 + 2);
        }
      }
    }
    __syncthreads();
  }

  float* dst = part + (size_t)blockIdx.y * (CH * CH);
  const int qlane = l >> 2;
  const int cbase = wcol * 128 + (l & 3) * 2;
#pragma unroll
  for (int jr = 0; jr < 4; jr++) {
    int m = m0 + wrow * 32 + (jr >> 1) * 16 + (jr & 1) * 8 + qlane;
#pragma unroll
    for (int nt = 0; nt < 16; nt++) {
      int d = cbase + nt * 8;
      *(float2*)(dst + (size_t)m * CH + d) = make_float2(ACCV(jr, nt, 0), ACCV(jr, nt, 1));
    }
  }
}

// sum slices; write TRANSPOSED hi/lo bf16: bt[d*256+m] = kvs[m][d]
__global__ void kvs_reduce(const float* __restrict__ part,
                           __nv_bfloat16* __restrict__ bth,
                           __nv_bfloat16* __restrict__ btl) {
  int idx = blockIdx.x * blockDim.x + threadIdx.x;
  if (idx < CH * CH) {
    int m = idx >> 8, d = idx & 255;
    float s = 0.f;
#pragma unroll
    for (int ss = 0; ss < NSLICE; ss++) s += part[(size_t)ss * CH * CH + idx];
    __nv_bfloat16 h = __float2bfloat16(s);
    __nv_bfloat16 lo = __float2bfloat16(s - __bfloat162float(h));
    bth[d * CH + m] = h;
    btl[d * CH + m] = lo;
  }
}

// ---------------------------------------------------------------------------
extern "C" void kernel_launch(void* const* d_in, const int* in_sizes, int n_in,
                              void* d_out, int out_size) {
  (void)in_sizes; (void)n_in; (void)out_size;
  const float* x    = (const float*)d_in[0];
  const float* fc_w = (const float*)d_in[1];
  const float* fc_b = (const float*)d_in[2];
  const float* Wq_w = (const float*)d_in[3];
  const float* Wq_b = (const float*)d_in[4];
  const float* Wk_w = (const float*)d_in[5];
  const float* Wk_b = (const float*)d_in[6];
  const float* Wv_w = (const float*)d_in[7];
  const float* Wv_b = (const float*)d_in[8];
  const float* ln_g = (const float*)d_in[9];
  const float* ln_b = (const float*)d_in[10];
  float* out = (float*)d_out;

  float *hA, *hB, *v, *part, *scal, *dp;
  __nv_bfloat16 *xh, *xl, *ahh, *ahl, *bhh, *bhl, *qh, *ql, *kh, *kl, *vh, *vl, *wh, *wl, *bth, *btl;
  cudaGetSymbolAddress((void**)&hA, g_h);
  cudaGetSymbolAddress((void**)&hB, g_h2);
  cudaGetSymbolAddress((void**)&v, g_v);
  cudaGetSymbolAddress((void**)&part, g_part);
  cudaGetSymbolAddress((void**)&scal, g_scal);
  cudaGetSymbolAddress((void**)&dp, g_dp);
  cudaGetSymbolAddress((void**)&xh, g_xh);  cudaGetSymbolAddress((void**)&xl, g_xl);
  cudaGetSymbolAddress((void**)&ahh, g_ahh); cudaGetSymbolAddress((void**)&ahl, g_ahl);
  cudaGetSymbolAddress((void**)&bhh, g_bhh); cudaGetSymbolAddress((void**)&bhl, g_bhl);
  cudaGetSymbolAddress((void**)&qh, g_qh);  cudaGetSymbolAddress((void**)&ql, g_ql);
  cudaGetSymbolAddress((void**)&kh, g_kh);  cudaGetSymbolAddress((void**)&kl, g_kl);
  cudaGetSymbolAddress((void**)&vh, g_vh);  cudaGetSymbolAddress((void**)&vl, g_vl);
  cudaGetSymbolAddress((void**)&wh, g_wh);  cudaGetSymbolAddress((void**)&wl, g_wl);
  cudaGetSymbolAddress((void**)&bth, g_bth); cudaGetSymbolAddress((void**)&btl, g_btl);

  cudaFuncSetAttribute(gemm_mma<EPI_LN>,   cudaFuncAttributeMaxDynamicSharedMemorySize, SMEM_SZ);
  cudaFuncSetAttribute(gemm_mma<EPI_Q>,    cudaFuncAttributeMaxDynamicSharedMemorySize, SMEM_SZ);
  cudaFuncSetAttribute(gemm_mma<EPI_K>,    cudaFuncAttributeMaxDynamicSharedMemorySize, SMEM_SZ);
  cudaFuncSetAttribute(gemm_mma<EPI_V>,    cudaFuncAttributeMaxDynamicSharedMemorySize, SMEM_SZ);
  cudaFuncSetAttribute(gemm_mma<EPI_ATTN>, cudaFuncAttributeMaxDynamicSharedMemorySize, SMEM_SZ);
  cudaFuncSetAttribute(gemm_kvs, cudaFuncAttributeMaxDynamicSharedMemorySize, KSMEM);

  const int WSZ = CH * CH;
  // launches 0-4: exactly 5 before the first gemm so ncu (-s 5) profiles gemm_mma<EPI_LN>
  split_kernel<<<WSZ / 256, 256>>>(fc_w, wh, wl, WSZ);
  split_kernel<<<WSZ / 256, 256>>>(Wq_w, wh + 1 * WSZ, wl + 1 * WSZ, WSZ);
  split_kernel<<<WSZ / 256, 256>>>(Wk_w, wh + 2 * WSZ, wl + 2 * WSZ, WSZ);
  split_kernel<<<WSZ / 256, 256>>>(Wv_w, wh + 3 * WSZ, wl + 3 * WSZ, WSZ);
  split_kernel<<<(NROWS * CH + 255) / 256, 256>>>(x, xh, xl, NROWS * CH);

  gemm_mma<EPI_LN><<<TGRID, NTHR, SMEM_SZ>>>(
      xh, xl, wh, wl, fc_b, hA, ahh, ahl, ln_g, ln_b,
      nullptr, nullptr, nullptr, nullptr, nullptr, nullptr);

  for (int L = 0; L < 2; L++) {
    if (L == 1) {
      split_kernel<<<WSZ / 256, 256>>>(Wq_w + (size_t)WSZ, wh + 4 * WSZ, wl + 4 * WSZ, WSZ);
      split_kernel<<<WSZ / 256, 256>>>(Wk_w + (size_t)WSZ, wh + 5 * WSZ, wl + 5 * WSZ, WSZ);
      split_kernel<<<WSZ / 256, 256>>>(Wv_w + (size_t)WSZ, wh + 6 * WSZ, wl + 6 * WSZ, WSZ);
    }
    const __nv_bfloat16* hh = L ? bhh : ahh;
    const __nv_bfloat16* hl = L ? bhl : ahl;
    const float* hP = L ? hB : hA;
    float* ob = L ? out : hB;
    const size_t bo = (size_t)L * CH;
    const int wo = (L ? 4 : 1);

    zero_kernel<<<1, CH + 4>>>(scal, CH + 4);
    gemm_mma<EPI_Q><<<TGRID, NTHR, SMEM_SZ>>>(
        hh, hl, wh + (size_t)wo * WSZ, wl + (size_t)wo * WSZ, Wq_b + bo,
        nullptr, qh, ql, nullptr, nullptr, scal + 0, nullptr, nullptr, nullptr, nullptr, nullptr);
    gemm_mma<EPI_K><<<TGRID, NTHR, SMEM_SZ>>>(
        hh, hl, wh + (size_t)(wo + 1) * WSZ, wl + (size_t)(wo + 1) * WSZ, Wk_b + bo,
        nullptr, kh, kl, nullptr, nullptr, scal + 1, scal + 4, nullptr, nullptr, nullptr, nullptr);
    gemm_mma<EPI_V><<<TGRID, NTHR, SMEM_SZ>>>(
        hh, hl, wh + (size_t)(wo + 2) * WSZ, wl + (size_t)(wo + 2) * WSZ, Wv_b + bo,
        v, vh, vl, nullptr, nullptr, nullptr, nullptr, nullptr, nullptr, nullptr, nullptr);
    dp_kernel<<<(NROWS + 31) / 32, NTHR>>>(qh, ql, scal, dp);
    gemm_kvs<<<dim3(2, NSLICE), NTHR, KSMEM>>>(kh, kl, vh, vl, part);
    kvs_reduce<<<64, 1024>>>(part, bth, btl);
    gemm_mma<EPI_ATTN><<<TGRID, NTHR, SMEM_SZ>>>(
        qh, ql, bth, btl, nullptr, ob, bhh, bhl,
        ln_g + (size_t)(L + 1) * CH, ln_b + (size_t)(L + 1) * CH,
        nullptr, nullptr, scal, dp, v, hP);
  }
}

// round 11
// speedup vs baseline: 2.5669x; 1.0291x over previous
#include <cuda_runtime.h>
#include <cuda_bf16.h>
#include <cstdint>

#define NROWS 100000
#define CH 256
#define NTHR 256
// ---- MMA gemm params ----
#define TM 128
#define TGRID ((NROWS + TM - 1) / TM)   // 782
#define AB (128 * 80)
#define WB (256 * 80)
#define BUFB (2 * AB + 2 * WB)
#define SCR (2 * BUFB)
#define SMEM_SZ (SCR + 4096)
// ---- kvs MMA params ----
#define NSLICE 73
#define SLICE_CHUNKS 43
#define KA_STR 272
#define KB_STR 528
#define KAB (32 * KA_STR)
#define KBB (32 * KB_STR)
#define KBUF (2 * KAB + 2 * KBB)
#define KSMEM (3 * KBUF)

// ---------------- scratch -----------------------------------------------------
__device__ float g_part[(size_t)NSLICE * CH * CH];
__device__ float g_scal[CH + 4];
__device__ float g_dp[NROWS];
__device__ __nv_bfloat16 g_xh[(size_t)NROWS * CH], g_xl[(size_t)NROWS * CH];
__device__ __nv_bfloat16 g_ahh[(size_t)NROWS * CH], g_ahl[(size_t)NROWS * CH];
__device__ __nv_bfloat16 g_bhh[(size_t)NROWS * CH], g_bhl[(size_t)NROWS * CH];
__device__ __nv_bfloat16 g_qh[(size_t)NROWS * CH], g_ql[(size_t)NROWS * CH];
__device__ __nv_bfloat16 g_kh[(size_t)NROWS * CH], g_kl[(size_t)NROWS * CH];
__device__ __nv_bfloat16 g_vh[(size_t)NROWS * CH], g_vl[(size_t)NROWS * CH];
__device__ __nv_bfloat16 g_wh[7 * 65536], g_wl[7 * 65536];
__device__ __nv_bfloat16 g_bth[65536], g_btl[65536];

// ---------------- helpers ------------------------------------------------------
__device__ __forceinline__ uint32_t smem_u32(const void* p) {
  uint32_t a;
  asm("{ .reg .u64 t; cvta.to.shared.u64 t, %1; cvt.u32.u64 %0, t; }" : "=r"(a) : "l"(p));
  return a;
}
#define CP16(dst, src) \
  asm volatile("cp.async.cg.shared.global [%0], [%1], 16;" :: "r"(dst), "l"(src))
#define CP16Z(dst, src, vb) \
  asm volatile("cp.async.cg.shared.global [%0], [%1], 16, %2;" :: "r"(dst), "l"(src), "r"(vb))
#define CP_COMMIT() asm volatile("cp.async.commit_group;" ::: "memory")
#define CP_WAIT(n) asm volatile("cp.async.wait_group %0;" :: "n"(n) : "memory")

__device__ __forceinline__ void ldm_x4(uint32_t* r, uint32_t addr) {
  asm volatile("ldmatrix.sync.aligned.m8n8.x4.shared.b16 {%0,%1,%2,%3}, [%4];"
               : "=r"(r[0]), "=r"(r[1]), "=r"(r[2]), "=r"(r[3]) : "r"(addr));
}
__device__ __forceinline__ void ldm_x4t(uint32_t* r, uint32_t addr) {
  asm volatile("ldmatrix.sync.aligned.m8n8.x4.trans.shared.b16 {%0,%1,%2,%3}, [%4];"
               : "=r"(r[0]), "=r"(r[1]), "=r"(r[2]), "=r"(r[3]) : "r"(addr));
}
__device__ __forceinline__ void mma_bf16(float* c, const uint32_t* a, const uint32_t* b) {
  asm volatile(
      "mma.sync.aligned.m16n8k16.row.col.f32.bf16.bf16.f32 "
      "{%0,%1,%2,%3}, {%4,%5,%6,%7}, {%8,%9}, {%0,%1,%2,%3};"
      : "+f"(c[0]), "+f"(c[1]), "+f"(c[2]), "+f"(c[3])
      : "r"(a[0]), "r"(a[1]), "r"(a[2]), "r"(a[3]), "r"(b[0]), "r"(b[1]));
}
__device__ __forceinline__ float wredf(float v) {
#pragma unroll
  for (int o = 16; o > 0; o >>= 1) v += __shfl_xor_sync(0xffffffffu, v, o);
  return v;
}
__device__ __forceinline__ unsigned short bfb(__nv_bfloat16 h) {
  return *reinterpret_cast<unsigned short*>(&h);
}
__device__ __forceinline__ void packhl(float v0, float v1, uint32_t& hi, uint32_t& lo) {
  __nv_bfloat16 h0 = __float2bfloat16(v0), h1 = __float2bfloat16(v1);
  __nv_bfloat16 l0 = __float2bfloat16(v0 - __bfloat162float(h0));
  __nv_bfloat16 l1 = __float2bfloat16(v1 - __bfloat162float(h1));
  hi = (uint32_t)bfb(h0) | ((uint32_t)bfb(h1) << 16);
  lo = (uint32_t)bfb(l0) | ((uint32_t)bfb(l1) << 16);
}
__device__ __forceinline__ float2 bf2f2(uint32_t u) {
  __nv_bfloat162 b = *reinterpret_cast<__nv_bfloat162*>(&u);
  return __bfloat1622float2(b);
}

// ---------------------------------------------------------------------------
__global__ void split_kernel(const float* __restrict__ src,
                             __nv_bfloat16* __restrict__ hi,
                             __nv_bfloat16* __restrict__ lo, int n) {
  int i = blockIdx.x * blockDim.x + threadIdx.x;
  if (i < n) {
    float x = src[i];
    __nv_bfloat16 h = __float2bfloat16(x);
    hi[i] = h;
    lo[i] = __float2bfloat16(x - __bfloat162float(h));
  }
}
__global__ void zero_kernel(float* p, int n) {
  int i = blockIdx.x * blockDim.x + threadIdx.x;
  if (i < n) p[i] = 0.f;
}

// dp[r] = q[r,:] . ks_sum
__global__ void __launch_bounds__(NTHR) dp_kernel(const __nv_bfloat16* __restrict__ Qh,
                                                  const __nv_bfloat16* __restrict__ Ql,
                                                  const float* __restrict__ scal,
                                                  float* __restrict__ dp) {
  int tid = threadIdx.x, w = tid >> 5, l = tid & 31;
  int rsub = l >> 3, cseg = l & 7;
  int r = blockIdx.x * 32 + w * 4 + rsub;
  float s = 0.f;
  if (r < NROWS) {
    const uint4* qh4 = (const uint4*)(Qh + (size_t)r * CH + cseg * 32);
    const uint4* ql4 = (const uint4*)(Ql + (size_t)r * CH + cseg * 32);
    const float4* k4 = (const float4*)(scal + 4 + cseg * 32);
#pragma unroll
    for (int i = 0; i < 4; i++) {
      uint4 H = qh4[i], L = ql4[i];
      float4 ka = k4[2 * i], kb = k4[2 * i + 1];
      float2 h0 = bf2f2(H.x), l0 = bf2f2(L.x);
      float2 h1 = bf2f2(H.y), l1 = bf2f2(L.y);
      float2 h2 = bf2f2(H.z), l2 = bf2f2(L.z);
      float2 h3 = bf2f2(H.w), l3 = bf2f2(L.w);
      s += (h0.x + l0.x) * ka.x + (h0.y + l0.y) * ka.y;
      s += (h1.x + l1.x) * ka.z + (h1.y + l1.y) * ka.w;
      s += (h2.x + l2.x) * kb.x + (h2.y + l2.y) * kb.y;
      s += (h3.x + l3.x) * kb.z + (h3.y + l3.y) * kb.w;
    }
  }
#pragma unroll
  for (int o = 4; o > 0; o >>= 1) s += __shfl_xor_sync(0xffffffffu, s, o);
  if (cseg == 0 && r < NROWS) dp[r] = s;
}

// ---------------------------------------------------------------------------
// MMA GEMM: C[128,256] = A[128,256] @ W[256,256]^T, bf16-split, fp32 acc.
// All activation I/O is bf16 hi/lo pairs; fp32 written only when Cf != null.
// ---------------------------------------------------------------------------
#define EPI_LN   0
#define EPI_Q    1
#define EPI_K    2
#define EPI_V    3
#define EPI_ATTN 4

#define ACCV(jr, nt, c) acc[(jr) >> 1][nt][(((jr) & 1) << 1) + (c)]

template<int EPI>
__global__ void __launch_bounds__(NTHR, 1) gemm_mma(
    const __nv_bfloat16* __restrict__ Ah, const __nv_bfloat16* __restrict__ Al,
    const __nv_bfloat16* __restrict__ Wh, const __nv_bfloat16* __restrict__ Wl,
    const float* __restrict__ bias,
    float* __restrict__ Cf, __nv_bfloat16* __restrict__ Chi, __nv_bfloat16* __restrict__ Clo,
    const float* __restrict__ gamma, const float* __restrict__ beta,
    float* __restrict__ normAcc, float* __restrict__ colAcc,
    const float* __restrict__ scal, const float* __restrict__ dpv,
    const __nv_bfloat16* __restrict__ Vh, const __nv_bfloat16* __restrict__ Vl,
    const __nv_bfloat16* __restrict__ Ph, const __nv_bfloat16* __restrict__ Pl)
{
  extern __shared__ char smem[];
  const uint32_t sb = smem_u32(smem);
  const int tid = threadIdx.x, w = tid >> 5, l = tid & 31;
  const int wrow = w >> 1, wcol = w & 1;
  const int m0 = blockIdx.x * TM;

  float* sS1  = (float*)(smem + SCR);
  float* sS2  = (float*)(smem + SCR + 1024);
  float* sCol = (float*)(smem + SCR + 2048);
  float* sRed = (float*)(smem + SCR + 3072);
  if (EPI == EPI_K) sCol[tid] = 0.f;

  float acc[2][16][4];
#pragma unroll
  for (int a = 0; a < 2; a++)
#pragma unroll
    for (int b = 0; b < 16; b++)
#pragma unroll
      for (int c = 0; c < 4; c++) acc[a][b][c] = 0.f;

  auto issue = [&](int ch, int buf) {
    const uint32_t base = sb + buf * BUFB;
    const int k0 = ch * 32;
#pragma unroll
    for (int t = 0; t < 2; t++) {
      int idx = tid + t * 256;
      int row = idx >> 2, seg = idx & 3;
      int gr = m0 + row; if (gr > NROWS - 1) gr = NROWS - 1;
      size_t g = (size_t)gr * CH + k0 + seg * 8;
      uint32_t so = row * 80 + seg * 16;
      CP16(base + so, Ah + g);
      CP16(base + AB + so, Al + g);
    }
#pragma unroll
    for (int t = 0; t < 4; t++) {
      int idx = tid + t * 256;
      int row = idx >> 2, seg = idx & 3;
      size_t g = (size_t)row * CH + k0 + seg * 8;
      uint32_t so = row * 80 + seg * 16;
      CP16(base + 2 * AB + so, Wh + g);
      CP16(base + 2 * AB + WB + so, Wl + g);
    }
  };

  issue(0, 0); CP_COMMIT();
#pragma unroll
  for (int ch = 0; ch < 8; ch++) {
    if (ch < 7) { issue(ch + 1, (ch + 1) & 1); CP_COMMIT(); CP_WAIT(1); }
    else CP_WAIT(0);
    __syncthreads();
    const uint32_t base = sb + (ch & 1) * BUFB;
#pragma unroll
    for (int kt = 0; kt < 2; kt++) {
      uint32_t ah[2][4], al_[2][4];
#pragma unroll
      for (int mt = 0; mt < 2; mt++) {
        int row = wrow * 32 + mt * 16 + (l & 15);
        int col = kt * 16 + ((l >> 4) << 3);
        uint32_t off = row * 80 + col * 2;
        ldm_x4(ah[mt], base + off);
        ldm_x4(al_[mt], base + AB + off);
      }
#pragma unroll
      for (int ntp = 0; ntp < 8; ntp++) {
        int n = wcol * 128 + ntp * 16 + ((l >> 4) << 3) + (l & 7);
        int col = kt * 16 + ((l >> 3) & 1) * 8;
        uint32_t off = n * 80 + col * 2;
        uint32_t bh4[4], bl4[4];
        ldm_x4(bh4, base + 2 * AB + off);
        ldm_x4(bl4, base + 2 * AB + WB + off);
#pragma unroll
        for (int mt = 0; mt < 2; mt++) {
          mma_bf16(acc[mt][2 * ntp],     ah[mt],  bh4);
          mma_bf16(acc[mt][2 * ntp],     ah[mt],  bl4);
          mma_bf16(acc[mt][2 * ntp],     al_[mt], bh4);
          mma_bf16(acc[mt][2 * ntp + 1], ah[mt],  bh4 + 2);
          mma_bf16(acc[mt][2 * ntp + 1], ah[mt],  bl4 + 2);
          mma_bf16(acc[mt][2 * ntp + 1], al_[mt], bh4 + 2);
        }
      }
    }
    __syncthreads();
  }

  // ---------------- epilogue -------------------------------------------------
  const int qlane = l >> 2;
  const int cbase = wcol * 128 + (l & 3) * 2;

  if (EPI == EPI_Q || EPI == EPI_K || EPI == EPI_V) {
    float nrm = 0.f;
#pragma unroll
    for (int nt = 0; nt < 16; nt++) {
      const int col = cbase + nt * 8;
      float2 bs = *(const float2*)(bias + col);
      float cs0 = 0.f, cs1 = 0.f;
#pragma unroll
      for (int jr = 0; jr < 4; jr++) {
        int r = m0 + wrow * 32 + (jr >> 1) * 16 + (jr & 1) * 8 + qlane;
        bool valid = r < NROWS;
        float v0 = ACCV(jr, nt, 0) + bs.x;
        float v1 = ACCV(jr, nt, 1) + bs.y;
        if (valid) {
          if (EPI == EPI_Q || EPI == EPI_K) nrm = fmaf(v0, v0, fmaf(v1, v1, nrm));
          if (EPI == EPI_K) { cs0 += v0; cs1 += v1; }
          uint32_t hi, lo;
          packhl(v0, v1, hi, lo);
          *(uint32_t*)(Chi + (size_t)r * CH + col) = hi;
          *(uint32_t*)(Clo + (size_t)r * CH + col) = lo;
        }
      }
      if (EPI == EPI_K) {
#pragma unroll
        for (int o = 4; o < 32; o <<= 1) {
          cs0 += __shfl_xor_sync(0xffffffffu, cs0, o);
          cs1 += __shfl_xor_sync(0xffffffffu, cs1, o);
        }
        if (qlane == 0) { atomicAdd(&sCol[col], cs0); atomicAdd(&sCol[col + 1], cs1); }
      }
    }
    if (EPI == EPI_Q || EPI == EPI_K) {
      float p = wredf(nrm);
      if (l == 0) sRed[w] = p;
      __syncthreads();
      if (tid == 0) {
        float s = 0.f;
#pragma unroll
        for (int i = 0; i < 8; i++) s += sRed[i];
        atomicAdd(normAcc, s);
      }
      if (EPI == EPI_K) atomicAdd(&colAcc[tid], sCol[tid]);
    }
  } else {
    const float nF = (float)NROWS;
    float cN = 0.f;
    if (EPI == EPI_ATTN) cN = rsqrtf(scal[0] * scal[1]);
#pragma unroll
    for (int jr = 0; jr < 4; jr++) {
      const int lrow = wrow * 32 + (jr >> 1) * 16 + (jr & 1) * 8 + qlane;
      const int r = m0 + lrow;
      const bool valid = r < NROWS;
      float invr = 0.f;
      if (EPI == EPI_ATTN) invr = 1.f / fmaf(cN, valid ? dpv[r] : 0.f, nF);
      float s1 = 0.f, s2 = 0.f;
#pragma unroll
      for (int nt = 0; nt < 16; nt++) {
        const int col = cbase + nt * 8;
        if (EPI == EPI_LN) {
          float2 bs = *(const float2*)(bias + col);
          float y0 = ACCV(jr, nt, 0) + bs.x;
          float y1 = ACCV(jr, nt, 1) + bs.y;
          ACCV(jr, nt, 0) = y0; ACCV(jr, nt, 1) = y1;
          s1 += y0 + y1; s2 = fmaf(y0, y0, fmaf(y1, y1, s2));
        } else {
          uint32_t uvh = 0, uvl = 0, uph = 0, upl = 0;
          if (valid) {
            uvh = *(const uint32_t*)(Vh + (size_t)r * CH + col);
            uvl = *(const uint32_t*)(Vl + (size_t)r * CH + col);
            uph = *(const uint32_t*)(Ph + (size_t)r * CH + col);
            upl = *(const uint32_t*)(Pl + (size_t)r * CH + col);
          }
          float2 a0 = bf2f2(uvh), a1 = bf2f2(uvl);
          float2 b0 = bf2f2(uph), b1 = bf2f2(upl);
          float vvx = a0.x + a1.x, vvy = a0.y + a1.y;
          float ppx = b0.x + b1.x, ppy = b0.y + b1.y;
          float h0 = 0.5f * (fmaf(cN, ACCV(jr, nt, 0), nF * vvx) * invr + ppx);
          float h1 = 0.5f * (fmaf(cN, ACCV(jr, nt, 1), nF * vvy) * invr + ppy);
          ACCV(jr, nt, 0) = h0; ACCV(jr, nt, 1) = h1;
          s1 += h0 + h1; s2 = fmaf(h0, h0, fmaf(h1, h1, s2));
        }
      }
#pragma unroll
      for (int o = 1; o < 4; o <<= 1) {
        s1 += __shfl_xor_sync(0xffffffffu, s1, o);
        s2 += __shfl_xor_sync(0xffffffffu, s2, o);
      }
      if ((l & 3) == 0) { sS1[wcol * 128 + lrow] = s1; sS2[wcol * 128 + lrow] = s2; }
    }
    __syncthreads();
#pragma unroll
    for (int jr = 0; jr < 4; jr++) {
      const int lrow = wrow * 32 + (jr >> 1) * 16 + (jr & 1) * 8 + qlane;
      const int r = m0 + lrow;
      const bool valid = r < NROWS;
      const float s1 = sS1[lrow] + sS1[128 + lrow];
      const float s2 = sS2[lrow] + sS2[128 + lrow];
      const float mu = s1 * (1.f / CH);
      const float rs = rsqrtf(s2 * (1.f / CH) - mu * mu + 1e-5f);
#pragma unroll
      for (int nt = 0; nt < 16; nt++) {
        const int col = cbase + nt * 8;
        float2 gg = *(const float2*)(gamma + col);
        float2 bb = *(const float2*)(beta + col);
        float o0 = fmaxf((ACCV(jr, nt, 0) - mu) * rs * gg.x + bb.x, 0.f);
        float o1 = fmaxf((ACCV(jr, nt, 1) - mu) * rs * gg.y + bb.y, 0.f);
        if (valid) {
          if (Cf) *(float2*)(Cf + (size_t)r * CH + col) = make_float2(o0, o1);
          if (Chi) {
            uint32_t hi, lo;
            packhl(o0, o1, hi, lo);
            *(uint32_t*)(Chi + (size_t)r * CH + col) = hi;
            *(uint32_t*)(Clo + (size_t)r * CH + col) = lo;
          }
        }
      }
    }
  }
}

// ---------------------------------------------------------------------------
// MMA kvs: part[s][m][d] = sum over slice-s rows n of K[n,m]*V[n,d]
// ---------------------------------------------------------------------------
__global__ void __launch_bounds__(NTHR, 1) gemm_kvs(
    const __nv_bfloat16* __restrict__ Kh, const __nv_bfloat16* __restrict__ Kl,
    const __nv_bfloat16* __restrict__ Vh, const __nv_bfloat16* __restrict__ Vl,
    float* __restrict__ part)
{
  extern __shared__ char smem[];
  const uint32_t sb = smem_u32(smem);
  const int tid = threadIdx.x, w = tid >> 5, l = tid & 31;
  const int wrow = w >> 1, wcol = w & 1;
  const int m0 = blockIdx.x * 128;
  const int n0 = blockIdx.y * (SLICE_CHUNKS * 32);

  float acc[2][16][4];
#pragma unroll
  for (int a = 0; a < 2; a++)
#pragma unroll
    for (int b = 0; b < 16; b++)
#pragma unroll
      for (int c = 0; c < 4; c++) acc[a][b][c] = 0.f;

  auto issue = [&](int ch, int buf) {
    const uint32_t base = sb + buf * KBUF;
    const int nb = n0 + ch * 32;
#pragma unroll
    for (int t = 0; t < 2; t++) {
      int idx = tid + t * 256;
      int row = idx >> 4, seg = idx & 15;
      int gn = nb + row;
      uint32_t vb = (gn < NROWS) ? 16u : 0u;
      if (gn > NROWS - 1) gn = NROWS - 1;
      size_t g = (size_t)gn * CH + m0 + seg * 8;
      uint32_t so = row * KA_STR + seg * 16;
      CP16Z(base + so, Kh + g, vb);
      CP16Z(base + KAB + so, Kl + g, vb);
    }
#pragma unroll
    for (int t = 0; t < 4; t++) {
      int idx = tid + t * 256;
      int row = idx >> 5, seg = idx & 31;
      int gn = nb + row;
      uint32_t vb = (gn < NROWS) ? 16u : 0u;
      if (gn > NROWS - 1) gn = NROWS - 1;
      size_t g = (size_t)gn * CH + seg * 8;
      uint32_t so = row * KB_STR + seg * 16;
      CP16Z(base + 2 * KAB + so, Vh + g, vb);
      CP16Z(base + 2 * KAB + KBB + so, Vl + g, vb);
    }
  };

  issue(0, 0); CP_COMMIT();
  issue(1, 1); CP_COMMIT();
  for (int ch = 0; ch < SLICE_CHUNKS; ch++) {
    if (ch + 1 < SLICE_CHUNKS) CP_WAIT(1); else CP_WAIT(0);
    __syncthreads();
    if (ch + 2 < SLICE_CHUNKS) { issue(ch + 2, (ch + 2) % 3); CP_COMMIT(); }
    const uint32_t base = sb + (ch % 3) * KBUF;
#pragma unroll
    for (int kt = 0; kt < 2; kt++) {
      const int k0 = kt * 16;
      uint32_t ah[2][4], al_[2][4];
#pragma unroll
      for (int mt = 0; mt < 2; mt++) {
        int krow = k0 + (l & 7) + ((l >> 4) << 3);
        int mcol = wrow * 32 + mt * 16 + ((l >> 3) & 1) * 8;
        uint32_t off = krow * KA_STR + mcol * 2;
        ldm_x4t(ah[mt], base + off);
        ldm_x4t(al_[mt], base + KAB + off);
      }
#pragma unroll
      for (int ntp = 0; ntp < 8; ntp++) {
        int d0 = wcol * 128 + ntp * 16 + ((l >> 4) << 3);
        int krow = k0 + (l & 7) + ((l >> 3) & 1) * 8;
        uint32_t off = krow * KB_STR + d0 * 2;
        uint32_t bh4[4], bl4[4];
        ldm_x4t(bh4, base + 2 * KAB + off);
        ldm_x4t(bl4, base + 2 * KAB + KBB + off);
#pragma unroll
        for (int mt = 0; mt < 2; mt++) {
          mma_bf16(acc[mt][2 * ntp],     ah[mt],  bh4);
          mma_bf16(acc[mt][2 * ntp],     ah[mt],  bl4);
          mma_bf16(acc[mt][2 * ntp],     al_[mt], bh4);
          mma_bf16(acc[mt][2 * ntp + 1], ah[mt],  bh4 + 2);
          mma_bf16(acc[mt][2 * ntp + 1], ah[mt],  bl4 + 2);
          mma_bf16(acc[mt][2 * ntp + 1], al_[mt], bh4 + 2);
        }
      }
    }
    __syncthreads();
  }

  float* dst = part + (size_t)blockIdx.y * (CH * CH);
  const int qlane = l >> 2;
  const int cbase = wcol * 128 + (l & 3) * 2;
#pragma unroll
  for (int jr = 0; jr < 4; jr++) {
    int m = m0 + wrow * 32 + (jr >> 1) * 16 + (jr & 1) * 8 + qlane;
#pragma unroll
    for (int nt = 0; nt < 16; nt++) {
      int d = cbase + nt * 8;
      *(float2*)(dst + (size_t)m * CH + d) = make_float2(ACCV(jr, nt, 0), ACCV(jr, nt, 1));
    }
  }
}

// sum slices; write TRANSPOSED hi/lo bf16: bt[d*256+m] = kvs[m][d]
__global__ void kvs_reduce(const float* __restrict__ part,
                           __nv_bfloat16* __restrict__ bth,
                           __nv_bfloat16* __restrict__ btl) {
  int idx = blockIdx.x * blockDim.x + threadIdx.x;
  if (idx < CH * CH) {
    int m = idx >> 8, d = idx & 255;
    float s = 0.f;
#pragma unroll
    for (int ss = 0; ss < NSLICE; ss++) s += part[(size_t)ss * CH * CH + idx];
    __nv_bfloat16 h = __float2bfloat16(s);
    __nv_bfloat16 lo = __float2bfloat16(s - __bfloat162float(h));
    bth[d * CH + m] = h;
    btl[d * CH + m] = lo;
  }
}

// ---------------------------------------------------------------------------
extern "C" void kernel_launch(void* const* d_in, const int* in_sizes, int n_in,
                              void* d_out, int out_size) {
  (void)in_sizes; (void)n_in; (void)out_size;
  const float* x    = (const float*)d_in[0];
  const float* fc_w = (const float*)d_in[1];
  const float* fc_b = (const float*)d_in[2];
  const float* Wq_w = (const float*)d_in[3];
  const float* Wq_b = (const float*)d_in[4];
  const float* Wk_w = (const float*)d_in[5];
  const float* Wk_b = (const float*)d_in[6];
  const float* Wv_w = (const float*)d_in[7];
  const float* Wv_b = (const float*)d_in[8];
  const float* ln_g = (const float*)d_in[9];
  const float* ln_b = (const float*)d_in[10];
  float* out = (float*)d_out;

  float *part, *scal, *dp;
  __nv_bfloat16 *xh, *xl, *ahh, *ahl, *bhh, *bhl, *qh, *ql, *kh, *kl, *vh, *vl, *wh, *wl, *bth, *btl;
  cudaGetSymbolAddress((void**)&part, g_part);
  cudaGetSymbolAddress((void**)&scal, g_scal);
  cudaGetSymbolAddress((void**)&dp, g_dp);
  cudaGetSymbolAddress((void**)&xh, g_xh);  cudaGetSymbolAddress((void**)&xl, g_xl);
  cudaGetSymbolAddress((void**)&ahh, g_ahh); cudaGetSymbolAddress((void**)&ahl, g_ahl);
  cudaGetSymbolAddress((void**)&bhh, g_bhh); cudaGetSymbolAddress((void**)&bhl, g_bhl);
  cudaGetSymbolAddress((void**)&qh, g_qh);  cudaGetSymbolAddress((void**)&ql, g_ql);
  cudaGetSymbolAddress((void**)&kh, g_kh);  cudaGetSymbolAddress((void**)&kl, g_kl);
  cudaGetSymbolAddress((void**)&vh, g_vh);  cudaGetSymbolAddress((void**)&vl, g_vl);
  cudaGetSymbolAddress((void**)&wh, g_wh);  cudaGetSymbolAddress((void**)&wl, g_wl);
  cudaGetSymbolAddress((void**)&bth, g_bth); cudaGetSymbolAddress((void**)&btl, g_btl);

  cudaFuncSetAttribute(gemm_mma<EPI_LN>,   cudaFuncAttributeMaxDynamicSharedMemorySize, SMEM_SZ);
  cudaFuncSetAttribute(gemm_mma<EPI_Q>,    cudaFuncAttributeMaxDynamicSharedMemorySize, SMEM_SZ);
  cudaFuncSetAttribute(gemm_mma<EPI_K>,    cudaFuncAttributeMaxDynamicSharedMemorySize, SMEM_SZ);
  cudaFuncSetAttribute(gemm_mma<EPI_V>,    cudaFuncAttributeMaxDynamicSharedMemorySize, SMEM_SZ);
  cudaFuncSetAttribute(gemm_mma<EPI_ATTN>, cudaFuncAttributeMaxDynamicSharedMemorySize, SMEM_SZ);
  cudaFuncSetAttribute(gemm_kvs, cudaFuncAttributeMaxDynamicSharedMemorySize, KSMEM);

  const int WSZ = CH * CH;
  split_kernel<<<WSZ / 256, 256>>>(fc_w, wh, wl, WSZ);
  split_kernel<<<WSZ / 256, 256>>>(Wq_w, wh + 1 * WSZ, wl + 1 * WSZ, WSZ);
  split_kernel<<<WSZ / 256, 256>>>(Wk_w, wh + 2 * WSZ, wl + 2 * WSZ, WSZ);
  split_kernel<<<WSZ / 256, 256>>>(Wv_w, wh + 3 * WSZ, wl + 3 * WSZ, WSZ);
  split_kernel<<<(NROWS * CH + 255) / 256, 256>>>(x, xh, xl, NROWS * CH);

  // h0 = relu(LN(x @ fc_w^T + fc_b)) -> hi/lo only
  gemm_mma<EPI_LN><<<TGRID, NTHR, SMEM_SZ>>>(
      xh, xl, wh, wl, fc_b, nullptr, ahh, ahl, ln_g, ln_b,
      nullptr, nullptr, nullptr, nullptr, nullptr, nullptr, nullptr, nullptr);

  for (int L = 0; L < 2; L++) {
    if (L == 1) {
      split_kernel<<<WSZ / 256, 256>>>(Wq_w + (size_t)WSZ, wh + 4 * WSZ, wl + 4 * WSZ, WSZ);
      split_kernel<<<WSZ / 256, 256>>>(Wk_w + (size_t)WSZ, wh + 5 * WSZ, wl + 5 * WSZ, WSZ);
      split_kernel<<<WSZ / 256, 256>>>(Wv_w + (size_t)WSZ, wh + 6 * WSZ, wl + 6 * WSZ, WSZ);
    }
    const __nv_bfloat16* hh = L ? bhh : ahh;
    const __nv_bfloat16* hl = L ? bhl : ahl;
    float* ob = L ? out : nullptr;
    __nv_bfloat16* obh = L ? nullptr : bhh;
    __nv_bfloat16* obl = L ? nullptr : bhl;
    const size_t bo = (size_t)L * CH;
    const int wo = (L ? 4 : 1);

    zero_kernel<<<1, CH + 4>>>(scal, CH + 4);
    gemm_mma<EPI_Q><<<TGRID, NTHR, SMEM_SZ>>>(
        hh, hl, wh + (size_t)wo * WSZ, wl + (size_t)wo * WSZ, Wq_b + bo,
        nullptr, qh, ql, nullptr, nullptr, scal + 0, nullptr, nullptr, nullptr,
        nullptr, nullptr, nullptr, nullptr);
    gemm_mma<EPI_K><<<TGRID, NTHR, SMEM_SZ>>>(
        hh, hl, wh + (size_t)(wo + 1) * WSZ, wl + (size_t)(wo + 1) * WSZ, Wk_b + bo,
        nullptr, kh, kl, nullptr, nullptr, scal + 1, scal + 4, nullptr, nullptr,
        nullptr, nullptr, nullptr, nullptr);
    gemm_mma<EPI_V><<<TGRID, NTHR, SMEM_SZ>>>(
        hh, hl, wh + (size_t)(wo + 2) * WSZ, wl + (size_t)(wo + 2) * WSZ, Wv_b + bo,
        nullptr, vh, vl, nullptr, nullptr, nullptr, nullptr, nullptr, nullptr,
        nullptr, nullptr, nullptr, nullptr);
    dp_kernel<<<(NROWS + 31) / 32, NTHR>>>(qh, ql, scal, dp);
    gemm_kvs<<<dim3(2, NSLICE), NTHR, KSMEM>>>(kh, kl, vh, vl, part);
    kvs_reduce<<<64, 1024>>>(part, bth, btl);
    gemm_mma<EPI_ATTN><<<TGRID, NTHR, SMEM_SZ>>>(
        qh, ql, bth, btl, nullptr, ob, obh, obl,
        ln_g + (size_t)(L + 1) * CH, ln_b + (size_t)(L + 1) * CH,
        nullptr, nullptr, scal, dp, vh, vl, hh, hl);
  }
}

// round 12
// speedup vs baseline: 2.7662x; 1.0776x over previous
#include <cuda_runtime.h>
#include <cuda_bf16.h>
#include <cstdint>

#define NROWS 100000
#define CH 256
#define NTHR 256
// ---- MMA gemm params (BM=64 x BN=256, occ 2) ----
#define TM 64
#define TGRID ((NROWS + TM - 1) / TM)   // 1563
#define AB (64 * 80)                    // 5120 B per A matrix (hi or lo)
#define WB (256 * 80)                   // 20480 B per W matrix
#define BUFB (2 * AB + 2 * WB)          // 51200 B per stage
#define SCR (2 * BUFB)                  // 102400
#define SMEM_SZ (SCR + 4096)            // 106496 -> 2 CTA/SM
// ---- kvs MMA params (m128 x d128 quarters, occ 2) ----
#define NSLICE 74
#define SLICE_CHUNKS 43                 // 74*43*32 = 101824 >= 100000
#define KA_STR 272                      // 128 bf16 cols + pad
#define KAB (32 * KA_STR)               // 8704
#define KBUF (4 * KAB)                  // 34816 per stage (Khi,Klo,Vhi,Vlo)
#define KSMEM (3 * KBUF)                // 104448 -> 2 CTA/SM

// ---------------- scratch -----------------------------------------------------
__device__ float g_part[(size_t)NSLICE * CH * CH];
__device__ float g_scal[CH + 4];
__device__ float g_dp[NROWS];
__device__ __nv_bfloat16 g_xh[(size_t)NROWS * CH], g_xl[(size_t)NROWS * CH];
__device__ __nv_bfloat16 g_ahh[(size_t)NROWS * CH], g_ahl[(size_t)NROWS * CH];
__device__ __nv_bfloat16 g_bhh[(size_t)NROWS * CH], g_bhl[(size_t)NROWS * CH];
__device__ __nv_bfloat16 g_qh[(size_t)NROWS * CH], g_ql[(size_t)NROWS * CH];
__device__ __nv_bfloat16 g_kh[(size_t)NROWS * CH], g_kl[(size_t)NROWS * CH];
__device__ __nv_bfloat16 g_vh[(size_t)NROWS * CH], g_vl[(size_t)NROWS * CH];
__device__ __nv_bfloat16 g_wh[7 * 65536], g_wl[7 * 65536];
__device__ __nv_bfloat16 g_bth[65536], g_btl[65536];

// ---------------- helpers ------------------------------------------------------
__device__ __forceinline__ uint32_t smem_u32(const void* p) {
  uint32_t a;
  asm("{ .reg .u64 t; cvta.to.shared.u64 t, %1; cvt.u32.u64 %0, t; }" : "=r"(a) : "l"(p));
  return a;
}
#define CP16(dst, src) \
  asm volatile("cp.async.cg.shared.global [%0], [%1], 16;" :: "r"(dst), "l"(src))
#define CP16Z(dst, src, vb) \
  asm volatile("cp.async.cg.shared.global [%0], [%1], 16, %2;" :: "r"(dst), "l"(src), "r"(vb))
#define CP_COMMIT() asm volatile("cp.async.commit_group;" ::: "memory")
#define CP_WAIT(n) asm volatile("cp.async.wait_group %0;" :: "n"(n) : "memory")

__device__ __forceinline__ void ldm_x4(uint32_t* r, uint32_t addr) {
  asm volatile("ldmatrix.sync.aligned.m8n8.x4.shared.b16 {%0,%1,%2,%3}, [%4];"
               : "=r"(r[0]), "=r"(r[1]), "=r"(r[2]), "=r"(r[3]) : "r"(addr));
}
__device__ __forceinline__ void ldm_x4t(uint32_t* r, uint32_t addr) {
  asm volatile("ldmatrix.sync.aligned.m8n8.x4.trans.shared.b16 {%0,%1,%2,%3}, [%4];"
               : "=r"(r[0]), "=r"(r[1]), "=r"(r[2]), "=r"(r[3]) : "r"(addr));
}
__device__ __forceinline__ void mma_bf16(float* c, const uint32_t* a, const uint32_t* b) {
  asm volatile(
      "mma.sync.aligned.m16n8k16.row.col.f32.bf16.bf16.f32 "
      "{%0,%1,%2,%3}, {%4,%5,%6,%7}, {%8,%9}, {%0,%1,%2,%3};"
      : "+f"(c[0]), "+f"(c[1]), "+f"(c[2]), "+f"(c[3])
      : "r"(a[0]), "r"(a[1]), "r"(a[2]), "r"(a[3]), "r"(b[0]), "r"(b[1]));
}
__device__ __forceinline__ float wredf(float v) {
#pragma unroll
  for (int o = 16; o > 0; o >>= 1) v += __shfl_xor_sync(0xffffffffu, v, o);
  return v;
}
__device__ __forceinline__ unsigned short bfb(__nv_bfloat16 h) {
  return *reinterpret_cast<unsigned short*>(&h);
}
__device__ __forceinline__ void packhl(float v0, float v1, uint32_t& hi, uint32_t& lo) {
  __nv_bfloat16 h0 = __float2bfloat16(v0), h1 = __float2bfloat16(v1);
  __nv_bfloat16 l0 = __float2bfloat16(v0 - __bfloat162float(h0));
  __nv_bfloat16 l1 = __float2bfloat16(v1 - __bfloat162float(h1));
  hi = (uint32_t)bfb(h0) | ((uint32_t)bfb(h1) << 16);
  lo = (uint32_t)bfb(l0) | ((uint32_t)bfb(l1) << 16);
}
__device__ __forceinline__ float2 bf2f2(uint32_t u) {
  __nv_bfloat162 b = *reinterpret_cast<__nv_bfloat162*>(&u);
  return __bfloat1622float2(b);
}

// ---------------------------------------------------------------------------
__global__ void split_kernel(const float* __restrict__ src,
                             __nv_bfloat16* __restrict__ hi,
                             __nv_bfloat16* __restrict__ lo, int n) {
  int i = blockIdx.x * blockDim.x + threadIdx.x;
  if (i < n) {
    float x = src[i];
    __nv_bfloat16 h = __float2bfloat16(x);
    hi[i] = h;
    lo[i] = __float2bfloat16(x - __bfloat162float(h));
  }
}
__global__ void zero_kernel(float* p, int n) {
  int i = blockIdx.x * blockDim.x + threadIdx.x;
  if (i < n) p[i] = 0.f;
}

// dp[r] = q[r,:] . ks_sum
__global__ void __launch_bounds__(NTHR) dp_kernel(const __nv_bfloat16* __restrict__ Qh,
                                                  const __nv_bfloat16* __restrict__ Ql,
                                                  const float* __restrict__ scal,
                                                  float* __restrict__ dp) {
  int tid = threadIdx.x, w = tid >> 5, l = tid & 31;
  int rsub = l >> 3, cseg = l & 7;
  int r = blockIdx.x * 32 + w * 4 + rsub;
  float s = 0.f;
  if (r < NROWS) {
    const uint4* qh4 = (const uint4*)(Qh + (size_t)r * CH + cseg * 32);
    const uint4* ql4 = (const uint4*)(Ql + (size_t)r * CH + cseg * 32);
    const float4* k4 = (const float4*)(scal + 4 + cseg * 32);
#pragma unroll
    for (int i = 0; i < 4; i++) {
      uint4 H = qh4[i], L = ql4[i];
      float4 ka = k4[2 * i], kb = k4[2 * i + 1];
      float2 h0 = bf2f2(H.x), l0 = bf2f2(L.x);
      float2 h1 = bf2f2(H.y), l1 = bf2f2(L.y);
      float2 h2 = bf2f2(H.z), l2 = bf2f2(L.z);
      float2 h3 = bf2f2(H.w), l3 = bf2f2(L.w);
      s += (h0.x + l0.x) * ka.x + (h0.y + l0.y) * ka.y;
      s += (h1.x + l1.x) * ka.z + (h1.y + l1.y) * ka.w;
      s += (h2.x + l2.x) * kb.x + (h2.y + l2.y) * kb.y;
      s += (h3.x + l3.x) * kb.z + (h3.y + l3.y) * kb.w;
    }
  }
#pragma unroll
  for (int o = 4; o > 0; o >>= 1) s += __shfl_xor_sync(0xffffffffu, s, o);
  if (cseg == 0 && r < NROWS) dp[r] = s;
}

// ---------------------------------------------------------------------------
// MMA GEMM: C[64,256] = A[64,256] @ W[256,256]^T, bf16-split, fp32 acc.
// 8 warps = 2 wrow (32 rows) x 4 wcol (64 cols). occ 2.
// ---------------------------------------------------------------------------
#define EPI_LN   0
#define EPI_Q    1
#define EPI_K    2
#define EPI_V    3
#define EPI_ATTN 4

#define ACCV(jr, nt, c) acc[(jr) >> 1][nt][(((jr) & 1) << 1) + (c)]

template<int EPI>
__global__ void __launch_bounds__(NTHR, 2) gemm_mma(
    const __nv_bfloat16* __restrict__ Ah, const __nv_bfloat16* __restrict__ Al,
    const __nv_bfloat16* __restrict__ Wh, const __nv_bfloat16* __restrict__ Wl,
    const float* __restrict__ bias,
    float* __restrict__ Cf, __nv_bfloat16* __restrict__ Chi, __nv_bfloat16* __restrict__ Clo,
    const float* __restrict__ gamma, const float* __restrict__ beta,
    float* __restrict__ normAcc, float* __restrict__ colAcc,
    const float* __restrict__ scal, const float* __restrict__ dpv,
    const __nv_bfloat16* __restrict__ Vh, const __nv_bfloat16* __restrict__ Vl,
    const __nv_bfloat16* __restrict__ Ph, const __nv_bfloat16* __restrict__ Pl)
{
  extern __shared__ char smem[];
  const uint32_t sb = smem_u32(smem);
  const int tid = threadIdx.x, w = tid >> 5, l = tid & 31;
  const int wrow = w >> 2, wcol = w & 3;      // 2 x 4
  const int m0 = blockIdx.x * TM;

  float* sS1  = (float*)(smem + SCR);          // 4 x 64
  float* sS2  = (float*)(smem + SCR + 1024);
  float* sCol = (float*)(smem + SCR + 2048);
  float* sRed = (float*)(smem + SCR + 3072);
  if (EPI == EPI_K) sCol[tid] = 0.f;

  float acc[2][8][4];
#pragma unroll
  for (int a = 0; a < 2; a++)
#pragma unroll
    for (int b = 0; b < 8; b++)
#pragma unroll
      for (int c = 0; c < 4; c++) acc[a][b][c] = 0.f;

  auto issue = [&](int ch, int buf) {
    const uint32_t base = sb + buf * BUFB;
    const int k0 = ch * 32;
    {
      int row = tid >> 2, seg = tid & 3;       // 64 rows x 4 segs = 256
      int gr = m0 + row; if (gr > NROWS - 1) gr = NROWS - 1;
      size_t g = (size_t)gr * CH + k0 + seg * 8;
      uint32_t so = row * 80 + seg * 16;
      CP16(base + so, Ah + g);
      CP16(base + AB + so, Al + g);
    }
#pragma unroll
    for (int t = 0; t < 4; t++) {
      int idx = tid + t * 256;
      int row = idx >> 2, seg = idx & 3;
      size_t g = (size_t)row * CH + k0 + seg * 8;
      uint32_t so = row * 80 + seg * 16;
      CP16(base + 2 * AB + so, Wh + g);
      CP16(base + 2 * AB + WB + so, Wl + g);
    }
  };

  issue(0, 0); CP_COMMIT();
#pragma unroll
  for (int ch = 0; ch < 8; ch++) {
    if (ch < 7) { issue(ch + 1, (ch + 1) & 1); CP_COMMIT(); CP_WAIT(1); }
    else CP_WAIT(0);
    __syncthreads();
    const uint32_t base = sb + (ch & 1) * BUFB;
#pragma unroll
    for (int kt = 0; kt < 2; kt++) {
      uint32_t ah[2][4], al_[2][4];
#pragma unroll
      for (int mt = 0; mt < 2; mt++) {
        int row = wrow * 32 + mt * 16 + (l & 15);
        int col = kt * 16 + ((l >> 4) << 3);
        uint32_t off = row * 80 + col * 2;
        ldm_x4(ah[mt], base + off);
        ldm_x4(al_[mt], base + AB + off);
      }
#pragma unroll
      for (int ntp = 0; ntp < 4; ntp++) {
        int n = wcol * 64 + ntp * 16 + ((l >> 4) << 3) + (l & 7);
        int col = kt * 16 + ((l >> 3) & 1) * 8;
        uint32_t off = n * 80 + col * 2;
        uint32_t bh4[4], bl4[4];
        ldm_x4(bh4, base + 2 * AB + off);
        ldm_x4(bl4, base + 2 * AB + WB + off);
#pragma unroll
        for (int mt = 0; mt < 2; mt++) {
          mma_bf16(acc[mt][2 * ntp],     ah[mt],  bh4);
          mma_bf16(acc[mt][2 * ntp],     ah[mt],  bl4);
          mma_bf16(acc[mt][2 * ntp],     al_[mt], bh4);
          mma_bf16(acc[mt][2 * ntp + 1], ah[mt],  bh4 + 2);
          mma_bf16(acc[mt][2 * ntp + 1], ah[mt],  bl4 + 2);
          mma_bf16(acc[mt][2 * ntp + 1], al_[mt], bh4 + 2);
        }
      }
    }
    __syncthreads();
  }

  // ---------------- epilogue -------------------------------------------------
  const int qlane = l >> 2;
  const int cbase = wcol * 64 + (l & 3) * 2;

  if (EPI == EPI_Q || EPI == EPI_K || EPI == EPI_V) {
    float nrm = 0.f;
#pragma unroll
    for (int nt = 0; nt < 8; nt++) {
      const int col = cbase + nt * 8;
      float2 bs = *(const float2*)(bias + col);
      float cs0 = 0.f, cs1 = 0.f;
#pragma unroll
      for (int jr = 0; jr < 4; jr++) {
        int r = m0 + wrow * 32 + (jr >> 1) * 16 + (jr & 1) * 8 + qlane;
        bool valid = r < NROWS;
        float v0 = ACCV(jr, nt, 0) + bs.x;
        float v1 = ACCV(jr, nt, 1) + bs.y;
        if (valid) {
          if (EPI == EPI_Q || EPI == EPI_K) nrm = fmaf(v0, v0, fmaf(v1, v1, nrm));
          if (EPI == EPI_K) { cs0 += v0; cs1 += v1; }
          uint32_t hi, lo;
          packhl(v0, v1, hi, lo);
          *(uint32_t*)(Chi + (size_t)r * CH + col) = hi;
          *(uint32_t*)(Clo + (size_t)r * CH + col) = lo;
        }
      }
      if (EPI == EPI_K) {
#pragma unroll
        for (int o = 4; o < 32; o <<= 1) {
          cs0 += __shfl_xor_sync(0xffffffffu, cs0, o);
          cs1 += __shfl_xor_sync(0xffffffffu, cs1, o);
        }
        if (qlane == 0) { atomicAdd(&sCol[col], cs0); atomicAdd(&sCol[col + 1], cs1); }
      }
    }
    if (EPI == EPI_Q || EPI == EPI_K) {
      float p = wredf(nrm);
      if (l == 0) sRed[w] = p;
      __syncthreads();
      if (tid == 0) {
        float s = 0.f;
#pragma unroll
        for (int i = 0; i < 8; i++) s += sRed[i];
        atomicAdd(normAcc, s);
      }
      if (EPI == EPI_K) atomicAdd(&colAcc[tid], sCol[tid]);
    }
  } else {
    const float nF = (float)NROWS;
    float cN = 0.f;
    if (EPI == EPI_ATTN) cN = rsqrtf(scal[0] * scal[1]);
#pragma unroll
    for (int jr = 0; jr < 4; jr++) {
      const int lrow = wrow * 32 + (jr >> 1) * 16 + (jr & 1) * 8 + qlane;
      const int r = m0 + lrow;
      const bool valid = r < NROWS;
      float invr = 0.f;
      if (EPI == EPI_ATTN) invr = 1.f / fmaf(cN, valid ? dpv[r] : 0.f, nF);
      float s1 = 0.f, s2 = 0.f;
#pragma unroll
      for (int nt = 0; nt < 8; nt++) {
        const int col = cbase + nt * 8;
        if (EPI == EPI_LN) {
          float2 bs = *(const float2*)(bias + col);
          float y0 = ACCV(jr, nt, 0) + bs.x;
          float y1 = ACCV(jr, nt, 1) + bs.y;
          ACCV(jr, nt, 0) = y0; ACCV(jr, nt, 1) = y1;
          s1 += y0 + y1; s2 = fmaf(y0, y0, fmaf(y1, y1, s2));
        } else {
          uint32_t uvh = 0, uvl = 0, uph = 0, upl = 0;
          if (valid) {
            uvh = *(const uint32_t*)(Vh + (size_t)r * CH + col);
            uvl = *(const uint32_t*)(Vl + (size_t)r * CH + col);
            uph = *(const uint32_t*)(Ph + (size_t)r * CH + col);
            upl = *(const uint32_t*)(Pl + (size_t)r * CH + col);
          }
          float2 a0 = bf2f2(uvh), a1 = bf2f2(uvl);
          float2 b0 = bf2f2(uph), b1 = bf2f2(upl);
          float vvx = a0.x + a1.x, vvy = a0.y + a1.y;
          float ppx = b0.x + b1.x, ppy = b0.y + b1.y;
          float h0 = 0.5f * (fmaf(cN, ACCV(jr, nt, 0), nF * vvx) * invr + ppx);
          float h1 = 0.5f * (fmaf(cN, ACCV(jr, nt, 1), nF * vvy) * invr + ppy);
          ACCV(jr, nt, 0) = h0; ACCV(jr, nt, 1) = h1;
          s1 += h0 + h1; s2 = fmaf(h0, h0, fmaf(h1, h1, s2));
        }
      }
#pragma unroll
      for (int o = 1; o < 4; o <<= 1) {
        s1 += __shfl_xor_sync(0xffffffffu, s1, o);
        s2 += __shfl_xor_sync(0xffffffffu, s2, o);
      }
      if ((l & 3) == 0) { sS1[wcol * 64 + lrow] = s1; sS2[wcol * 64 + lrow] = s2; }
    }
    __syncthreads();
#pragma unroll
    for (int jr = 0; jr < 4; jr++) {
      const int lrow = wrow * 32 + (jr >> 1) * 16 + (jr & 1) * 8 + qlane;
      const int r = m0 + lrow;
      const bool valid = r < NROWS;
      const float s1 = sS1[lrow] + sS1[64 + lrow] + sS1[128 + lrow] + sS1[192 + lrow];
      const float s2 = sS2[lrow] + sS2[64 + lrow] + sS2[128 + lrow] + sS2[192 + lrow];
      const float mu = s1 * (1.f / CH);
      const float rs = rsqrtf(s2 * (1.f / CH) - mu * mu + 1e-5f);
#pragma unroll
      for (int nt = 0; nt < 8; nt++) {
        const int col = cbase + nt * 8;
        float2 gg = *(const float2*)(gamma + col);
        float2 bb = *(const float2*)(beta + col);
        float o0 = fmaxf((ACCV(jr, nt, 0) - mu) * rs * gg.x + bb.x, 0.f);
        float o1 = fmaxf((ACCV(jr, nt, 1) - mu) * rs * gg.y + bb.y, 0.f);
        if (valid) {
          if (Cf) *(float2*)(Cf + (size_t)r * CH + col) = make_float2(o0, o1);
          if (Chi) {
            uint32_t hi, lo;
            packhl(o0, o1, hi, lo);
            *(uint32_t*)(Chi + (size_t)r * CH + col) = hi;
            *(uint32_t*)(Clo + (size_t)r * CH + col) = lo;
          }
        }
      }
    }
  }
}

// ---------------------------------------------------------------------------
// MMA kvs: part[s][m][d] quarters (m 128 x d 128). occ 2. 3-stage pipeline.
// grid: (2 m-half, 2 d-half, NSLICE)
// ---------------------------------------------------------------------------
__global__ void __launch_bounds__(NTHR, 2) gemm_kvs(
    const __nv_bfloat16* __restrict__ Kh, const __nv_bfloat16* __restrict__ Kl,
    const __nv_bfloat16* __restrict__ Vh, const __nv_bfloat16* __restrict__ Vl,
    float* __restrict__ part)
{
  extern __shared__ char smem[];
  const uint32_t sb = smem_u32(smem);
  const int tid = threadIdx.x, w = tid >> 5, l = tid & 31;
  const int wrow = w >> 1, wcol = w & 1;      // 4 x 32 m-rows, 2 x 64 d-cols
  const int m0 = blockIdx.x * 128;
  const int d0g = blockIdx.y * 128;
  const int n0 = blockIdx.z * (SLICE_CHUNKS * 32);

  float acc[2][8][4];
#pragma unroll
  for (int a = 0; a < 2; a++)
#pragma unroll
    for (int b = 0; b < 8; b++)
#pragma unroll
      for (int c = 0; c < 4; c++) acc[a][b][c] = 0.f;

  auto issue = [&](int ch, int buf) {
    const uint32_t base = sb + buf * KBUF;
    const int nb = n0 + ch * 32;
#pragma unroll
    for (int t = 0; t < 2; t++) {
      int idx = tid + t * 256;
      int row = idx >> 4, seg = idx & 15;     // 32 rows x 16 segs
      int gn = nb + row;
      uint32_t vb = (gn < NROWS) ? 16u : 0u;
      if (gn > NROWS - 1) gn = NROWS - 1;
      uint32_t so = row * KA_STR + seg * 16;
      size_t gk = (size_t)gn * CH + m0 + seg * 8;
      size_t gv = (size_t)gn * CH + d0g + seg * 8;
      CP16Z(base + so, Kh + gk, vb);
      CP16Z(base + KAB + so, Kl + gk, vb);
      CP16Z(base + 2 * KAB + so, Vh + gv, vb);
      CP16Z(base + 3 * KAB + so, Vl + gv, vb);
    }
  };

  issue(0, 0); CP_COMMIT();
  issue(1, 1); CP_COMMIT();
  for (int ch = 0; ch < SLICE_CHUNKS; ch++) {
    if (ch + 1 < SLICE_CHUNKS) CP_WAIT(1); else CP_WAIT(0);
    __syncthreads();
    if (ch + 2 < SLICE_CHUNKS) { issue(ch + 2, (ch + 2) % 3); CP_COMMIT(); }
    const uint32_t base = sb + (ch % 3) * KBUF;
#pragma unroll
    for (int kt = 0; kt < 2; kt++) {
      const int k0 = kt * 16;
      uint32_t ah[2][4], al_[2][4];
#pragma unroll
      for (int mt = 0; mt < 2; mt++) {
        int krow = k0 + (l & 7) + ((l >> 4) << 3);
        int mcol = wrow * 32 + mt * 16 + ((l >> 3) & 1) * 8;
        uint32_t off = krow * KA_STR + mcol * 2;
        ldm_x4t(ah[mt], base + off);
        ldm_x4t(al_[mt], base + KAB + off);
      }
#pragma unroll
      for (int ntp = 0; ntp < 4; ntp++) {
        int dd = wcol * 64 + ntp * 16 + ((l >> 4) << 3);
        int krow = k0 + (l & 7) + ((l >> 3) & 1) * 8;
        uint32_t off = krow * KA_STR + dd * 2;
        uint32_t bh4[4], bl4[4];
        ldm_x4t(bh4, base + 2 * KAB + off);
        ldm_x4t(bl4, base + 3 * KAB + off);
#pragma unroll
        for (int mt = 0; mt < 2; mt++) {
          mma_bf16(acc[mt][2 * ntp],     ah[mt],  bh4);
          mma_bf16(acc[mt][2 * ntp],     ah[mt],  bl4);
          mma_bf16(acc[mt][2 * ntp],     al_[mt], bh4);
          mma_bf16(acc[mt][2 * ntp + 1], ah[mt],  bh4 + 2);
          mma_bf16(acc[mt][2 * ntp + 1], ah[mt],  bl4 + 2);
          mma_bf16(acc[mt][2 * ntp + 1], al_[mt], bh4 + 2);
        }
      }
    }
    __syncthreads();
  }

  float* dst = part + (size_t)blockIdx.z * (CH * CH);
  const int qlane = l >> 2;
  const int cbase = wcol * 64 + (l & 3) * 2;
#pragma unroll
  for (int jr = 0; jr < 4; jr++) {
    int m = m0 + wrow * 32 + (jr >> 1) * 16 + (jr & 1) * 8 + qlane;
#pragma unroll
    for (int nt = 0; nt < 8; nt++) {
      int d = d0g + cbase + nt * 8;
      *(float2*)(dst + (size_t)m * CH + d) = make_float2(ACCV(jr, nt, 0), ACCV(jr, nt, 1));
    }
  }
}

// sum slices; write TRANSPOSED hi/lo bf16: bt[d*256+m] = kvs[m][d]
__global__ void kvs_reduce(const float* __restrict__ part,
                           __nv_bfloat16* __restrict__ bth,
                           __nv_bfloat16* __restrict__ btl) {
  int idx = blockIdx.x * blockDim.x + threadIdx.x;
  if (idx < CH * CH) {
    int m = idx >> 8, d = idx & 255;
    float s = 0.f;
#pragma unroll
    for (int ss = 0; ss < NSLICE; ss++) s += part[(size_t)ss * CH * CH + idx];
    __nv_bfloat16 h = __float2bfloat16(s);
    __nv_bfloat16 lo = __float2bfloat16(s - __bfloat162float(h));
    bth[d * CH + m] = h;
    btl[d * CH + m] = lo;
  }
}

// ---------------------------------------------------------------------------
extern "C" void kernel_launch(void* const* d_in, const int* in_sizes, int n_in,
                              void* d_out, int out_size) {
  (void)in_sizes; (void)n_in; (void)out_size;
  const float* x    = (const float*)d_in[0];
  const float* fc_w = (const float*)d_in[1];
  const float* fc_b = (const float*)d_in[2];
  const float* Wq_w = (const float*)d_in[3];
  const float* Wq_b = (const float*)d_in[4];
  const float* Wk_w = (const float*)d_in[5];
  const float* Wk_b = (const float*)d_in[6];
  const float* Wv_w = (const float*)d_in[7];
  const float* Wv_b = (const float*)d_in[8];
  const float* ln_g = (const float*)d_in[9];
  const float* ln_b = (const float*)d_in[10];
  float* out = (float*)d_out;

  float *part, *scal, *dp;
  __nv_bfloat16 *xh, *xl, *ahh, *ahl, *bhh, *bhl, *qh, *ql, *kh, *kl, *vh, *vl, *wh, *wl, *bth, *btl;
  cudaGetSymbolAddress((void**)&part, g_part);
  cudaGetSymbolAddress((void**)&scal, g_scal);
  cudaGetSymbolAddress((void**)&dp, g_dp);
  cudaGetSymbolAddress((void**)&xh, g_xh);  cudaGetSymbolAddress((void**)&xl, g_xl);
  cudaGetSymbolAddress((void**)&ahh, g_ahh); cudaGetSymbolAddress((void**)&ahl, g_ahl);
  cudaGetSymbolAddress((void**)&bhh, g_bhh); cudaGetSymbolAddress((void**)&bhl, g_bhl);
  cudaGetSymbolAddress((void**)&qh, g_qh);  cudaGetSymbolAddress((void**)&ql, g_ql);
  cudaGetSymbolAddress((void**)&kh, g_kh);  cudaGetSymbolAddress((void**)&kl, g_kl);
  cudaGetSymbolAddress((void**)&vh, g_vh);  cudaGetSymbolAddress((void**)&vl, g_vl);
  cudaGetSymbolAddress((void**)&wh, g_wh);  cudaGetSymbolAddress((void**)&wl, g_wl);
  cudaGetSymbolAddress((void**)&bth, g_bth); cudaGetSymbolAddress((void**)&btl, g_btl);

  cudaFuncSetAttribute(gemm_mma<EPI_LN>,   cudaFuncAttributeMaxDynamicSharedMemorySize, SMEM_SZ);
  cudaFuncSetAttribute(gemm_mma<EPI_Q>,    cudaFuncAttributeMaxDynamicSharedMemorySize, SMEM_SZ);
  cudaFuncSetAttribute(gemm_mma<EPI_K>,    cudaFuncAttributeMaxDynamicSharedMemorySize, SMEM_SZ);
  cudaFuncSetAttribute(gemm_mma<EPI_V>,    cudaFuncAttributeMaxDynamicSharedMemorySize, SMEM_SZ);
  cudaFuncSetAttribute(gemm_mma<EPI_ATTN>, cudaFuncAttributeMaxDynamicSharedMemorySize, SMEM_SZ);
  cudaFuncSetAttribute(gemm_kvs, cudaFuncAttributeMaxDynamicSharedMemorySize, KSMEM);

  const int WSZ = CH * CH;
  // order: [0] fc split, [1] x split, [2] Wq0 split, [3] gemm_LN (profiled), ...
  split_kernel<<<WSZ / 256, 256>>>(fc_w, wh, wl, WSZ);
  split_kernel<<<(NROWS * CH + 255) / 256, 256>>>(x, xh, xl, NROWS * CH);
  split_kernel<<<WSZ / 256, 256>>>(Wq_w, wh + 1 * WSZ, wl + 1 * WSZ, WSZ);

  gemm_mma<EPI_LN><<<TGRID, NTHR, SMEM_SZ>>>(
      xh, xl, wh, wl, fc_b, nullptr, ahh, ahl, ln_g, ln_b,
      nullptr, nullptr, nullptr, nullptr, nullptr, nullptr, nullptr, nullptr);

  split_kernel<<<WSZ / 256, 256>>>(Wk_w, wh + 2 * WSZ, wl + 2 * WSZ, WSZ);
  split_kernel<<<WSZ / 256, 256>>>(Wv_w, wh + 3 * WSZ, wl + 3 * WSZ, WSZ);

  for (int L = 0; L < 2; L++) {
    if (L == 1) {
      split_kernel<<<WSZ / 256, 256>>>(Wq_w + (size_t)WSZ, wh + 4 * WSZ, wl + 4 * WSZ, WSZ);
      split_kernel<<<WSZ / 256, 256>>>(Wk_w + (size_t)WSZ, wh + 5 * WSZ, wl + 5 * WSZ, WSZ);
      split_kernel<<<WSZ / 256, 256>>>(Wv_w + (size_t)WSZ, wh + 6 * WSZ, wl + 6 * WSZ, WSZ);
    }
    const __nv_bfloat16* hh = L ? bhh : ahh;
    const __nv_bfloat16* hl = L ? bhl : ahl;
    float* ob = L ? out : nullptr;
    __nv_bfloat16* obh = L ? nullptr : bhh;
    __nv_bfloat16* obl = L ? nullptr : bhl;
    const size_t bo = (size_t)L * CH;
    const int wo = (L ? 4 : 1);

    zero_kernel<<<1, CH + 4>>>(scal, CH + 4);
    gemm_mma<EPI_Q><<<TGRID, NTHR, SMEM_SZ>>>(
        hh, hl, wh + (size_t)wo * WSZ, wl + (size_t)wo * WSZ, Wq_b + bo,
        nullptr, qh, ql, nullptr, nullptr, scal + 0, nullptr, nullptr, nullptr,
        nullptr, nullptr, nullptr, nullptr);
    gemm_mma<EPI_K><<<TGRID, NTHR, SMEM_SZ>>>(
        hh, hl, wh + (size_t)(wo + 1) * WSZ, wl + (size_t)(wo + 1) * WSZ, Wk_b + bo,
        nullptr, kh, kl, nullptr, nullptr, scal + 1, scal + 4, nullptr, nullptr,
        nullptr, nullptr, nullptr, nullptr);
    gemm_mma<EPI_V><<<TGRID, NTHR, SMEM_SZ>>>(
        hh, hl, wh + (size_t)(wo + 2) * WSZ, wl + (size_t)(wo + 2) * WSZ, Wv_b + bo,
        nullptr, vh, vl, nullptr, nullptr, nullptr, nullptr, nullptr, nullptr,
        nullptr, nullptr, nullptr, nullptr);
    dp_kernel<<<(NROWS + 31) / 32, NTHR>>>(qh, ql, scal, dp);
    gemm_kvs<<<dim3(2, 2, NSLICE), NTHR, KSMEM>>>(kh, kl, vh, vl, part);
    kvs_reduce<<<64, 1024>>>(part, bth, btl);
    gemm_mma<EPI_ATTN><<<TGRID, NTHR, SMEM_SZ>>>(
        qh, ql, bth, btl, nullptr, ob, obh, obl,
        ln_g + (size_t)(L + 1) * CH, ln_b + (size_t)(L + 1) * CH,
        nullptr, nullptr, scal, dp, vh, vl, hh, hl);
  }
}

// round 14
// speedup vs baseline: 2.8589x; 1.0335x over previous
#include <cuda_runtime.h>
#include <cuda_bf16.h>
#include <cstdint>

#define NROWS 100000
#define CH 256
#define NTHR 256
// ---- MMA gemm params (BM=64 x BN=256, occ 2) ----
#define TM 64
#define TGRID ((NROWS + TM - 1) / TM)   // 1563
#define AB (64 * 80)
#define WB (256 * 80)
#define BUFB (2 * AB + 2 * WB)
#define SCR (2 * BUFB)
#define SMEM_SZ (SCR + 4096)
// ---- kvs MMA params ----
#define NSLICE 74
#define SLICE_CHUNKS 43
#define KA_STR 272
#define KAB (32 * KA_STR)
#define KBUF (4 * KAB)
#define KSMEM (3 * KBUF)

// ---------------- scratch -----------------------------------------------------
__device__ float g_part[(size_t)NSLICE * CH * CH];
__device__ float g_scal[CH + 4];
__device__ float g_dp[NROWS];
__device__ __nv_bfloat16 g_xh[(size_t)NROWS * CH], g_xl[(size_t)NROWS * CH];
__device__ __nv_bfloat16 g_ahh[(size_t)NROWS * CH], g_ahl[(size_t)NROWS * CH];
__device__ __nv_bfloat16 g_bhh[(size_t)NROWS * CH], g_bhl[(size_t)NROWS * CH];
__device__ __nv_bfloat16 g_qh[(size_t)NROWS * CH], g_ql[(size_t)NROWS * CH];
__device__ __nv_bfloat16 g_kh[(size_t)NROWS * CH], g_kl[(size_t)NROWS * CH];
__device__ __nv_bfloat16 g_vh[(size_t)NROWS * CH], g_vl[(size_t)NROWS * CH];
__device__ __nv_bfloat16 g_wh[7 * 65536], g_wl[7 * 65536];
__device__ __nv_bfloat16 g_bth[65536], g_btl[65536];

// ---------------- helpers ------------------------------------------------------
__device__ __forceinline__ uint32_t smem_u32(const void* p) {
  uint32_t a;
  asm("{ .reg .u64 t; cvta.to.shared.u64 t, %1; cvt.u32.u64 %0, t; }" : "=r"(a) : "l"(p));
  return a;
}
#define CP16(dst, src) \
  asm volatile("cp.async.cg.shared.global [%0], [%1], 16;" :: "r"(dst), "l"(src))
#define CP16Z(dst, src, vb) \
  asm volatile("cp.async.cg.shared.global [%0], [%1], 16, %2;" :: "r"(dst), "l"(src), "r"(vb))
#define CP_COMMIT() asm volatile("cp.async.commit_group;" ::: "memory")
#define CP_WAIT(n) asm volatile("cp.async.wait_group %0;" :: "n"(n) : "memory")

__device__ __forceinline__ void ldm_x4(uint32_t* r, uint32_t addr) {
  asm volatile("ldmatrix.sync.aligned.m8n8.x4.shared.b16 {%0,%1,%2,%3}, [%4];"
               : "=r"(r[0]), "=r"(r[1]), "=r"(r[2]), "=r"(r[3]) : "r"(addr));
}
__device__ __forceinline__ void ldm_x4t(uint32_t* r, uint32_t addr) {
  asm volatile("ldmatrix.sync.aligned.m8n8.x4.trans.shared.b16 {%0,%1,%2,%3}, [%4];"
               : "=r"(r[0]), "=r"(r[1]), "=r"(r[2]), "=r"(r[3]) : "r"(addr));
}
__device__ __forceinline__ void mma_bf16(float* c, const uint32_t* a, const uint32_t* b) {
  asm volatile(
      "mma.sync.aligned.m16n8k16.row.col.f32.bf16.bf16.f32 "
      "{%0,%1,%2,%3}, {%4,%5,%6,%7}, {%8,%9}, {%0,%1,%2,%3};"
      : "+f"(c[0]), "+f"(c[1]), "+f"(c[2]), "+f"(c[3])
      : "r"(a[0]), "r"(a[1]), "r"(a[2]), "r"(a[3]), "r"(b[0]), "r"(b[1]));
}
// 12 MMAs per ntp, term-major: consecutive MMAs hit different accumulators.
#define MMA_BLOCK(acc, ntp, ah, al_, bh4, bl4) do { \
  mma_bf16(acc[0][2*(ntp)],     ah[0],  bh4);     \
  mma_bf16(acc[1][2*(ntp)],     ah[1],  bh4);     \
  mma_bf16(acc[0][2*(ntp) + 1], ah[0],  bh4 + 2); \
  mma_bf16(acc[1][2*(ntp) + 1], ah[1],  bh4 + 2); \
  mma_bf16(acc[0][2*(ntp)],     ah[0],  bl4);     \
  mma_bf16(acc[1][2*(ntp)],     ah[1],  bl4);     \
  mma_bf16(acc[0][2*(ntp) + 1], ah[0],  bl4 + 2); \
  mma_bf16(acc[1][2*(ntp) + 1], ah[1],  bl4 + 2); \
  mma_bf16(acc[0][2*(ntp)],     al_[0], bh4);     \
  mma_bf16(acc[1][2*(ntp)],     al_[1], bh4);     \
  mma_bf16(acc[0][2*(ntp) + 1], al_[0], bh4 + 2); \
  mma_bf16(acc[1][2*(ntp) + 1], al_[1], bh4 + 2); \
} while (0)

__device__ __forceinline__ float wredf(float v) {
#pragma unroll
  for (int o = 16; o > 0; o >>= 1) v += __shfl_xor_sync(0xffffffffu, v, o);
  return v;
}
__device__ __forceinline__ unsigned short bfb(__nv_bfloat16 h) {
  return *reinterpret_cast<unsigned short*>(&h);
}
__device__ __forceinline__ void packhl(float v0, float v1, uint32_t& hi, uint32_t& lo) {
  __nv_bfloat16 h0 = __float2bfloat16(v0), h1 = __float2bfloat16(v1);
  __nv_bfloat16 l0 = __float2bfloat16(v0 - __bfloat162float(h0));
  __nv_bfloat16 l1 = __float2bfloat16(v1 - __bfloat162float(h1));
  hi = (uint32_t)bfb(h0) | ((uint32_t)bfb(h1) << 16);
  lo = (uint32_t)bfb(l0) | ((uint32_t)bfb(l1) << 16);
}
__device__ __forceinline__ float2 bf2f2(uint32_t u) {
  __nv_bfloat162 b = *reinterpret_cast<__nv_bfloat162*>(&u);
  return __bfloat1622float2(b);
}

// ---------------------------------------------------------------------------
__global__ void split_kernel(const float* __restrict__ src,
                             __nv_bfloat16* __restrict__ hi,
                             __nv_bfloat16* __restrict__ lo, int n) {
  int i = blockIdx.x * blockDim.x + threadIdx.x;
  if (i < n) {
    float x = src[i];
    __nv_bfloat16 h = __float2bfloat16(x);
    hi[i] = h;
    lo[i] = __float2bfloat16(x - __bfloat162float(h));
  }
}
__global__ void zero_kernel(float* p, int n) {
  int i = blockIdx.x * blockDim.x + threadIdx.x;
  if (i < n) p[i] = 0.f;
}

// dp[r] = q[r,:] . ks_sum
__global__ void __launch_bounds__(NTHR) dp_kernel(const __nv_bfloat16* __restrict__ Qh,
                                                  const __nv_bfloat16* __restrict__ Ql,
                                                  const float* __restrict__ scal,
                                                  float* __restrict__ dp) {
  int tid = threadIdx.x, w = tid >> 5, l = tid & 31;
  int rsub = l >> 3, cseg = l & 7;
  int r = blockIdx.x * 32 + w * 4 + rsub;
  float s = 0.f;
  if (r < NROWS) {
    const uint4* qh4 = (const uint4*)(Qh + (size_t)r * CH + cseg * 32);
    const uint4* ql4 = (const uint4*)(Ql + (size_t)r * CH + cseg * 32);
    const float4* k4 = (const float4*)(scal + 4 + cseg * 32);
#pragma unroll
    for (int i = 0; i < 4; i++) {
      uint4 H = qh4[i], L = ql4[i];
      float4 ka = k4[2 * i], kb = k4[2 * i + 1];
      float2 h0 = bf2f2(H.x), l0 = bf2f2(L.x);
      float2 h1 = bf2f2(H.y), l1 = bf2f2(L.y);
      float2 h2 = bf2f2(H.z), l2 = bf2f2(L.z);
      float2 h3 = bf2f2(H.w), l3 = bf2f2(L.w);
      s += (h0.x + l0.x) * ka.x + (h0.y + l0.y) * ka.y;
      s += (h1.x + l1.x) * ka.z + (h1.y + l1.y) * ka.w;
      s += (h2.x + l2.x) * kb.x + (h2.y + l2.y) * kb.y;
      s += (h3.x + l3.x) * kb.z + (h3.y + l3.y) * kb.w;
    }
  }
#pragma unroll
  for (int o = 4; o > 0; o >>= 1) s += __shfl_xor_sync(0xffffffffu, s, o);
  if (cseg == 0 && r < NROWS) dp[r] = s;
}

#define ACCV(jr, nt, c) acc[(jr) >> 1][nt][(((jr) & 1) << 1) + (c)]

// ---------------------------------------------------------------------------
// fused QKV GEMM: blockIdx.y selects {Q,K,V} weights + epilogue
// ---------------------------------------------------------------------------
__global__ void __launch_bounds__(NTHR, 2) gemm_qkv(
    const __nv_bfloat16* __restrict__ Ah, const __nv_bfloat16* __restrict__ Al,
    const __nv_bfloat16* __restrict__ WhB, const __nv_bfloat16* __restrict__ WlB,
    const float* __restrict__ bq, const float* __restrict__ bk, const float* __restrict__ bv,
    __nv_bfloat16* __restrict__ Qh, __nv_bfloat16* __restrict__ Ql,
    __nv_bfloat16* __restrict__ Kh, __nv_bfloat16* __restrict__ Kl,
    __nv_bfloat16* __restrict__ Vhh, __nv_bfloat16* __restrict__ Vll,
    float* __restrict__ scal)
{
  extern __shared__ char smem[];
  const uint32_t sb = smem_u32(smem);
  const int tid = threadIdx.x, w = tid >> 5, l = tid & 31;
  const int wrow = w >> 2, wcol = w & 3;
  const int m0 = blockIdx.x * TM;
  const int y = blockIdx.y;           // 0=Q 1=K 2=V
  const bool isQ = (y == 0), isK = (y == 1);

  float* sCol = (float*)(smem + SCR + 2048);
  float* sRed = (float*)(smem + SCR + 3072);
  if (isK) sCol[tid] = 0.f;

  const __nv_bfloat16* Wh = WhB + (size_t)y * (CH * CH);
  const __nv_bfloat16* Wl = WlB + (size_t)y * (CH * CH);
  const float* bias = isQ ? bq : (isK ? bk : bv);
  __nv_bfloat16* Chi = isQ ? Qh : (isK ? Kh : Vhh);
  __nv_bfloat16* Clo = isQ ? Ql : (isK ? Kl : Vll);

  float acc[2][8][4];
#pragma unroll
  for (int a = 0; a < 2; a++)
#pragma unroll
    for (int b = 0; b < 8; b++)
#pragma unroll
      for (int c = 0; c < 4; c++) acc[a][b][c] = 0.f;

  auto issue = [&](int ch, int buf) {
    const uint32_t base = sb + buf * BUFB;
    const int k0 = ch * 32;
    {
      int row = tid >> 2, seg = tid & 3;
      int gr = m0 + row; if (gr > NROWS - 1) gr = NROWS - 1;
      size_t g = (size_t)gr * CH + k0 + seg * 8;
      uint32_t so = row * 80 + seg * 16;
      CP16(base + so, Ah + g);
      CP16(base + AB + so, Al + g);
    }
#pragma unroll
    for (int t = 0; t < 4; t++) {
      int idx = tid + t * 256;
      int row = idx >> 2, seg = idx & 3;
      size_t g = (size_t)row * CH + k0 + seg * 8;
      uint32_t so = row * 80 + seg * 16;
      CP16(base + 2 * AB + so, Wh + g);
      CP16(base + 2 * AB + WB + so, Wl + g);
    }
  };

  issue(0, 0); CP_COMMIT();
#pragma unroll
  for (int ch = 0; ch < 8; ch++) {
    if (ch < 7) { issue(ch + 1, (ch + 1) & 1); CP_COMMIT(); CP_WAIT(1); }
    else CP_WAIT(0);
    __syncthreads();
    const uint32_t base = sb + (ch & 1) * BUFB;
#pragma unroll
    for (int kt = 0; kt < 2; kt++) {
      uint32_t ah[2][4], al_[2][4];
#pragma unroll
      for (int mt = 0; mt < 2; mt++) {
        int row = wrow * 32 + mt * 16 + (l & 15);
        int col = kt * 16 + ((l >> 4) << 3);
        uint32_t off = row * 80 + col * 2;
        ldm_x4(ah[mt], base + off);
        ldm_x4(al_[mt], base + AB + off);
      }
#pragma unroll
      for (int ntp = 0; ntp < 4; ntp++) {
        int n = wcol * 64 + ntp * 16 + ((l >> 4) << 3) + (l & 7);
        int col = kt * 16 + ((l >> 3) & 1) * 8;
        uint32_t off = n * 80 + col * 2;
        uint32_t bh4[4], bl4[4];
        ldm_x4(bh4, base + 2 * AB + off);
        ldm_x4(bl4, base + 2 * AB + WB + off);
        MMA_BLOCK(acc, ntp, ah, al_, bh4, bl4);
      }
    }
    __syncthreads();
  }

  // epilogue
  const int qlane = l >> 2;
  const int cbase = wcol * 64 + (l & 3) * 2;
  float nrm = 0.f;
#pragma unroll
  for (int nt = 0; nt < 8; nt++) {
    const int col = cbase + nt * 8;
    float2 bs = *(const float2*)(bias + col);
    float cs0 = 0.f, cs1 = 0.f;
#pragma unroll
    for (int jr = 0; jr < 4; jr++) {
      int r = m0 + wrow * 32 + (jr >> 1) * 16 + (jr & 1) * 8 + qlane;
      bool valid = r < NROWS;
      float v0 = ACCV(jr, nt, 0) + bs.x;
      float v1 = ACCV(jr, nt, 1) + bs.y;
      if (valid) {
        if (y < 2) nrm = fmaf(v0, v0, fmaf(v1, v1, nrm));
        if (isK) { cs0 += v0; cs1 += v1; }
        uint32_t hi, lo;
        packhl(v0, v1, hi, lo);
        *(uint32_t*)(Chi + (size_t)r * CH + col) = hi;
        *(uint32_t*)(Clo + (size_t)r * CH + col) = lo;
      }
    }
    if (isK) {
#pragma unroll
      for (int o = 4; o < 32; o <<= 1) {
        cs0 += __shfl_xor_sync(0xffffffffu, cs0, o);
        cs1 += __shfl_xor_sync(0xffffffffu, cs1, o);
      }
      if (qlane == 0) { atomicAdd(&sCol[col], cs0); atomicAdd(&sCol[col + 1], cs1); }
    }
  }
  if (y < 2) {
    float p = wredf(nrm);
    if (l == 0) sRed[w] = p;
    __syncthreads();
    if (tid == 0) {
      float s = 0.f;
#pragma unroll
      for (int i = 0; i < 8; i++) s += sRed[i];
      atomicAdd(scal + (isQ ? 0 : 1), s);
    }
    if (isK) atomicAdd(&scal[4 + tid], sCol[tid]);
  }
}

// ---------------------------------------------------------------------------
// gemm_mma: EPI_LN (fc) and EPI_ATTN
// ---------------------------------------------------------------------------
#define EPI_LN   0
#define EPI_ATTN 4

template<int EPI>
__global__ void __launch_bounds__(NTHR, 2) gemm_mma(
    const __nv_bfloat16* __restrict__ Ah, const __nv_bfloat16* __restrict__ Al,
    const __nv_bfloat16* __restrict__ Wh, const __nv_bfloat16* __restrict__ Wl,
    const float* __restrict__ bias,
    float* __restrict__ Cf, __nv_bfloat16* __restrict__ Chi, __nv_bfloat16* __restrict__ Clo,
    const float* __restrict__ gamma, const float* __restrict__ beta,
    const float* __restrict__ scal, const float* __restrict__ dpv,
    const __nv_bfloat16* __restrict__ Vh, const __nv_bfloat16* __restrict__ Vl,
    const __nv_bfloat16* __restrict__ Ph, const __nv_bfloat16* __restrict__ Pl)
{
  extern __shared__ char smem[];
  const uint32_t sb = smem_u32(smem);
  const int tid = threadIdx.x, w = tid >> 5, l = tid & 31;
  const int wrow = w >> 2, wcol = w & 3;
  const int m0 = blockIdx.x * TM;

  float* sS1 = (float*)(smem + SCR);
  float* sS2 = (float*)(smem + SCR + 1024);

  float acc[2][8][4];
#pragma unroll
  for (int a = 0; a < 2; a++)
#pragma unroll
    for (int b = 0; b < 8; b++)
#pragma unroll
      for (int c = 0; c < 4; c++) acc[a][b][c] = 0.f;

  auto issue = [&](int ch, int buf) {
    const uint32_t base = sb + buf * BUFB;
    const int k0 = ch * 32;
    {
      int row = tid >> 2, seg = tid & 3;
      int gr = m0 + row; if (gr > NROWS - 1) gr = NROWS - 1;
      size_t g = (size_t)gr * CH + k0 + seg * 8;
      uint32_t so = row * 80 + seg * 16;
      CP16(base + so, Ah + g);
      CP16(base + AB + so, Al + g);
    }
#pragma unroll
    for (int t = 0; t < 4; t++) {
      int idx = tid + t * 256;
      int row = idx >> 2, seg = idx & 3;
      size_t g = (size_t)row * CH + k0 + seg * 8;
      uint32_t so = row * 80 + seg * 16;
      CP16(base + 2 * AB + so, Wh + g);
      CP16(base + 2 * AB + WB + so, Wl + g);
    }
  };

  issue(0, 0); CP_COMMIT();
#pragma unroll
  for (int ch = 0; ch < 8; ch++) {
    if (ch < 7) { issue(ch + 1, (ch + 1) & 1); CP_COMMIT(); CP_WAIT(1); }
    else CP_WAIT(0);
    __syncthreads();
    const uint32_t base = sb + (ch & 1) * BUFB;
#pragma unroll
    for (int kt = 0; kt < 2; kt++) {
      uint32_t ah[2][4], al_[2][4];
#pragma unroll
      for (int mt = 0; mt < 2; mt++) {
        int row = wrow * 32 + mt * 16 + (l & 15);
        int col = kt * 16 + ((l >> 4) << 3);
        uint32_t off = row * 80 + col * 2;
        ldm_x4(ah[mt], base + off);
        ldm_x4(al_[mt], base + AB + off);
      }
#pragma unroll
      for (int ntp = 0; ntp < 4; ntp++) {
        int n = wcol * 64 + ntp * 16 + ((l >> 4) << 3) + (l & 7);
        int col = kt * 16 + ((l >> 3) & 1) * 8;
        uint32_t off = n * 80 + col * 2;
        uint32_t bh4[4], bl4[4];
        ldm_x4(bh4, base + 2 * AB + off);
        ldm_x4(bl4, base + 2 * AB + WB + off);
        MMA_BLOCK(acc, ntp, ah, al_, bh4, bl4);
      }
    }
    __syncthreads();
  }

  // epilogue: transform -> row stats -> LN+ReLU
  const int qlane = l >> 2;
  const int cbase = wcol * 64 + (l & 3) * 2;
  const float nF = (float)NROWS;
  float cN = 0.f;
  if (EPI == EPI_ATTN) cN = rsqrtf(scal[0] * scal[1]);
#pragma unroll
  for (int jr = 0; jr < 4; jr++) {
    const int lrow = wrow * 32 + (jr >> 1) * 16 + (jr & 1) * 8 + qlane;
    const int r = m0 + lrow;
    const bool valid = r < NROWS;
    float invr = 0.f;
    if (EPI == EPI_ATTN) invr = 1.f / fmaf(cN, valid ? dpv[r] : 0.f, nF);
    float s1 = 0.f, s2 = 0.f;
#pragma unroll
    for (int nt = 0; nt < 8; nt++) {
      const int col = cbase + nt * 8;
      if (EPI == EPI_LN) {
        float2 bs = *(const float2*)(bias + col);
        float y0 = ACCV(jr, nt, 0) + bs.x;
        float y1 = ACCV(jr, nt, 1) + bs.y;
        ACCV(jr, nt, 0) = y0; ACCV(jr, nt, 1) = y1;
        s1 += y0 + y1; s2 = fmaf(y0, y0, fmaf(y1, y1, s2));
      } else {
        uint32_t uvh = 0, uvl = 0, uph = 0, upl = 0;
        if (valid) {
          uvh = *(const uint32_t*)(Vh + (size_t)r * CH + col);
          uvl = *(const uint32_t*)(Vl + (size_t)r * CH + col);
          uph = *(const uint32_t*)(Ph + (size_t)r * CH + col);
          upl = *(const uint32_t*)(Pl + (size_t)r * CH + col);
        }
        float2 a0 = bf2f2(uvh), a1 = bf2f2(uvl);
        float2 b0 = bf2f2(uph), b1 = bf2f2(upl);
        float vvx = a0.x + a1.x, vvy = a0.y + a1.y;
        float ppx = b0.x + b1.x, ppy = b0.y + b1.y;
        float h0 = 0.5f * (fmaf(cN, ACCV(jr, nt, 0), nF * vvx) * invr + ppx);
        float h1 = 0.5f * (fmaf(cN, ACCV(jr, nt, 1), nF * vvy) * invr + ppy);
        ACCV(jr, nt, 0) = h0; ACCV(jr, nt, 1) = h1;
        s1 += h0 + h1; s2 = fmaf(h0, h0, fmaf(h1, h1, s2));
      }
    }
#pragma unroll
    for (int o = 1; o < 4; o <<= 1) {
      s1 += __shfl_xor_sync(0xffffffffu, s1, o);
      s2 += __shfl_xor_sync(0xffffffffu, s2, o);
    }
    if ((l & 3) == 0) { sS1[wcol * 64 + lrow] = s1; sS2[wcol * 64 + lrow] = s2; }
  }
  __syncthreads();
#pragma unroll
  for (int jr = 0; jr < 4; jr++) {
    const int lrow = wrow * 32 + (jr >> 1) * 16 + (jr & 1) * 8 + qlane;
    const int r = m0 + lrow;
    const bool valid = r < NROWS;
    const float s1 = sS1[lrow] + sS1[64 + lrow] + sS1[128 + lrow] + sS1[192 + lrow];
    const float s2 = sS2[lrow] + sS2[64 + lrow] + sS2[128 + lrow] + sS2[192 + lrow];
    const float mu = s1 * (1.f / CH);
    const float rs = rsqrtf(s2 * (1.f / CH) - mu * mu + 1e-5f);
#pragma unroll
    for (int nt = 0; nt < 8; nt++) {
      const int col = cbase + nt * 8;
      float2 gg = *(const float2*)(gamma + col);
      float2 bb = *(const float2*)(beta + col);
      float o0 = fmaxf((ACCV(jr, nt, 0) - mu) * rs * gg.x + bb.x, 0.f);
      float o1 = fmaxf((ACCV(jr, nt, 1) - mu) * rs * gg.y + bb.y, 0.f);
      if (valid) {
        if (Cf) *(float2*)(Cf + (size_t)r * CH + col) = make_float2(o0, o1);
        if (Chi) {
          uint32_t hi, lo;
          packhl(o0, o1, hi, lo);
          *(uint32_t*)(Chi + (size_t)r * CH + col) = hi;
          *(uint32_t*)(Clo + (size_t)r * CH + col) = lo;
        }
      }
    }
  }
}

// ---------------------------------------------------------------------------
// MMA kvs: part[s][m][d] quarters (m 128 x d 128). occ 2. 3-stage pipeline.
// ---------------------------------------------------------------------------
__global__ void __launch_bounds__(NTHR, 2) gemm_kvs(
    const __nv_bfloat16* __restrict__ Kh, const __nv_bfloat16* __restrict__ Kl,
    const __nv_bfloat16* __restrict__ Vh, const __nv_bfloat16* __restrict__ Vl,
    float* __restrict__ part)
{
  extern __shared__ char smem[];
  const uint32_t sb = smem_u32(smem);
  const int tid = threadIdx.x, w = tid >> 5, l = tid & 31;
  const int wrow = w >> 1, wcol = w & 1;
  const int m0 = blockIdx.x * 128;
  const int d0g = blockIdx.y * 128;
  const int n0 = blockIdx.z * (SLICE_CHUNKS * 32);

  float acc[2][8][4];
#pragma unroll
  for (int a = 0; a < 2; a++)
#pragma unroll
    for (int b = 0; b < 8; b++)
#pragma unroll
      for (int c = 0; c < 4; c++) acc[a][b][c] = 0.f;

  auto issue = [&](int ch, int buf) {
    const uint32_t base = sb + buf * KBUF;
    const int nb = n0 + ch * 32;
#pragma unroll
    for (int t = 0; t < 2; t++) {
      int idx = tid + t * 256;
      int row = idx >> 4, seg = idx & 15;
      int gn = nb + row;
      uint32_t vb = (gn < NROWS) ? 16u : 0u;
      if (gn > NROWS - 1) gn = NROWS - 1;
      uint32_t so = row * KA_STR + seg * 16;
      size_t gk = (size_t)gn * CH + m0 + seg * 8;
      size_t gv = (size_t)gn * CH + d0g + seg * 8;
      CP16Z(base + so, Kh + gk, vb);
      CP16Z(base + KAB + so, Kl + gk, vb);
      CP16Z(base + 2 * KAB + so, Vh + gv, vb);
      CP16Z(base + 3 * KAB + so, Vl + gv, vb);
    }
  };

  issue(0, 0); CP_COMMIT();
  issue(1, 1); CP_COMMIT();
  for (int ch = 0; ch < SLICE_CHUNKS; ch++) {
    if (ch + 1 < SLICE_CHUNKS) CP_WAIT(1); else CP_WAIT(0);
    __syncthreads();
    if (ch + 2 < SLICE_CHUNKS) { issue(ch + 2, (ch + 2) % 3); CP_COMMIT(); }
    const uint32_t base = sb + (ch % 3) * KBUF;
#pragma unroll
    for (int kt = 0; kt < 2; kt++) {
      const int k0 = kt * 16;
      uint32_t ah[2][4], al_[2][4];
#pragma unroll
      for (int mt = 0; mt < 2; mt++) {
        int krow = k0 + (l & 7) + ((l >> 4) << 3);
        int mcol = wrow * 32 + mt * 16 + ((l >> 3) & 1) * 8;
        uint32_t off = krow * KA_STR + mcol * 2;
        ldm_x4t(ah[mt], base + off);
        ldm_x4t(al_[mt], base + KAB + off);
      }
#pragma unroll
      for (int ntp = 0; ntp < 4; ntp++) {
        int dd = wcol * 64 + ntp * 16 + ((l >> 4) << 3);
        int krow = k0 + (l & 7) + ((l >> 3) & 1) * 8;
        uint32_t off = krow * KA_STR + dd * 2;
        uint32_t bh4[4], bl4[4];
        ldm_x4t(bh4, base + 2 * KAB + off);
        ldm_x4t(bl4, base + 3 * KAB + off);
        MMA_BLOCK(acc, ntp, ah, al_, bh4, bl4);
      }
    }
    __syncthreads();
  }

  float* dst = part + (size_t)blockIdx.z * (CH * CH);
  const int qlane = l >> 2;
  const int cbase = wcol * 64 + (l & 3) * 2;
#pragma unroll
  for (int jr = 0; jr < 4; jr++) {
    int m = m0 + wrow * 32 + (jr >> 1) * 16 + (jr & 1) * 8 + qlane;
#pragma unroll
    for (int nt = 0; nt < 8; nt++) {
      int d = d0g + cbase + nt * 8;
      *(float2*)(dst + (size_t)m * CH + d) = make_float2(ACCV(jr, nt, 0), ACCV(jr, nt, 1));
    }
  }
}

// sum slices; write TRANSPOSED hi/lo bf16
__global__ void kvs_reduce(const float* __restrict__ part,
                           __nv_bfloat16* __restrict__ bth,
                           __nv_bfloat16* __restrict__ btl) {
  int idx = blockIdx.x * blockDim.x + threadIdx.x;
  if (idx < CH * CH) {
    int m = idx >> 8, d = idx & 255;
    float s = 0.f;
#pragma unroll
    for (int ss = 0; ss < NSLICE; ss++) s += part[(size_t)ss * CH * CH + idx];
    __nv_bfloat16 h = __float2bfloat16(s);
    __nv_bfloat16 lo = __float2bfloat16(s - __bfloat162float(h));
    bth[d * CH + m] = h;
    btl[d * CH + m] = lo;
  }
}

// ---------------------------------------------------------------------------
extern "C" void kernel_launch(void* const* d_in, const int* in_sizes, int n_in,
                              void* d_out, int out_size) {
  (void)in_sizes; (void)n_in; (void)out_size;
  const float* x    = (const float*)d_in[0];
  const float* fc_w = (const float*)d_in[1];
  const float* fc_b = (const float*)d_in[2];
  const float* Wq_w = (const float*)d_in[3];
  const float* Wq_b = (const float*)d_in[4];
  const float* Wk_w = (const float*)d_in[5];
  const float* Wk_b = (const float*)d_in[6];
  const float* Wv_w = (const float*)d_in[7];
  const float* Wv_b = (const float*)d_in[8];
  const float* ln_g = (const float*)d_in[9];
  const float* ln_b = (const float*)d_in[10];
  float* out = (float*)d_out;

  float *part, *scal, *dp;
  __nv_bfloat16 *xh, *xl, *ahh, *ahl, *bhh, *bhl, *qh, *ql, *kh, *kl, *vh, *vl, *wh, *wl, *bth, *btl;
  cudaGetSymbolAddress((void**)&part, g_part);
  cudaGetSymbolAddress((void**)&scal, g_scal);
  cudaGetSymbolAddress((void**)&dp, g_dp);
  cudaGetSymbolAddress((void**)&xh, g_xh);  cudaGetSymbolAddress((void**)&xl, g_xl);
  cudaGetSymbolAddress((void**)&ahh, g_ahh); cudaGetSymbolAddress((void**)&ahl, g_ahl);
  cudaGetSymbolAddress((void**)&bhh, g_bhh); cudaGetSymbolAddress((void**)&bhl, g_bhl);
  cudaGetSymbolAddress((void**)&qh, g_qh);  cudaGetSymbolAddress((void**)&ql, g_ql);
  cudaGetSymbolAddress((void**)&kh, g_kh);  cudaGetSymbolAddress((void**)&kl, g_kl);
  cudaGetSymbolAddress((void**)&vh, g_vh);  cudaGetSymbolAddress((void**)&vl, g_vl);
  cudaGetSymbolAddress((void**)&wh, g_wh);  cudaGetSymbolAddress((void**)&wl, g_wl);
  cudaGetSymbolAddress((void**)&bth, g_bth); cudaGetSymbolAddress((void**)&btl, g_btl);

  cudaFuncSetAttribute(gemm_mma<EPI_LN>,   cudaFuncAttributeMaxDynamicSharedMemorySize, SMEM_SZ);
  cudaFuncSetAttribute(gemm_mma<EPI_ATTN>, cudaFuncAttributeMaxDynamicSharedMemorySize, SMEM_SZ);
  cudaFuncSetAttribute(gemm_qkv, cudaFuncAttributeMaxDynamicSharedMemorySize, SMEM_SZ);
  cudaFuncSetAttribute(gemm_kvs, cudaFuncAttributeMaxDynamicSharedMemorySize, KSMEM);

  const int WSZ = CH * CH;
  split_kernel<<<WSZ / 256, 256>>>(fc_w, wh, wl, WSZ);
  split_kernel<<<(NROWS * CH + 255) / 256, 256>>>(x, xh, xl, NROWS * CH);
  split_kernel<<<WSZ / 256, 256>>>(Wq_w, wh + 1 * WSZ, wl + 1 * WSZ, WSZ);

  gemm_mma<EPI_LN><<<TGRID, NTHR, SMEM_SZ>>>(
      xh, xl, wh, wl, fc_b, nullptr, ahh, ahl, ln_g, ln_b,
      nullptr, nullptr, nullptr, nullptr, nullptr, nullptr);

  split_kernel<<<WSZ / 256, 256>>>(Wk_w, wh + 2 * WSZ, wl + 2 * WSZ, WSZ);
  split_kernel<<<WSZ / 256, 256>>>(Wv_w, wh + 3 * WSZ, wl + 3 * WSZ, WSZ);

  for (int L = 0; L < 2; L++) {
    if (L == 1) {
      split_kernel<<<WSZ / 256, 256>>>(Wq_w + (size_t)WSZ, wh + 4 * WSZ, wl + 4 * WSZ, WSZ);
      split_kernel<<<WSZ / 256, 256>>>(Wk_w + (size_t)WSZ, wh + 5 * WSZ, wl + 5 * WSZ, WSZ);
      split_kernel<<<WSZ / 256, 256>>>(Wv_w + (size_t)WSZ, wh + 6 * WSZ, wl + 6 * WSZ, WSZ);
    }
    const __nv_bfloat16* hh = L ? bhh : ahh;
    const __nv_bfloat16* hl = L ? bhl : ahl;
    float* ob = L ? out : nullptr;
    __nv_bfloat16* obh = L ? nullptr : bhh;
    __nv_bfloat16* obl = L ? nullptr : bhl;
    const size_t bo = (size_t)L * CH;
    const int wo = (L ? 4 : 1);

    zero_kernel<<<1, CH + 4>>>(scal, CH + 4);
    gemm_qkv<<<dim3(TGRID, 3), NTHR, SMEM_SZ>>>(
        hh, hl, wh + (size_t)wo * WSZ, wl + (size_t)wo * WSZ,
        Wq_b + bo, Wk_b + bo, Wv_b + bo,
        qh, ql, kh, kl, vh, vl, scal);
    dp_kernel<<<(NROWS + 31) / 32, NTHR>>>(qh, ql, scal, dp);
    gemm_kvs<<<dim3(2, 2, NSLICE), NTHR, KSMEM>>>(kh, kl, vh, vl, part);
    kvs_reduce<<<64, 1024>>>(part, bth, btl);
    gemm_mma<EPI_ATTN><<<TGRID, NTHR, SMEM_SZ>>>(
        qh, ql, bth, btl, nullptr, ob, obh, obl,
        ln_g + (size_t)(L + 1) * CH, ln_b + (size_t)(L + 1) * CH,
        scal, dp, vh, vl, hh, hl);
  }
}

// round 15
// speedup vs baseline: 3.9241x; 1.3726x over previous
#include <cuda_runtime.h>
#include <cuda_bf16.h>
#include <cstdint>

#define NROWS 100000
#define CH 256
#define NTHR 256
// ---- MMA gemm params (BM=64 x BN=256, occ 2) ----
#define TM 64
#define TGRID ((NROWS + TM - 1) / TM)   // 1563
#define AB (64 * 80)
#define WB (256 * 80)
#define BUFB (2 * AB + 2 * WB)
#define SCR (2 * BUFB)
#define SMEM_SZ (SCR + 4096)
// ---- kvs MMA params (1-term: K hi + V hi only) ----
#define NSLICE 74
#define SLICE_CHUNKS 43
#define KA_STR 272
#define KAB (32 * KA_STR)
#define KBUF (2 * KAB)                  // Khi, Vhi
#define KSMEM (3 * KBUF)

// ---------------- scratch -----------------------------------------------------
__device__ float g_part[(size_t)NSLICE * CH * CH];
__device__ float g_scal[CH + 4];
__device__ float g_dp[NROWS];
__device__ __nv_bfloat16 g_xh[(size_t)NROWS * CH], g_xl[(size_t)NROWS * CH];
__device__ __nv_bfloat16 g_ahh[(size_t)NROWS * CH], g_ahl[(size_t)NROWS * CH];
__device__ __nv_bfloat16 g_bhh[(size_t)NROWS * CH], g_bhl[(size_t)NROWS * CH];
__device__ __nv_bfloat16 g_qh[(size_t)NROWS * CH];
__device__ __nv_bfloat16 g_kh[(size_t)NROWS * CH];
__device__ __nv_bfloat16 g_vh[(size_t)NROWS * CH], g_vl[(size_t)NROWS * CH];
__device__ __nv_bfloat16 g_wh[7 * 65536], g_wl[7 * 65536];
__device__ __nv_bfloat16 g_bth[65536];

// ---------------- helpers ------------------------------------------------------
__device__ __forceinline__ uint32_t smem_u32(const void* p) {
  uint32_t a;
  asm("{ .reg .u64 t; cvta.to.shared.u64 t, %1; cvt.u32.u64 %0, t; }" : "=r"(a) : "l"(p));
  return a;
}
#define CP16(dst, src) \
  asm volatile("cp.async.cg.shared.global [%0], [%1], 16;" :: "r"(dst), "l"(src))
#define CP16Z(dst, src, vb) \
  asm volatile("cp.async.cg.shared.global [%0], [%1], 16, %2;" :: "r"(dst), "l"(src), "r"(vb))
#define CP_COMMIT() asm volatile("cp.async.commit_group;" ::: "memory")
#define CP_WAIT(n) asm volatile("cp.async.wait_group %0;" :: "n"(n) : "memory")

__device__ __forceinline__ void ldm_x4(uint32_t* r, uint32_t addr) {
  asm volatile("ldmatrix.sync.aligned.m8n8.x4.shared.b16 {%0,%1,%2,%3}, [%4];"
               : "=r"(r[0]), "=r"(r[1]), "=r"(r[2]), "=r"(r[3]) : "r"(addr));
}
__device__ __forceinline__ void ldm_x4t(uint32_t* r, uint32_t addr) {
  asm volatile("ldmatrix.sync.aligned.m8n8.x4.trans.shared.b16 {%0,%1,%2,%3}, [%4];"
               : "=r"(r[0]), "=r"(r[1]), "=r"(r[2]), "=r"(r[3]) : "r"(addr));
}
__device__ __forceinline__ void mma_bf16(float* c, const uint32_t* a, const uint32_t* b) {
  asm volatile(
      "mma.sync.aligned.m16n8k16.row.col.f32.bf16.bf16.f32 "
      "{%0,%1,%2,%3}, {%4,%5,%6,%7}, {%8,%9}, {%0,%1,%2,%3};"
      : "+f"(c[0]), "+f"(c[1]), "+f"(c[2]), "+f"(c[3])
      : "r"(a[0]), "r"(a[1]), "r"(a[2]), "r"(a[3]), "r"(b[0]), "r"(b[1]));
}
// full 3-term split: 12 MMAs, term-major
#define MMA_BLOCK(acc, ntp, ah, al_, bh4, bl4) do { \
  mma_bf16(acc[0][2*(ntp)],     ah[0],  bh4);     \
  mma_bf16(acc[1][2*(ntp)],     ah[1],  bh4);     \
  mma_bf16(acc[0][2*(ntp) + 1], ah[0],  bh4 + 2); \
  mma_bf16(acc[1][2*(ntp) + 1], ah[1],  bh4 + 2); \
  mma_bf16(acc[0][2*(ntp)],     ah[0],  bl4);     \
  mma_bf16(acc[1][2*(ntp)],     ah[1],  bl4);     \
  mma_bf16(acc[0][2*(ntp) + 1], ah[0],  bl4 + 2); \
  mma_bf16(acc[1][2*(ntp) + 1], ah[1],  bl4 + 2); \
  mma_bf16(acc[0][2*(ntp)],     al_[0], bh4);     \
  mma_bf16(acc[1][2*(ntp)],     al_[1], bh4);     \
  mma_bf16(acc[0][2*(ntp) + 1], al_[0], bh4 + 2); \
  mma_bf16(acc[1][2*(ntp) + 1], al_[1], bh4 + 2); \
} while (0)
// 1-term (pure bf16): 4 MMAs
#define MMA_BLOCK1(acc, ntp, ah, bh4) do { \
  mma_bf16(acc[0][2*(ntp)],     ah[0],  bh4);     \
  mma_bf16(acc[1][2*(ntp)],     ah[1],  bh4);     \
  mma_bf16(acc[0][2*(ntp) + 1], ah[0],  bh4 + 2); \
  mma_bf16(acc[1][2*(ntp) + 1], ah[1],  bh4 + 2); \
} while (0)

__device__ __forceinline__ float wredf(float v) {
#pragma unroll
  for (int o = 16; o > 0; o >>= 1) v += __shfl_xor_sync(0xffffffffu, v, o);
  return v;
}
__device__ __forceinline__ unsigned short bfb(__nv_bfloat16 h) {
  return *reinterpret_cast<unsigned short*>(&h);
}
__device__ __forceinline__ void packhl(float v0, float v1, uint32_t& hi, uint32_t& lo) {
  __nv_bfloat16 h0 = __float2bfloat16(v0), h1 = __float2bfloat16(v1);
  __nv_bfloat16 l0 = __float2bfloat16(v0 - __bfloat162float(h0));
  __nv_bfloat16 l1 = __float2bfloat16(v1 - __bfloat162float(h1));
  hi = (uint32_t)bfb(h0) | ((uint32_t)bfb(h1) << 16);
  lo = (uint32_t)bfb(l0) | ((uint32_t)bfb(l1) << 16);
}
__device__ __forceinline__ uint32_t packh(float v0, float v1) {
  __nv_bfloat16 h0 = __float2bfloat16(v0), h1 = __float2bfloat16(v1);
  return (uint32_t)bfb(h0) | ((uint32_t)bfb(h1) << 16);
}
__device__ __forceinline__ float2 bf2f2(uint32_t u) {
  __nv_bfloat162 b = *reinterpret_cast<__nv_bfloat162*>(&u);
  return __bfloat1622float2(b);
}

// ---------------------------------------------------------------------------
__global__ void split_kernel(const float* __restrict__ src,
                             __nv_bfloat16* __restrict__ hi,
                             __nv_bfloat16* __restrict__ lo, int n) {
  int i = blockIdx.x * blockDim.x + threadIdx.x;
  if (i < n) {
    float x = src[i];
    __nv_bfloat16 h = __float2bfloat16(x);
    hi[i] = h;
    lo[i] = __float2bfloat16(x - __bfloat162float(h));
  }
}
__global__ void zero_kernel(float* p, int n) {
  int i = blockIdx.x * blockDim.x + threadIdx.x;
  if (i < n) p[i] = 0.f;
}

// dp[r] = q[r,:] . ks_sum   (bf16 q)
__global__ void __launch_bounds__(NTHR) dp_kernel(const __nv_bfloat16* __restrict__ Qh,
                                                  const float* __restrict__ scal,
                                                  float* __restrict__ dp) {
  int tid = threadIdx.x, w = tid >> 5, l = tid & 31;
  int rsub = l >> 3, cseg = l & 7;
  int r = blockIdx.x * 32 + w * 4 + rsub;
  float s = 0.f;
  if (r < NROWS) {
    const uint4* qh4 = (const uint4*)(Qh + (size_t)r * CH + cseg * 32);
    const float4* k4 = (const float4*)(scal + 4 + cseg * 32);
#pragma unroll
    for (int i = 0; i < 4; i++) {
      uint4 H = qh4[i];
      float4 ka = k4[2 * i], kb = k4[2 * i + 1];
      float2 h0 = bf2f2(H.x), h1 = bf2f2(H.y), h2 = bf2f2(H.z), h3 = bf2f2(H.w);
      s += h0.x * ka.x + h0.y * ka.y + h1.x * ka.z + h1.y * ka.w;
      s += h2.x * kb.x + h2.y * kb.y + h3.x * kb.z + h3.y * kb.w;
    }
  }
#pragma unroll
  for (int o = 4; o > 0; o >>= 1) s += __shfl_xor_sync(0xffffffffu, s, o);
  if (cseg == 0 && r < NROWS) dp[r] = s;
}

#define ACCV(jr, nt, c) acc[(jr) >> 1][nt][(((jr) & 1) << 1) + (c)]

// ---------------------------------------------------------------------------
// fused QKV GEMM: blockIdx.y selects {Q,K,V}. Q,K = 1-term bf16; V = 3-term.
// ---------------------------------------------------------------------------
__global__ void __launch_bounds__(NTHR, 2) gemm_qkv(
    const __nv_bfloat16* __restrict__ Ah, const __nv_bfloat16* __restrict__ Al,
    const __nv_bfloat16* __restrict__ WhB, const __nv_bfloat16* __restrict__ WlB,
    const float* __restrict__ bq, const float* __restrict__ bk, const float* __restrict__ bv,
    __nv_bfloat16* __restrict__ Qh,
    __nv_bfloat16* __restrict__ Kh,
    __nv_bfloat16* __restrict__ Vhh, __nv_bfloat16* __restrict__ Vll,
    float* __restrict__ scal)
{
  extern __shared__ char smem[];
  const uint32_t sb = smem_u32(smem);
  const int tid = threadIdx.x, w = tid >> 5, l = tid & 31;
  const int wrow = w >> 2, wcol = w & 3;
  const int m0 = blockIdx.x * TM;
  const int y = blockIdx.y;           // 0=Q 1=K 2=V
  const bool isQ = (y == 0), isK = (y == 1);
  const bool full = (y == 2);

  float* sCol = (float*)(smem + SCR + 2048);
  float* sRed = (float*)(smem + SCR + 3072);
  if (isK) sCol[tid] = 0.f;

  const __nv_bfloat16* Wh = WhB + (size_t)y * (CH * CH);
  const __nv_bfloat16* Wl = WlB + (size_t)y * (CH * CH);
  const float* bias = isQ ? bq : (isK ? bk : bv);
  __nv_bfloat16* Chi = isQ ? Qh : (isK ? Kh : Vhh);

  float acc[2][8][4];
#pragma unroll
  for (int a = 0; a < 2; a++)
#pragma unroll
    for (int b = 0; b < 8; b++)
#pragma unroll
      for (int c = 0; c < 4; c++) acc[a][b][c] = 0.f;

  auto issue = [&](int ch, int buf) {
    const uint32_t base = sb + buf * BUFB;
    const int k0 = ch * 32;
    {
      int row = tid >> 2, seg = tid & 3;
      int gr = m0 + row; if (gr > NROWS - 1) gr = NROWS - 1;
      size_t g = (size_t)gr * CH + k0 + seg * 8;
      uint32_t so = row * 80 + seg * 16;
      CP16(base + so, Ah + g);
      if (full) CP16(base + AB + so, Al + g);
    }
#pragma unroll
    for (int t = 0; t < 4; t++) {
      int idx = tid + t * 256;
      int row = idx >> 2, seg = idx & 3;
      size_t g = (size_t)row * CH + k0 + seg * 8;
      uint32_t so = row * 80 + seg * 16;
      CP16(base + 2 * AB + so, Wh + g);
      if (full) CP16(base + 2 * AB + WB + so, Wl + g);
    }
  };

  issue(0, 0); CP_COMMIT();
#pragma unroll
  for (int ch = 0; ch < 8; ch++) {
    if (ch < 7) { issue(ch + 1, (ch + 1) & 1); CP_COMMIT(); CP_WAIT(1); }
    else CP_WAIT(0);
    __syncthreads();
    const uint32_t base = sb + (ch & 1) * BUFB;
#pragma unroll
    for (int kt = 0; kt < 2; kt++) {
      uint32_t ah[2][4], al_[2][4];
#pragma unroll
      for (int mt = 0; mt < 2; mt++) {
        int row = wrow * 32 + mt * 16 + (l & 15);
        int col = kt * 16 + ((l >> 4) << 3);
        uint32_t off = row * 80 + col * 2;
        ldm_x4(ah[mt], base + off);
        if (full) ldm_x4(al_[mt], base + AB + off);
      }
#pragma unroll
      for (int ntp = 0; ntp < 4; ntp++) {
        int n = wcol * 64 + ntp * 16 + ((l >> 4) << 3) + (l & 7);
        int col = kt * 16 + ((l >> 3) & 1) * 8;
        uint32_t off = n * 80 + col * 2;
        uint32_t bh4[4], bl4[4];
        ldm_x4(bh4, base + 2 * AB + off);
        if (full) {
          ldm_x4(bl4, base + 2 * AB + WB + off);
          MMA_BLOCK(acc, ntp, ah, al_, bh4, bl4);
        } else {
          MMA_BLOCK1(acc, ntp, ah, bh4);
        }
      }
    }
    __syncthreads();
  }

  // epilogue
  const int qlane = l >> 2;
  const int cbase = wcol * 64 + (l & 3) * 2;
  float nrm = 0.f;
#pragma unroll
  for (int nt = 0; nt < 8; nt++) {
    const int col = cbase + nt * 8;
    float2 bs = *(const float2*)(bias + col);
    float cs0 = 0.f, cs1 = 0.f;
#pragma unroll
    for (int jr = 0; jr < 4; jr++) {
      int r = m0 + wrow * 32 + (jr >> 1) * 16 + (jr & 1) * 8 + qlane;
      bool valid = r < NROWS;
      float v0 = ACCV(jr, nt, 0) + bs.x;
      float v1 = ACCV(jr, nt, 1) + bs.y;
      if (valid) {
        if (y < 2) nrm = fmaf(v0, v0, fmaf(v1, v1, nrm));
        if (isK) { cs0 += v0; cs1 += v1; }
        if (full) {
          uint32_t hi, lo;
          packhl(v0, v1, hi, lo);
          *(uint32_t*)(Chi + (size_t)r * CH + col) = hi;
          *(uint32_t*)(Vll + (size_t)r * CH + col) = lo;
        } else {
          *(uint32_t*)(Chi + (size_t)r * CH + col) = packh(v0, v1);
        }
      }
    }
    if (isK) {
#pragma unroll
      for (int o = 4; o < 32; o <<= 1) {
        cs0 += __shfl_xor_sync(0xffffffffu, cs0, o);
        cs1 += __shfl_xor_sync(0xffffffffu, cs1, o);
      }
      if (qlane == 0) { atomicAdd(&sCol[col], cs0); atomicAdd(&sCol[col + 1], cs1); }
    }
  }
  if (y < 2) {
    float p = wredf(nrm);
    if (l == 0) sRed[w] = p;
    __syncthreads();
    if (tid == 0) {
      float s = 0.f;
#pragma unroll
      for (int i = 0; i < 8; i++) s += sRed[i];
      atomicAdd(scal + (isQ ? 0 : 1), s);
    }
    if (isK) atomicAdd(&scal[4 + tid], sCol[tid]);
  }
}

// ---------------------------------------------------------------------------
// gemm_mma: EPI_LN (fc, 3-term) and EPI_ATTN (q@KVS, 1-term)
// ---------------------------------------------------------------------------
#define EPI_LN   0
#define EPI_ATTN 4

template<int EPI, bool FULL>
__global__ void __launch_bounds__(NTHR, 2) gemm_mma(
    const __nv_bfloat16* __restrict__ Ah, const __nv_bfloat16* __restrict__ Al,
    const __nv_bfloat16* __restrict__ Wh, const __nv_bfloat16* __restrict__ Wl,
    const float* __restrict__ bias,
    float* __restrict__ Cf, __nv_bfloat16* __restrict__ Chi, __nv_bfloat16* __restrict__ Clo,
    const float* __restrict__ gamma, const float* __restrict__ beta,
    const float* __restrict__ scal, const float* __restrict__ dpv,
    const __nv_bfloat16* __restrict__ Vh, const __nv_bfloat16* __restrict__ Vl,
    const __nv_bfloat16* __restrict__ Ph, const __nv_bfloat16* __restrict__ Pl)
{
  extern __shared__ char smem[];
  const uint32_t sb = smem_u32(smem);
  const int tid = threadIdx.x, w = tid >> 5, l = tid & 31;
  const int wrow = w >> 2, wcol = w & 3;
  const int m0 = blockIdx.x * TM;

  float* sS1 = (float*)(smem + SCR);
  float* sS2 = (float*)(smem + SCR + 1024);

  float acc[2][8][4];
#pragma unroll
  for (int a = 0; a < 2; a++)
#pragma unroll
    for (int b = 0; b < 8; b++)
#pragma unroll
      for (int c = 0; c < 4; c++) acc[a][b][c] = 0.f;

  auto issue = [&](int ch, int buf) {
    const uint32_t base = sb + buf * BUFB;
    const int k0 = ch * 32;
    {
      int row = tid >> 2, seg = tid & 3;
      int gr = m0 + row; if (gr > NROWS - 1) gr = NROWS - 1;
      size_t g = (size_t)gr * CH + k0 + seg * 8;
      uint32_t so = row * 80 + seg * 16;
      CP16(base + so, Ah + g);
      if (FULL) CP16(base + AB + so, Al + g);
    }
#pragma unroll
    for (int t = 0; t < 4; t++) {
      int idx = tid + t * 256;
      int row = idx >> 2, seg = idx & 3;
      size_t g = (size_t)row * CH + k0 + seg * 8;
      uint32_t so = row * 80 + seg * 16;
      CP16(base + 2 * AB + so, Wh + g);
      if (FULL) CP16(base + 2 * AB + WB + so, Wl + g);
    }
  };

  issue(0, 0); CP_COMMIT();
#pragma unroll
  for (int ch = 0; ch < 8; ch++) {
    if (ch < 7) { issue(ch + 1, (ch + 1) & 1); CP_COMMIT(); CP_WAIT(1); }
    else CP_WAIT(0);
    __syncthreads();
    const uint32_t base = sb + (ch & 1) * BUFB;
#pragma unroll
    for (int kt = 0; kt < 2; kt++) {
      uint32_t ah[2][4], al_[2][4];
#pragma unroll
      for (int mt = 0; mt < 2; mt++) {
        int row = wrow * 32 + mt * 16 + (l & 15);
        int col = kt * 16 + ((l >> 4) << 3);
        uint32_t off = row * 80 + col * 2;
        ldm_x4(ah[mt], base + off);
        if (FULL) ldm_x4(al_[mt], base + AB + off);
      }
#pragma unroll
      for (int ntp = 0; ntp < 4; ntp++) {
        int n = wcol * 64 + ntp * 16 + ((l >> 4) << 3) + (l & 7);
        int col = kt * 16 + ((l >> 3) & 1) * 8;
        uint32_t off = n * 80 + col * 2;
        uint32_t bh4[4], bl4[4];
        ldm_x4(bh4, base + 2 * AB + off);
        if (FULL) {
          ldm_x4(bl4, base + 2 * AB + WB + off);
          MMA_BLOCK(acc, ntp, ah, al_, bh4, bl4);
        } else {
          MMA_BLOCK1(acc, ntp, ah, bh4);
        }
      }
    }
    __syncthreads();
  }

  // epilogue: transform -> row stats -> LN+ReLU
  const int qlane = l >> 2;
  const int cbase = wcol * 64 + (l & 3) * 2;
  const float nF = (float)NROWS;
  float cN = 0.f;
  if (EPI == EPI_ATTN) cN = rsqrtf(scal[0] * scal[1]);
#pragma unroll
  for (int jr = 0; jr < 4; jr++) {
    const int lrow = wrow * 32 + (jr >> 1) * 16 + (jr & 1) * 8 + qlane;
    const int r = m0 + lrow;
    const bool valid = r < NROWS;
    float invr = 0.f;
    if (EPI == EPI_ATTN) invr = 1.f / fmaf(cN, valid ? dpv[r] : 0.f, nF);
    float s1 = 0.f, s2 = 0.f;
#pragma unroll
    for (int nt = 0; nt < 8; nt++) {
      const int col = cbase + nt * 8;
      if (EPI == EPI_LN) {
        float2 bs = *(const float2*)(bias + col);
        float y0 = ACCV(jr, nt, 0) + bs.x;
        float y1 = ACCV(jr, nt, 1) + bs.y;
        ACCV(jr, nt, 0) = y0; ACCV(jr, nt, 1) = y1;
        s1 += y0 + y1; s2 = fmaf(y0, y0, fmaf(y1, y1, s2));
      } else {
        uint32_t uvh = 0, uvl = 0, uph = 0, upl = 0;
        if (valid) {
          uvh = *(const uint32_t*)(Vh + (size_t)r * CH + col);
          uvl = *(const uint32_t*)(Vl + (size_t)r * CH + col);
          uph = *(const uint32_t*)(Ph + (size_t)r * CH + col);
          upl = *(const uint32_t*)(Pl + (size_t)r * CH + col);
        }
        float2 a0 = bf2f2(uvh), a1 = bf2f2(uvl);
        float2 b0 = bf2f2(uph), b1 = bf2f2(upl);
        float vvx = a0.x + a1.x, vvy = a0.y + a1.y;
        float ppx = b0.x + b1.x, ppy = b0.y + b1.y;
        float h0 = 0.5f * (fmaf(cN, ACCV(jr, nt, 0), nF * vvx) * invr + ppx);
        float h1 = 0.5f * (fmaf(cN, ACCV(jr, nt, 1), nF * vvy) * invr + ppy);
        ACCV(jr, nt, 0) = h0; ACCV(jr, nt, 1) = h1;
        s1 += h0 + h1; s2 = fmaf(h0, h0, fmaf(h1, h1, s2));
      }
    }
#pragma unroll
    for (int o = 1; o < 4; o <<= 1) {
      s1 += __shfl_xor_sync(0xffffffffu, s1, o);
      s2 += __shfl_xor_sync(0xffffffffu, s2, o);
    }
    if ((l & 3) == 0) { sS1[wcol * 64 + lrow] = s1; sS2[wcol * 64 + lrow] = s2; }
  }
  __syncthreads();
#pragma unroll
  for (int jr = 0; jr < 4; jr++) {
    const int lrow = wrow * 32 + (jr >> 1) * 16 + (jr & 1) * 8 + qlane;
    const int r = m0 + lrow;
    const bool valid = r < NROWS;
    const float s1 = sS1[lrow] + sS1[64 + lrow] + sS1[128 + lrow] + sS1[192 + lrow];
    const float s2 = sS2[lrow] + sS2[64 + lrow] + sS2[128 + lrow] + sS2[192 + lrow];
    const float mu = s1 * (1.f / CH);
    const float rs = rsqrtf(s2 * (1.f / CH) - mu * mu + 1e-5f);
#pragma unroll
    for (int nt = 0; nt < 8; nt++) {
      const int col = cbase + nt * 8;
      float2 gg = *(const float2*)(gamma + col);
      float2 bb = *(const float2*)(beta + col);
      float o0 = fmaxf((ACCV(jr, nt, 0) - mu) * rs * gg.x + bb.x, 0.f);
      float o1 = fmaxf((ACCV(jr, nt, 1) - mu) * rs * gg.y + bb.y, 0.f);
      if (valid) {
        if (Cf) *(float2*)(Cf + (size_t)r * CH + col) = make_float2(o0, o1);
        if (Chi) {
          uint32_t hi, lo;
          packhl(o0, o1, hi, lo);
          *(uint32_t*)(Chi + (size_t)r * CH + col) = hi;
          *(uint32_t*)(Clo + (size_t)r * CH + col) = lo;
        }
      }
    }
  }
}

// ---------------------------------------------------------------------------
// MMA kvs (1-term bf16): part[s][m][d] quarters (m 128 x d 128).
// ---------------------------------------------------------------------------
__global__ void __launch_bounds__(NTHR, 2) gemm_kvs(
    const __nv_bfloat16* __restrict__ Kh,
    const __nv_bfloat16* __restrict__ Vh,
    float* __restrict__ part)
{
  extern __shared__ char smem[];
  const uint32_t sb = smem_u32(smem);
  const int tid = threadIdx.x, w = tid >> 5, l = tid & 31;
  const int wrow = w >> 1, wcol = w & 1;
  const int m0 = blockIdx.x * 128;
  const int d0g = blockIdx.y * 128;
  const int n0 = blockIdx.z * (SLICE_CHUNKS * 32);

  float acc[2][8][4];
#pragma unroll
  for (int a = 0; a < 2; a++)
#pragma unroll
    for (int b = 0; b < 8; b++)
#pragma unroll
      for (int c = 0; c < 4; c++) acc[a][b][c] = 0.f;

  auto issue = [&](int ch, int buf) {
    const uint32_t base = sb + buf * KBUF;
    const int nb = n0 + ch * 32;
#pragma unroll
    for (int t = 0; t < 2; t++) {
      int idx = tid + t * 256;
      int row = idx >> 4, seg = idx & 15;
      int gn = nb + row;
      uint32_t vb = (gn < NROWS) ? 16u : 0u;
      if (gn > NROWS - 1) gn = NROWS - 1;
      uint32_t so = row * KA_STR + seg * 16;
      size_t gk = (size_t)gn * CH + m0 + seg * 8;
      size_t gv = (size_t)gn * CH + d0g + seg * 8;
      CP16Z(base + so, Kh + gk, vb);
      CP16Z(base + KAB + so, Vh + gv, vb);
    }
  };

  issue(0, 0); CP_COMMIT();
  issue(1, 1); CP_COMMIT();
  for (int ch = 0; ch < SLICE_CHUNKS; ch++) {
    if (ch + 1 < SLICE_CHUNKS) CP_WAIT(1); else CP_WAIT(0);
    __syncthreads();
    if (ch + 2 < SLICE_CHUNKS) { issue(ch + 2, (ch + 2) % 3); CP_COMMIT(); }
    const uint32_t base = sb + (ch % 3) * KBUF;
#pragma unroll
    for (int kt = 0; kt < 2; kt++) {
      const int k0 = kt * 16;
      uint32_t ah[2][4];
#pragma unroll
      for (int mt = 0; mt < 2; mt++) {
        int krow = k0 + (l & 7) + ((l >> 4) << 3);
        int mcol = wrow * 32 + mt * 16 + ((l >> 3) & 1) * 8;
        uint32_t off = krow * KA_STR + mcol * 2;
        ldm_x4t(ah[mt], base + off);
      }
#pragma unroll
      for (int ntp = 0; ntp < 4; ntp++) {
        int dd = wcol * 64 + ntp * 16 + ((l >> 4) << 3);
        int krow = k0 + (l & 7) + ((l >> 3) & 1) * 8;
        uint32_t off = krow * KA_STR + dd * 2;
        uint32_t bh4[4];
        ldm_x4t(bh4, base + KAB + off);
        MMA_BLOCK1(acc, ntp, ah, bh4);
      }
    }
    __syncthreads();
  }

  float* dst = part + (size_t)blockIdx.z * (CH * CH);
  const int qlane = l >> 2;
  const int cbase = wcol * 64 + (l & 3) * 2;
#pragma unroll
  for (int jr = 0; jr < 4; jr++) {
    int m = m0 + wrow * 32 + (jr >> 1) * 16 + (jr & 1) * 8 + qlane;
#pragma unroll
    for (int nt = 0; nt < 8; nt++) {
      int d = d0g + cbase + nt * 8;
      *(float2*)(dst + (size_t)m * CH + d) = make_float2(ACCV(jr, nt, 0), ACCV(jr, nt, 1));
    }
  }
}

// sum slices; write TRANSPOSED hi bf16
__global__ void kvs_reduce(const float* __restrict__ part,
                           __nv_bfloat16* __restrict__ bth) {
  int idx = blockIdx.x * blockDim.x + threadIdx.x;
  if (idx < CH * CH) {
    int m = idx >> 8, d = idx & 255;
    float s = 0.f;
#pragma unroll
    for (int ss = 0; ss < NSLICE; ss++) s += part[(size_t)ss * CH * CH + idx];
    bth[d * CH + m] = __float2bfloat16(s);
  }
}

// ---------------------------------------------------------------------------
extern "C" void kernel_launch(void* const* d_in, const int* in_sizes, int n_in,
                              void* d_out, int out_size) {
  (void)in_sizes; (void)n_in; (void)out_size;
  const float* x    = (const float*)d_in[0];
  const float* fc_w = (const float*)d_in[1];
  const float* fc_b = (const float*)d_in[2];
  const float* Wq_w = (const float*)d_in[3];
  const float* Wq_b = (const float*)d_in[4];
  const float* Wk_w = (const float*)d_in[5];
  const float* Wk_b = (const float*)d_in[6];
  const float* Wv_w = (const float*)d_in[7];
  const float* Wv_b = (const float*)d_in[8];
  const float* ln_g = (const float*)d_in[9];
  const float* ln_b = (const float*)d_in[10];
  float* out = (float*)d_out;

  float *part, *scal, *dp;
  __nv_bfloat16 *xh, *xl, *ahh, *ahl, *bhh, *bhl, *qh, *kh, *vh, *vl, *wh, *wl, *bth;
  cudaGetSymbolAddress((void**)&part, g_part);
  cudaGetSymbolAddress((void**)&scal, g_scal);
  cudaGetSymbolAddress((void**)&dp, g_dp);
  cudaGetSymbolAddress((void**)&xh, g_xh);  cudaGetSymbolAddress((void**)&xl, g_xl);
  cudaGetSymbolAddress((void**)&ahh, g_ahh); cudaGetSymbolAddress((void**)&ahl, g_ahl);
  cudaGetSymbolAddress((void**)&bhh, g_bhh); cudaGetSymbolAddress((void**)&bhl, g_bhl);
  cudaGetSymbolAddress((void**)&qh, g_qh);
  cudaGetSymbolAddress((void**)&kh, g_kh);
  cudaGetSymbolAddress((void**)&vh, g_vh);  cudaGetSymbolAddress((void**)&vl, g_vl);
  cudaGetSymbolAddress((void**)&wh, g_wh);  cudaGetSymbolAddress((void**)&wl, g_wl);
  cudaGetSymbolAddress((void**)&bth, g_bth);

  cudaFuncSetAttribute(gemm_mma<EPI_LN, true>,    cudaFuncAttributeMaxDynamicSharedMemorySize, SMEM_SZ);
  cudaFuncSetAttribute(gemm_mma<EPI_ATTN, false>, cudaFuncAttributeMaxDynamicSharedMemorySize, SMEM_SZ);
  cudaFuncSetAttribute(gemm_qkv, cudaFuncAttributeMaxDynamicSharedMemorySize, SMEM_SZ);
  cudaFuncSetAttribute(gemm_kvs, cudaFuncAttributeMaxDynamicSharedMemorySize, KSMEM);

  const int WSZ = CH * CH;
  split_kernel<<<WSZ / 256, 256>>>(fc_w, wh, wl, WSZ);
  split_kernel<<<(NROWS * CH + 255) / 256, 256>>>(x, xh, xl, NROWS * CH);
  split_kernel<<<WSZ / 256, 256>>>(Wq_w, wh + 1 * WSZ, wl + 1 * WSZ, WSZ);

  gemm_mma<EPI_LN, true><<<TGRID, NTHR, SMEM_SZ>>>(
      xh, xl, wh, wl, fc_b, nullptr, ahh, ahl, ln_g, ln_b,
      nullptr, nullptr, nullptr, nullptr, nullptr, nullptr);

  split_kernel<<<WSZ / 256, 256>>>(Wk_w, wh + 2 * WSZ, wl + 2 * WSZ, WSZ);
  split_kernel<<<WSZ / 256, 256>>>(Wv_w, wh + 3 * WSZ, wl + 3 * WSZ, WSZ);

  for (int L = 0; L < 2; L++) {
    if (L == 1) {
      split_kernel<<<WSZ / 256, 256>>>(Wq_w + (size_t)WSZ, wh + 4 * WSZ, wl + 4 * WSZ, WSZ);
      split_kernel<<<WSZ / 256, 256>>>(Wk_w + (size_t)WSZ, wh + 5 * WSZ, wl + 5 * WSZ, WSZ);
      split_kernel<<<WSZ / 256, 256>>>(Wv_w + (size_t)WSZ, wh + 6 * WSZ, wl + 6 * WSZ, WSZ);
    }
    const __nv_bfloat16* hh = L ? bhh : ahh;
    const __nv_bfloat16* hl = L ? bhl : ahl;
    float* ob = L ? out : nullptr;
    __nv_bfloat16* obh = L ? nullptr : bhh;
    __nv_bfloat16* obl = L ? nullptr : bhl;
    const size_t bo = (size_t)L * CH;
    const int wo = (L ? 4 : 1);

    zero_kernel<<<1, CH + 4>>>(scal, CH + 4);
    gemm_qkv<<<dim3(TGRID, 3), NTHR, SMEM_SZ>>>(
        hh, hl, wh + (size_t)wo * WSZ, wl + (size_t)wo * WSZ,
        Wq_b + bo, Wk_b + bo, Wv_b + bo,
        qh, kh, vh, vl, scal);
    dp_kernel<<<(NROWS + 31) / 32, NTHR>>>(qh, scal, dp);
    gemm_kvs<<<dim3(2, 2, NSLICE), NTHR, KSMEM>>>(kh, vh, part);
    kvs_reduce<<<64, 1024>>>(part, bth);
    gemm_mma<EPI_ATTN, false><<<TGRID, NTHR, SMEM_SZ>>>(
        qh, nullptr, bth, nullptr, nullptr, ob, obh, obl,
        ln_g + (size_t)(L + 1) * CH, ln_b + (size_t)(L + 1) * CH,
        scal, dp, vh, vl, hh, hl);
  }
}

// round 16
// speedup vs baseline: 4.1196x; 1.0498x over previous
#include <cuda_runtime.h>
#include <cuda_bf16.h>
#include <cstdint>

#define NROWS 100000
#define CH 256
#define NTHR 256
// ---- MMA gemm params (BM=64 x BN=256, occ 2) ----
#define TM 64
#define TGRID ((NROWS + TM - 1) / TM)   // 1563
#define AB (64 * 80)
#define WB (256 * 80)
#define BUFB (2 * AB + 2 * WB)
#define SCR (2 * BUFB)
#define SMEM_SZ (SCR + 4096)
// ---- kvs MMA params (1-term) ----
#define NSLICE 74
#define SLICE_CHUNKS 43
#define KA_STR 272
#define KAB (32 * KA_STR)
#define KBUF (2 * KAB)
#define KSMEM (3 * KBUF)

// ---------------- scratch -----------------------------------------------------
__device__ __nv_bfloat16 g_part[(size_t)NSLICE * CH * CH];
__device__ float g_scal[CH + 4];
__device__ __nv_bfloat16 g_xh[(size_t)NROWS * CH], g_xl[(size_t)NROWS * CH];
__device__ __nv_bfloat16 g_ahh[(size_t)NROWS * CH], g_ahl[(size_t)NROWS * CH];
__device__ __nv_bfloat16 g_bhh[(size_t)NROWS * CH], g_bhl[(size_t)NROWS * CH];
__device__ __nv_bfloat16 g_qh[(size_t)NROWS * CH];
__device__ __nv_bfloat16 g_kh[(size_t)NROWS * CH];
__device__ __nv_bfloat16 g_vh[(size_t)NROWS * CH], g_vl[(size_t)NROWS * CH];
__device__ __nv_bfloat16 g_wh[7 * 65536], g_wl[7 * 65536];
__device__ __nv_bfloat16 g_bth[65536];

// ---------------- helpers ------------------------------------------------------
__device__ __forceinline__ uint32_t smem_u32(const void* p) {
  uint32_t a;
  asm("{ .reg .u64 t; cvta.to.shared.u64 t, %1; cvt.u32.u64 %0, t; }" : "=r"(a) : "l"(p));
  return a;
}
#define CP16(dst, src) \
  asm volatile("cp.async.cg.shared.global [%0], [%1], 16;" :: "r"(dst), "l"(src))
#define CP16Z(dst, src, vb) \
  asm volatile("cp.async.cg.shared.global [%0], [%1], 16, %2;" :: "r"(dst), "l"(src), "r"(vb))
#define CP_COMMIT() asm volatile("cp.async.commit_group;" ::: "memory")
#define CP_WAIT(n) asm volatile("cp.async.wait_group %0;" :: "n"(n) : "memory")

__device__ __forceinline__ void ldm_x4(uint32_t* r, uint32_t addr) {
  asm volatile("ldmatrix.sync.aligned.m8n8.x4.shared.b16 {%0,%1,%2,%3}, [%4];"
               : "=r"(r[0]), "=r"(r[1]), "=r"(r[2]), "=r"(r[3]) : "r"(addr));
}
__device__ __forceinline__ void ldm_x4t(uint32_t* r, uint32_t addr) {
  asm volatile("ldmatrix.sync.aligned.m8n8.x4.trans.shared.b16 {%0,%1,%2,%3}, [%4];"
               : "=r"(r[0]), "=r"(r[1]), "=r"(r[2]), "=r"(r[3]) : "r"(addr));
}
__device__ __forceinline__ void mma_bf16(float* c, const uint32_t* a, const uint32_t* b) {
  asm volatile(
      "mma.sync.aligned.m16n8k16.row.col.f32.bf16.bf16.f32 "
      "{%0,%1,%2,%3}, {%4,%5,%6,%7}, {%8,%9}, {%0,%1,%2,%3};"
      : "+f"(c[0]), "+f"(c[1]), "+f"(c[2]), "+f"(c[3])
      : "r"(a[0]), "r"(a[1]), "r"(a[2]), "r"(a[3]), "r"(b[0]), "r"(b[1]));
}
#define MMA_BLOCK(acc, ntp, ah, al_, bh4, bl4) do { \
  mma_bf16(acc[0][2*(ntp)],     ah[0],  bh4);     \
  mma_bf16(acc[1][2*(ntp)],     ah[1],  bh4);     \
  mma_bf16(acc[0][2*(ntp) + 1], ah[0],  bh4 + 2); \
  mma_bf16(acc[1][2*(ntp) + 1], ah[1],  bh4 + 2); \
  mma_bf16(acc[0][2*(ntp)],     ah[0],  bl4);     \
  mma_bf16(acc[1][2*(ntp)],     ah[1],  bl4);     \
  mma_bf16(acc[0][2*(ntp) + 1], ah[0],  bl4 + 2); \
  mma_bf16(acc[1][2*(ntp) + 1], ah[1],  bl4 + 2); \
  mma_bf16(acc[0][2*(ntp)],     al_[0], bh4);     \
  mma_bf16(acc[1][2*(ntp)],     al_[1], bh4);     \
  mma_bf16(acc[0][2*(ntp) + 1], al_[0], bh4 + 2); \
  mma_bf16(acc[1][2*(ntp) + 1], al_[1], bh4 + 2); \
} while (0)
#define MMA_BLOCK1(acc, ntp, ah, bh4) do { \
  mma_bf16(acc[0][2*(ntp)],     ah[0],  bh4);     \
  mma_bf16(acc[1][2*(ntp)],     ah[1],  bh4);     \
  mma_bf16(acc[0][2*(ntp) + 1], ah[0],  bh4 + 2); \
  mma_bf16(acc[1][2*(ntp) + 1], ah[1],  bh4 + 2); \
} while (0)

__device__ __forceinline__ float wredf(float v) {
#pragma unroll
  for (int o = 16; o > 0; o >>= 1) v += __shfl_xor_sync(0xffffffffu, v, o);
  return v;
}
__device__ __forceinline__ unsigned short bfb(__nv_bfloat16 h) {
  return *reinterpret_cast<unsigned short*>(&h);
}
__device__ __forceinline__ void packhl(float v0, float v1, uint32_t& hi, uint32_t& lo) {
  __nv_bfloat16 h0 = __float2bfloat16(v0), h1 = __float2bfloat16(v1);
  __nv_bfloat16 l0 = __float2bfloat16(v0 - __bfloat162float(h0));
  __nv_bfloat16 l1 = __float2bfloat16(v1 - __bfloat162float(h1));
  hi = (uint32_t)bfb(h0) | ((uint32_t)bfb(h1) << 16);
  lo = (uint32_t)bfb(l0) | ((uint32_t)bfb(l1) << 16);
}
__device__ __forceinline__ uint32_t packh(float v0, float v1) {
  __nv_bfloat16 h0 = __float2bfloat16(v0), h1 = __float2bfloat16(v1);
  return (uint32_t)bfb(h0) | ((uint32_t)bfb(h1) << 16);
}
__device__ __forceinline__ float2 bf2f2(uint32_t u) {
  __nv_bfloat162 b = *reinterpret_cast<__nv_bfloat162*>(&u);
  return __bfloat1622float2(b);
}

// ---------------------------------------------------------------------------
__global__ void split_kernel(const float* __restrict__ src,
                             __nv_bfloat16* __restrict__ hi,
                             __nv_bfloat16* __restrict__ lo, int n) {
  int i = blockIdx.x * blockDim.x + threadIdx.x;
  if (i < n) {
    float x = src[i];
    __nv_bfloat16 h = __float2bfloat16(x);
    hi[i] = h;
    lo[i] = __float2bfloat16(x - __bfloat162float(h));
  }
}
// one launch splits all 7 weight matrices; y selects the source
__global__ void split7_kernel(const float* __restrict__ fcw,
                              const float* __restrict__ Wq,
                              const float* __restrict__ Wk,
                              const float* __restrict__ Wv,
                              __nv_bfloat16* __restrict__ wh,
                              __nv_bfloat16* __restrict__ wl) {
  const int WSZ = CH * CH;
  int y = blockIdx.y;
  const float* src;
  switch (y) {
    case 0: src = fcw; break;
    case 1: src = Wq; break;
    case 2: src = Wk; break;
    case 3: src = Wv; break;
    case 4: src = Wq + WSZ; break;
    case 5: src = Wk + WSZ; break;
    default: src = Wv + WSZ; break;
  }
  int i = blockIdx.x * blockDim.x + threadIdx.x;
  float x = src[i];
  __nv_bfloat16 h = __float2bfloat16(x);
  wh[(size_t)y * WSZ + i] = h;
  wl[(size_t)y * WSZ + i] = __float2bfloat16(x - __bfloat162float(h));
}
__global__ void zero_kernel(float* p, int n) {
  int i = blockIdx.x * blockDim.x + threadIdx.x;
  if (i < n) p[i] = 0.f;
}

#define ACCV(jr, nt, c) acc[(jr) >> 1][nt][(((jr) & 1) << 1) + (c)]

// ---------------------------------------------------------------------------
// fused QKV GEMM: blockIdx.y selects {Q,K,V}. Q,K = 1-term bf16; V = 3-term.
// ---------------------------------------------------------------------------
__global__ void __launch_bounds__(NTHR, 2) gemm_qkv(
    const __nv_bfloat16* __restrict__ Ah, const __nv_bfloat16* __restrict__ Al,
    const __nv_bfloat16* __restrict__ WhB, const __nv_bfloat16* __restrict__ WlB,
    const float* __restrict__ bq, const float* __restrict__ bk, const float* __restrict__ bv,
    __nv_bfloat16* __restrict__ Qh,
    __nv_bfloat16* __restrict__ Kh,
    __nv_bfloat16* __restrict__ Vhh, __nv_bfloat16* __restrict__ Vll,
    float* __restrict__ scal)
{
  extern __shared__ char smem[];
  const uint32_t sb = smem_u32(smem);
  const int tid = threadIdx.x, w = tid >> 5, l = tid & 31;
  const int wrow = w >> 2, wcol = w & 3;
  const int m0 = blockIdx.x * TM;
  const int y = blockIdx.y;           // 0=Q 1=K 2=V
  const bool isQ = (y == 0), isK = (y == 1);
  const bool full = (y == 2);

  float* sCol = (float*)(smem + SCR + 2048);
  float* sRed = (float*)(smem + SCR + 3072);
  if (isK) sCol[tid] = 0.f;

  const __nv_bfloat16* Wh = WhB + (size_t)y * (CH * CH);
  const __nv_bfloat16* Wl = WlB + (size_t)y * (CH * CH);
  const float* bias = isQ ? bq : (isK ? bk : bv);
  __nv_bfloat16* Chi = isQ ? Qh : (isK ? Kh : Vhh);

  float acc[2][8][4];
#pragma unroll
  for (int a = 0; a < 2; a++)
#pragma unroll
    for (int b = 0; b < 8; b++)
#pragma unroll
      for (int c = 0; c < 4; c++) acc[a][b][c] = 0.f;

  auto issue = [&](int ch, int buf) {
    const uint32_t base = sb + buf * BUFB;
    const int k0 = ch * 32;
    {
      int row = tid >> 2, seg = tid & 3;
      int gr = m0 + row; if (gr > NROWS - 1) gr = NROWS - 1;
      size_t g = (size_t)gr * CH + k0 + seg * 8;
      uint32_t so = row * 80 + seg * 16;
      CP16(base + so, Ah + g);
      if (full) CP16(base + AB + so, Al + g);
    }
#pragma unroll
    for (int t = 0; t < 4; t++) {
      int idx = tid + t * 256;
      int row = idx >> 2, seg = idx & 3;
      size_t g = (size_t)row * CH + k0 + seg * 8;
      uint32_t so = row * 80 + seg * 16;
      CP16(base + 2 * AB + so, Wh + g);
      if (full) CP16(base + 2 * AB + WB + so, Wl + g);
    }
  };

  issue(0, 0); CP_COMMIT();
#pragma unroll
  for (int ch = 0; ch < 8; ch++) {
    if (ch < 7) { issue(ch + 1, (ch + 1) & 1); CP_COMMIT(); CP_WAIT(1); }
    else CP_WAIT(0);
    __syncthreads();
    const uint32_t base = sb + (ch & 1) * BUFB;
#pragma unroll
    for (int kt = 0; kt < 2; kt++) {
      uint32_t ah[2][4], al_[2][4];
#pragma unroll
      for (int mt = 0; mt < 2; mt++) {
        int row = wrow * 32 + mt * 16 + (l & 15);
        int col = kt * 16 + ((l >> 4) << 3);
        uint32_t off = row * 80 + col * 2;
        ldm_x4(ah[mt], base + off);
        if (full) ldm_x4(al_[mt], base + AB + off);
      }
#pragma unroll
      for (int ntp = 0; ntp < 4; ntp++) {
        int n = wcol * 64 + ntp * 16 + ((l >> 4) << 3) + (l & 7);
        int col = kt * 16 + ((l >> 3) & 1) * 8;
        uint32_t off = n * 80 + col * 2;
        uint32_t bh4[4], bl4[4];
        ldm_x4(bh4, base + 2 * AB + off);
        if (full) {
          ldm_x4(bl4, base + 2 * AB + WB + off);
          MMA_BLOCK(acc, ntp, ah, al_, bh4, bl4);
        } else {
          MMA_BLOCK1(acc, ntp, ah, bh4);
        }
      }
    }
    __syncthreads();
  }

  // epilogue
  const int qlane = l >> 2;
  const int cbase = wcol * 64 + (l & 3) * 2;
  float nrm = 0.f;
#pragma unroll
  for (int nt = 0; nt < 8; nt++) {
    const int col = cbase + nt * 8;
    float2 bs = *(const float2*)(bias + col);
    float cs0 = 0.f, cs1 = 0.f;
#pragma unroll
    for (int jr = 0; jr < 4; jr++) {
      int r = m0 + wrow * 32 + (jr >> 1) * 16 + (jr & 1) * 8 + qlane;
      bool valid = r < NROWS;
      float v0 = ACCV(jr, nt, 0) + bs.x;
      float v1 = ACCV(jr, nt, 1) + bs.y;
      if (valid) {
        if (y < 2) nrm = fmaf(v0, v0, fmaf(v1, v1, nrm));
        if (isK) { cs0 += v0; cs1 += v1; }
        if (full) {
          uint32_t hi, lo;
          packhl(v0, v1, hi, lo);
          *(uint32_t*)(Chi + (size_t)r * CH + col) = hi;
          *(uint32_t*)(Vll + (size_t)r * CH + col) = lo;
        } else {
          *(uint32_t*)(Chi + (size_t)r * CH + col) = packh(v0, v1);
        }
      }
    }
    if (isK) {
#pragma unroll
      for (int o = 4; o < 32; o <<= 1) {
        cs0 += __shfl_xor_sync(0xffffffffu, cs0, o);
        cs1 += __shfl_xor_sync(0xffffffffu, cs1, o);
      }
      if (qlane == 0) { atomicAdd(&sCol[col], cs0); atomicAdd(&sCol[col + 1], cs1); }
    }
  }
  if (y < 2) {
    float p = wredf(nrm);
    if (l == 0) sRed[w] = p;
    __syncthreads();
    if (tid == 0) {
      float s = 0.f;
#pragma unroll
      for (int i = 0; i < 8; i++) s += sRed[i];
      atomicAdd(scal + (isQ ? 0 : 1), s);
    }
    if (isK) atomicAdd(&scal[4 + tid], sCol[tid]);
  }
}

// ---------------------------------------------------------------------------
// gemm_mma: EPI_LN (fc, 3-term) and EPI_ATTN (q@KVS, 1-term, dp fused in mainloop)
// ---------------------------------------------------------------------------
#define EPI_LN   0
#define EPI_ATTN 4

template<int EPI, bool FULL>
__global__ void __launch_bounds__(NTHR, 2) gemm_mma(
    const __nv_bfloat16* __restrict__ Ah, const __nv_bfloat16* __restrict__ Al,
    const __nv_bfloat16* __restrict__ Wh, const __nv_bfloat16* __restrict__ Wl,
    const float* __restrict__ bias,
    float* __restrict__ Cf, __nv_bfloat16* __restrict__ Chi, __nv_bfloat16* __restrict__ Clo,
    const float* __restrict__ gamma, const float* __restrict__ beta,
    const float* __restrict__ scal,
    const __nv_bfloat16* __restrict__ Vh, const __nv_bfloat16* __restrict__ Vl,
    const __nv_bfloat16* __restrict__ Ph, const __nv_bfloat16* __restrict__ Pl)
{
  extern __shared__ char smem[];
  const uint32_t sb = smem_u32(smem);
  const int tid = threadIdx.x, w = tid >> 5, l = tid & 31;
  const int wrow = w >> 2, wcol = w & 3;
  const int m0 = blockIdx.x * TM;

  float* sS1 = (float*)(smem + SCR);
  float* sS2 = (float*)(smem + SCR + 1024);
  float* sDP = (float*)(smem + SCR + 2048);   // 64 floats (full dp per tile row)
  float* sKS = (float*)(smem + SCR + 3072);   // 256 floats (ks_sum)
  if (EPI == EPI_ATTN) sKS[tid] = scal[4 + tid];

  float acc[2][8][4];
#pragma unroll
  for (int a = 0; a < 2; a++)
#pragma unroll
    for (int b = 0; b < 8; b++)
#pragma unroll
      for (int c = 0; c < 4; c++) acc[a][b][c] = 0.f;

  // dp accumulator: thread owns row tid>>2, cols (tid&3)*8..+7 of each chunk
  float dpp = 0.f;
  const int dprow = tid >> 2;
  const int dpseg = tid & 3;

  auto issue = [&](int ch, int buf) {
    const uint32_t base = sb + buf * BUFB;
    const int k0 = ch * 32;
    {
      int row = tid >> 2, seg = tid & 3;
      int gr = m0 + row; if (gr > NROWS - 1) gr = NROWS - 1;
      size_t g = (size_t)gr * CH + k0 + seg * 8;
      uint32_t so = row * 80 + seg * 16;
      CP16(base + so, Ah + g);
      if (FULL) CP16(base + AB + so, Al + g);
    }
#pragma unroll
    for (int t = 0; t < 4; t++) {
      int idx = tid + t * 256;
      int row = idx >> 2, seg = idx & 3;
      size_t g = (size_t)row * CH + k0 + seg * 8;
      uint32_t so = row * 80 + seg * 16;
      CP16(base + 2 * AB + so, Wh + g);
      if (FULL) CP16(base + 2 * AB + WB + so, Wl + g);
    }
  };

  issue(0, 0); CP_COMMIT();
#pragma unroll
  for (int ch = 0; ch < 8; ch++) {
    if (ch < 7) { issue(ch + 1, (ch + 1) & 1); CP_COMMIT(); CP_WAIT(1); }
    else CP_WAIT(0);
    __syncthreads();
    const uint32_t base = sb + (ch & 1) * BUFB;
    if (EPI == EPI_ATTN) {
      // dp partial: q smem tile row dprow, cols dpseg*8..+7 against sKS
      const int k0 = ch * 32;
      uint4 qv = *(const uint4*)(smem + (ch & 1) * BUFB + dprow * 80 + dpseg * 16);
      float2 q0 = bf2f2(qv.x), q1 = bf2f2(qv.y), q2 = bf2f2(qv.z), q3 = bf2f2(qv.w);
      const float* ks = sKS + k0 + dpseg * 8;
      dpp = fmaf(q0.x, ks[0], dpp); dpp = fmaf(q0.y, ks[1], dpp);
      dpp = fmaf(q1.x, ks[2], dpp); dpp = fmaf(q1.y, ks[3], dpp);
      dpp = fmaf(q2.x, ks[4], dpp); dpp = fmaf(q2.y, ks[5], dpp);
      dpp = fmaf(q3.x, ks[6], dpp); dpp = fmaf(q3.y, ks[7], dpp);
    }
#pragma unroll
    for (int kt = 0; kt < 2; kt++) {
      uint32_t ah[2][4], al_[2][4];
#pragma unroll
      for (int mt = 0; mt < 2; mt++) {
        int row = wrow * 32 + mt * 16 + (l & 15);
        int col = kt * 16 + ((l >> 4) << 3);
        uint32_t off = row * 80 + col * 2;
        ldm_x4(ah[mt], base + off);
        if (FULL) ldm_x4(al_[mt], base + AB + off);
      }
#pragma unroll
      for (int ntp = 0; ntp < 4; ntp++) {
        int n = wcol * 64 + ntp * 16 + ((l >> 4) << 3) + (l & 7);
        int col = kt * 16 + ((l >> 3) & 1) * 8;
        uint32_t off = n * 80 + col * 2;
        uint32_t bh4[4], bl4[4];
        ldm_x4(bh4, base + 2 * AB + off);
        if (FULL) {
          ldm_x4(bl4, base + 2 * AB + WB + off);
          MMA_BLOCK(acc, ntp, ah, al_, bh4, bl4);
        } else {
          MMA_BLOCK1(acc, ntp, ah, bh4);
        }
      }
    }
    __syncthreads();
  }
  if (EPI == EPI_ATTN) {
    // reduce dp over the 4 col-segments (lanes l&3)
    dpp += __shfl_xor_sync(0xffffffffu, dpp, 1);
    dpp += __shfl_xor_sync(0xffffffffu, dpp, 2);
    if (dpseg == 0) sDP[dprow] = dpp;
    __syncthreads();
  }

  // epilogue: transform -> row stats -> LN+ReLU
  const int qlane = l >> 2;
  const int cbase = wcol * 64 + (l & 3) * 2;
  const float nF = (float)NROWS;
  float cN = 0.f;
  if (EPI == EPI_ATTN) cN = rsqrtf(scal[0] * scal[1]);
#pragma unroll
  for (int jr = 0; jr < 4; jr++) {
    const int lrow = wrow * 32 + (jr >> 1) * 16 + (jr & 1) * 8 + qlane;
    const int r = m0 + lrow;
    const bool valid = r < NROWS;
    float invr = 0.f;
    if (EPI == EPI_ATTN) invr = 1.f / fmaf(cN, sDP[lrow], nF);
    float s1 = 0.f, s2 = 0.f;
#pragma unroll
    for (int nt = 0; nt < 8; nt++) {
      const int col = cbase + nt * 8;
      if (EPI == EPI_LN) {
        float2 bs = *(const float2*)(bias + col);
        float y0 = ACCV(jr, nt, 0) + bs.x;
        float y1 = ACCV(jr, nt, 1) + bs.y;
        ACCV(jr, nt, 0) = y0; ACCV(jr, nt, 1) = y1;
        s1 += y0 + y1; s2 = fmaf(y0, y0, fmaf(y1, y1, s2));
      } else {
        uint32_t uvh = 0, uvl = 0, uph = 0, upl = 0;
        if (valid) {
          uvh = *(const uint32_t*)(Vh + (size_t)r * CH + col);
          uvl = *(const uint32_t*)(Vl + (size_t)r * CH + col);
          uph = *(const uint32_t*)(Ph + (size_t)r * CH + col);
          upl = *(const uint32_t*)(Pl + (size_t)r * CH + col);
        }
        float2 a0 = bf2f2(uvh), a1 = bf2f2(uvl);
        float2 b0 = bf2f2(uph), b1 = bf2f2(upl);
        float vvx = a0.x + a1.x, vvy = a0.y + a1.y;
        float ppx = b0.x + b1.x, ppy = b0.y + b1.y;
        float h0 = 0.5f * (fmaf(cN, ACCV(jr, nt, 0), nF * vvx) * invr + ppx);
        float h1 = 0.5f * (fmaf(cN, ACCV(jr, nt, 1), nF * vvy) * invr + ppy);
        ACCV(jr, nt, 0) = h0; ACCV(jr, nt, 1) = h1;
        s1 += h0 + h1; s2 = fmaf(h0, h0, fmaf(h1, h1, s2));
      }
    }
#pragma unroll
    for (int o = 1; o < 4; o <<= 1) {
      s1 += __shfl_xor_sync(0xffffffffu, s1, o);
      s2 += __shfl_xor_sync(0xffffffffu, s2, o);
    }
    if ((l & 3) == 0) { sS1[wcol * 64 + lrow] = s1; sS2[wcol * 64 + lrow] = s2; }
  }
  __syncthreads();
#pragma unroll
  for (int jr = 0; jr < 4; jr++) {
    const int lrow = wrow * 32 + (jr >> 1) * 16 + (jr & 1) * 8 + qlane;
    const int r = m0 + lrow;
    const bool valid = r < NROWS;
    const float s1 = sS1[lrow] + sS1[64 + lrow] + sS1[128 + lrow] + sS1[192 + lrow];
    const float s2 = sS2[lrow] + sS2[64 + lrow] + sS2[128 + lrow] + sS2[192 + lrow];
    const float mu = s1 * (1.f / CH);
    const float rs = rsqrtf(s2 * (1.f / CH) - mu * mu + 1e-5f);
#pragma unroll
    for (int nt = 0; nt < 8; nt++) {
      const int col = cbase + nt * 8;
      float2 gg = *(const float2*)(gamma + col);
      float2 bb = *(const float2*)(beta + col);
      float o0 = fmaxf((ACCV(jr, nt, 0) - mu) * rs * gg.x + bb.x, 0.f);
      float o1 = fmaxf((ACCV(jr, nt, 1) - mu) * rs * gg.y + bb.y, 0.f);
      if (valid) {
        if (Cf) *(float2*)(Cf + (size_t)r * CH + col) = make_float2(o0, o1);
        if (Chi) {
          uint32_t hi, lo;
          packhl(o0, o1, hi, lo);
          *(uint32_t*)(Chi + (size_t)r * CH + col) = hi;
          *(uint32_t*)(Clo + (size_t)r * CH + col) = lo;
        }
      }
    }
  }
}

// ---------------------------------------------------------------------------
// MMA kvs (1-term bf16): part[s][m][d] quarters (m 128 x d 128). bf16 partials.
// ---------------------------------------------------------------------------
__global__ void __launch_bounds__(NTHR, 2) gemm_kvs(
    const __nv_bfloat16* __restrict__ Kh,
    const __nv_bfloat16* __restrict__ Vh,
    __nv_bfloat16* __restrict__ part)
{
  extern __shared__ char smem[];
  const uint32_t sb = smem_u32(smem);
  const int tid = threadIdx.x, w = tid >> 5, l = tid & 31;
  const int wrow = w >> 1, wcol = w & 1;
  const int m0 = blockIdx.x * 128;
  const int d0g = blockIdx.y * 128;
  const int n0 = blockIdx.z * (SLICE_CHUNKS * 32);

  float acc[2][8][4];
#pragma unroll
  for (int a = 0; a < 2; a++)
#pragma unroll
    for (int b = 0; b < 8; b++)
#pragma unroll
      for (int c = 0; c < 4; c++) acc[a][b][c] = 0.f;

  auto issue = [&](int ch, int buf) {
    const uint32_t base = sb + buf * KBUF;
    const int nb = n0 + ch * 32;
#pragma unroll
    for (int t = 0; t < 2; t++) {
      int idx = tid + t * 256;
      int row = idx >> 4, seg = idx & 15;
      int gn = nb + row;
      uint32_t vb = (gn < NROWS) ? 16u : 0u;
      if (gn > NROWS - 1) gn = NROWS - 1;
      uint32_t so = row * KA_STR + seg * 16;
      size_t gk = (size_t)gn * CH + m0 + seg * 8;
      size_t gv = (size_t)gn * CH + d0g + seg * 8;
      CP16Z(base + so, Kh + gk, vb);
      CP16Z(base + KAB + so, Vh + gv, vb);
    }
  };

  issue(0, 0); CP_COMMIT();
  issue(1, 1); CP_COMMIT();
  for (int ch = 0; ch < SLICE_CHUNKS; ch++) {
    if (ch + 1 < SLICE_CHUNKS) CP_WAIT(1); else CP_WAIT(0);
    __syncthreads();
    if (ch + 2 < SLICE_CHUNKS) { issue(ch + 2, (ch + 2) % 3); CP_COMMIT(); }
    const uint32_t base = sb + (ch % 3) * KBUF;
#pragma unroll
    for (int kt = 0; kt < 2; kt++) {
      const int k0 = kt * 16;
      uint32_t ah[2][4];
#pragma unroll
      for (int mt = 0; mt < 2; mt++) {
        int krow = k0 + (l & 7) + ((l >> 4) << 3);
        int mcol = wrow * 32 + mt * 16 + ((l >> 3) & 1) * 8;
        uint32_t off = krow * KA_STR + mcol * 2;
        ldm_x4t(ah[mt], base + off);
      }
#pragma unroll
      for (int ntp = 0; ntp < 4; ntp++) {
        int dd = wcol * 64 + ntp * 16 + ((l >> 4) << 3);
        int krow = k0 + (l & 7) + ((l >> 3) & 1) * 8;
        uint32_t off = krow * KA_STR + dd * 2;
        uint32_t bh4[4];
        ldm_x4t(bh4, base + KAB + off);
        MMA_BLOCK1(acc, ntp, ah, bh4);
      }
    }
    __syncthreads();
  }

  __nv_bfloat16* dst = part + (size_t)blockIdx.z * (CH * CH);
  const int qlane = l >> 2;
  const int cbase = wcol * 64 + (l & 3) * 2;
#pragma unroll
  for (int jr = 0; jr < 4; jr++) {
    int m = m0 + wrow * 32 + (jr >> 1) * 16 + (jr & 1) * 8 + qlane;
#pragma unroll
    for (int nt = 0; nt < 8; nt++) {
      int d = d0g + cbase + nt * 8;
      *(uint32_t*)(dst + (size_t)m * CH + d) = packh(ACCV(jr, nt, 0), ACCV(jr, nt, 1));
    }
  }
}

// sum bf16 slices; write TRANSPOSED hi bf16
__global__ void kvs_reduce(const __nv_bfloat16* __restrict__ part,
                           __nv_bfloat16* __restrict__ bth) {
  int idx = blockIdx.x * blockDim.x + threadIdx.x;
  if (idx < CH * CH) {
    int m = idx >> 8, d = idx & 255;
    float s = 0.f;
#pragma unroll
    for (int ss = 0; ss < NSLICE; ss++)
      s += __bfloat162float(part[(size_t)ss * CH * CH + idx]);
    bth[d * CH + m] = __float2bfloat16(s);
  }
}

// ---------------------------------------------------------------------------
extern "C" void kernel_launch(void* const* d_in, const int* in_sizes, int n_in,
                              void* d_out, int out_size) {
  (void)in_sizes; (void)n_in; (void)out_size;
  const float* x    = (const float*)d_in[0];
  const float* fc_w = (const float*)d_in[1];
  const float* fc_b = (const float*)d_in[2];
  const float* Wq_w = (const float*)d_in[3];
  const float* Wq_b = (const float*)d_in[4];
  const float* Wk_w = (const float*)d_in[5];
  const float* Wk_b = (const float*)d_in[6];
  const float* Wv_w = (const float*)d_in[7];
  const float* Wv_b = (const float*)d_in[8];
  const float* ln_g = (const float*)d_in[9];
  const float* ln_b = (const float*)d_in[10];
  float* out = (float*)d_out;

  float *scal;
  __nv_bfloat16 *part, *xh, *xl, *ahh, *ahl, *bhh, *bhl, *qh, *kh, *vh, *vl, *wh, *wl, *bth;
  cudaGetSymbolAddress((void**)&part, g_part);
  cudaGetSymbolAddress((void**)&scal, g_scal);
  cudaGetSymbolAddress((void**)&xh, g_xh);  cudaGetSymbolAddress((void**)&xl, g_xl);
  cudaGetSymbolAddress((void**)&ahh, g_ahh); cudaGetSymbolAddress((void**)&ahl, g_ahl);
  cudaGetSymbolAddress((void**)&bhh, g_bhh); cudaGetSymbolAddress((void**)&bhl, g_bhl);
  cudaGetSymbolAddress((void**)&qh, g_qh);
  cudaGetSymbolAddress((void**)&kh, g_kh);
  cudaGetSymbolAddress((void**)&vh, g_vh);  cudaGetSymbolAddress((void**)&vl, g_vl);
  cudaGetSymbolAddress((void**)&wh, g_wh);  cudaGetSymbolAddress((void**)&wl, g_wl);
  cudaGetSymbolAddress((void**)&bth, g_bth);

  cudaFuncSetAttribute(gemm_mma<EPI_LN, true>,    cudaFuncAttributeMaxDynamicSharedMemorySize, SMEM_SZ);
  cudaFuncSetAttribute(gemm_mma<EPI_ATTN, false>, cudaFuncAttributeMaxDynamicSharedMemorySize, SMEM_SZ);
  cudaFuncSetAttribute(gemm_qkv, cudaFuncAttributeMaxDynamicSharedMemorySize, SMEM_SZ);
  cudaFuncSetAttribute(gemm_kvs, cudaFuncAttributeMaxDynamicSharedMemorySize, KSMEM);

  const int WSZ = CH * CH;
  split7_kernel<<<dim3(WSZ / 256, 7), 256>>>(fc_w, Wq_w, Wk_w, Wv_w, wh, wl);
  split_kernel<<<(NROWS * CH + 255) / 256, 256>>>(x, xh, xl, NROWS * CH);

  gemm_mma<EPI_LN, true><<<TGRID, NTHR, SMEM_SZ>>>(
      xh, xl, wh, wl, fc_b, nullptr, ahh, ahl, ln_g, ln_b,
      nullptr, nullptr, nullptr, nullptr, nullptr);

  for (int L = 0; L < 2; L++) {
    const __nv_bfloat16* hh = L ? bhh : ahh;
    const __nv_bfloat16* hl = L ? bhl : ahl;
    float* ob = L ? out : nullptr;
    __nv_bfloat16* obh = L ? nullptr : bhh;
    __nv_bfloat16* obl = L ? nullptr : bhl;
    const size_t bo = (size_t)L * CH;
    const int wo = 1 + 3 * L;

    zero_kernel<<<1, CH + 4>>>(scal, CH + 4);
    gemm_qkv<<<dim3(TGRID, 3), NTHR, SMEM_SZ>>>(
        hh, hl, wh + (size_t)wo * WSZ, wl + (size_t)wo * WSZ,
        Wq_b + bo, Wk_b + bo, Wv_b + bo,
        qh, kh, vh, vl, scal);
    gemm_kvs<<<dim3(2, 2, NSLICE), NTHR, KSMEM>>>(kh, vh, part);
    kvs_reduce<<<64, 1024>>>(part, bth);
    gemm_mma<EPI_ATTN, false><<<TGRID, NTHR, SMEM_SZ>>>(
        qh, nullptr, bth, nullptr, nullptr, ob, obh, obl,
        ln_g + (size_t)(L + 1) * CH, ln_b + (size_t)(L + 1) * CH,
        scal, vh, vl, hh, hl);
  }
}

// round 17
// speedup vs baseline: 4.3098x; 1.0462x over previous
#include <cuda_runtime.h>
#include <cuda_bf16.h>
#include <cstdint>

#define NROWS 100000
#define CH 256
#define NTHR 256
// ---- MMA gemm params (BM=64 x BN=256, occ 2) ----
#define TM 64
#define TGRID ((NROWS + TM - 1) / TM)   // 1563
#define AB (64 * 80)
#define WB (256 * 80)
#define BUFB (2 * AB + 2 * WB)
#define SCR (2 * BUFB)
#define SMEM_SZ (SCR + 4096)
// ---- kvs MMA params (1-term) ----
#define NSLICE 74
#define SLICE_CHUNKS 43
#define KA_STR 272
#define KAB (32 * KA_STR)
#define KBUF (2 * KAB)
#define KSMEM (3 * KBUF)

// ---------------- scratch -----------------------------------------------------
__device__ __nv_bfloat16 g_part[(size_t)NSLICE * CH * CH];
__device__ float g_scal[CH + 4];
__device__ __nv_bfloat16 g_ahh[(size_t)NROWS * CH], g_ahl[(size_t)NROWS * CH];
__device__ __nv_bfloat16 g_bhh[(size_t)NROWS * CH], g_bhl[(size_t)NROWS * CH];
__device__ __nv_bfloat16 g_qh[(size_t)NROWS * CH];
__device__ __nv_bfloat16 g_kh[(size_t)NROWS * CH];
__device__ __nv_bfloat16 g_vh[(size_t)NROWS * CH], g_vl[(size_t)NROWS * CH];
__device__ __nv_bfloat16 g_wh[7 * 65536], g_wl[7 * 65536];
__device__ __nv_bfloat16 g_bth[65536];

// ---------------- helpers ------------------------------------------------------
__device__ __forceinline__ uint32_t smem_u32(const void* p) {
  uint32_t a;
  asm("{ .reg .u64 t; cvta.to.shared.u64 t, %1; cvt.u32.u64 %0, t; }" : "=r"(a) : "l"(p));
  return a;
}
#define CP16(dst, src) \
  asm volatile("cp.async.cg.shared.global [%0], [%1], 16;" :: "r"(dst), "l"(src))
#define CP16Z(dst, src, vb) \
  asm volatile("cp.async.cg.shared.global [%0], [%1], 16, %2;" :: "r"(dst), "l"(src), "r"(vb))
#define CP_COMMIT() asm volatile("cp.async.commit_group;" ::: "memory")
#define CP_WAIT(n) asm volatile("cp.async.wait_group %0;" :: "n"(n) : "memory")

__device__ __forceinline__ void ldm_x4(uint32_t* r, uint32_t addr) {
  asm volatile("ldmatrix.sync.aligned.m8n8.x4.shared.b16 {%0,%1,%2,%3}, [%4];"
               : "=r"(r[0]), "=r"(r[1]), "=r"(r[2]), "=r"(r[3]) : "r"(addr));
}
__device__ __forceinline__ void ldm_x4t(uint32_t* r, uint32_t addr) {
  asm volatile("ldmatrix.sync.aligned.m8n8.x4.trans.shared.b16 {%0,%1,%2,%3}, [%4];"
               : "=r"(r[0]), "=r"(r[1]), "=r"(r[2]), "=r"(r[3]) : "r"(addr));
}
__device__ __forceinline__ void mma_bf16(float* c, const uint32_t* a, const uint32_t* b) {
  asm volatile(
      "mma.sync.aligned.m16n8k16.row.col.f32.bf16.bf16.f32 "
      "{%0,%1,%2,%3}, {%4,%5,%6,%7}, {%8,%9}, {%0,%1,%2,%3};"
      : "+f"(c[0]), "+f"(c[1]), "+f"(c[2]), "+f"(c[3])
      : "r"(a[0]), "r"(a[1]), "r"(a[2]), "r"(a[3]), "r"(b[0]), "r"(b[1]));
}
#define MMA_BLOCK(acc, ntp, ah, al_, bh4, bl4) do { \
  mma_bf16(acc[0][2*(ntp)],     ah[0],  bh4);     \
  mma_bf16(acc[1][2*(ntp)],     ah[1],  bh4);     \
  mma_bf16(acc[0][2*(ntp) + 1], ah[0],  bh4 + 2); \
  mma_bf16(acc[1][2*(ntp) + 1], ah[1],  bh4 + 2); \
  mma_bf16(acc[0][2*(ntp)],     ah[0],  bl4);     \
  mma_bf16(acc[1][2*(ntp)],     ah[1],  bl4);     \
  mma_bf16(acc[0][2*(ntp) + 1], ah[0],  bl4 + 2); \
  mma_bf16(acc[1][2*(ntp) + 1], ah[1],  bl4 + 2); \
  mma_bf16(acc[0][2*(ntp)],     al_[0], bh4);     \
  mma_bf16(acc[1][2*(ntp)],     al_[1], bh4);     \
  mma_bf16(acc[0][2*(ntp) + 1], al_[0], bh4 + 2); \
  mma_bf16(acc[1][2*(ntp) + 1], al_[1], bh4 + 2); \
} while (0)
#define MMA_BLOCK1(acc, ntp, ah, bh4) do { \
  mma_bf16(acc[0][2*(ntp)],     ah[0],  bh4);     \
  mma_bf16(acc[1][2*(ntp)],     ah[1],  bh4);     \
  mma_bf16(acc[0][2*(ntp) + 1], ah[0],  bh4 + 2); \
  mma_bf16(acc[1][2*(ntp) + 1], ah[1],  bh4 + 2); \
} while (0)

__device__ __forceinline__ float wredf(float v) {
#pragma unroll
  for (int o = 16; o > 0; o >>= 1) v += __shfl_xor_sync(0xffffffffu, v, o);
  return v;
}
__device__ __forceinline__ unsigned short bfb(__nv_bfloat16 h) {
  return *reinterpret_cast<unsigned short*>(&h);
}
__device__ __forceinline__ void packhl(float v0, float v1, uint32_t& hi, uint32_t& lo) {
  __nv_bfloat16 h0 = __float2bfloat16(v0), h1 = __float2bfloat16(v1);
  __nv_bfloat16 l0 = __float2bfloat16(v0 - __bfloat162float(h0));
  __nv_bfloat16 l1 = __float2bfloat16(v1 - __bfloat162float(h1));
  hi = (uint32_t)bfb(h0) | ((uint32_t)bfb(h1) << 16);
  lo = (uint32_t)bfb(l0) | ((uint32_t)bfb(l1) << 16);
}
__device__ __forceinline__ uint32_t packh(float v0, float v1) {
  __nv_bfloat16 h0 = __float2bfloat16(v0), h1 = __float2bfloat16(v1);
  return (uint32_t)bfb(h0) | ((uint32_t)bfb(h1) << 16);
}
__device__ __forceinline__ float2 bf2f2(uint32_t u) {
  __nv_bfloat162 b = *reinterpret_cast<__nv_bfloat162*>(&u);
  return __bfloat1622float2(b);
}

// ---------------------------------------------------------------------------
// one launch splits all 7 weight matrices; y selects the source
__global__ void split7_kernel(const float* __restrict__ fcw,
                              const float* __restrict__ Wq,
                              const float* __restrict__ Wk,
                              const float* __restrict__ Wv,
                              __nv_bfloat16* __restrict__ wh,
                              __nv_bfloat16* __restrict__ wl) {
  const int WSZ = CH * CH;
  int y = blockIdx.y;
  const float* src;
  switch (y) {
    case 0: src = fcw; break;
    case 1: src = Wq; break;
    case 2: src = Wk; break;
    case 3: src = Wv; break;
    case 4: src = Wq + WSZ; break;
    case 5: src = Wk + WSZ; break;
    default: src = Wv + WSZ; break;
  }
  int i = blockIdx.x * blockDim.x + threadIdx.x;
  float x = src[i];
  __nv_bfloat16 h = __float2bfloat16(x);
  wh[(size_t)y * WSZ + i] = h;
  wl[(size_t)y * WSZ + i] = __float2bfloat16(x - __bfloat162float(h));
}
__global__ void zero_kernel(float* p, int n) {
  int i = blockIdx.x * blockDim.x + threadIdx.x;
  if (i < n) p[i] = 0.f;
}

#define ACCV(jr, nt, c) acc[(jr) >> 1][nt][(((jr) & 1) << 1) + (c)]

// ---------------------------------------------------------------------------
// fc GEMM with fused x split: A = fp32 x (LDG + in-register hi/lo pack + STS),
// W = bf16 hi/lo via cp.async. 3-term. Epilogue: bias + LN + ReLU -> hi/lo out.
// ---------------------------------------------------------------------------
__global__ void __launch_bounds__(NTHR, 2) gemm_fc(
    const float* __restrict__ Xf,
    const __nv_bfloat16* __restrict__ Wh, const __nv_bfloat16* __restrict__ Wl,
    const float* __restrict__ bias,
    __nv_bfloat16* __restrict__ Chi, __nv_bfloat16* __restrict__ Clo,
    const float* __restrict__ gamma, const float* __restrict__ beta)
{
  extern __shared__ char smem[];
  const uint32_t sb = smem_u32(smem);
  const int tid = threadIdx.x, w = tid >> 5, l = tid & 31;
  const int wrow = w >> 2, wcol = w & 3;
  const int m0 = blockIdx.x * TM;

  float* sS1 = (float*)(smem + SCR);
  float* sS2 = (float*)(smem + SCR + 1024);

  float acc[2][8][4];
#pragma unroll
  for (int a = 0; a < 2; a++)
#pragma unroll
    for (int b = 0; b < 8; b++)
#pragma unroll
      for (int c = 0; c < 4; c++) acc[a][b][c] = 0.f;

  const int arow = tid >> 2, aseg = tid & 3;
  int gr = m0 + arow; if (gr > NROWS - 1) gr = NROWS - 1;
  const float* xrow = Xf + (size_t)gr * CH + aseg * 8;
  const uint32_t aso = arow * 80 + aseg * 16;

  float xr[8];
  auto loadA = [&](int ch) {
    float4 a = *(const float4*)(xrow + ch * 32);
    float4 b = *(const float4*)(xrow + ch * 32 + 4);
    xr[0] = a.x; xr[1] = a.y; xr[2] = a.z; xr[3] = a.w;
    xr[4] = b.x; xr[5] = b.y; xr[6] = b.z; xr[7] = b.w;
  };
  auto stsA = [&](int buf) {
    uint32_t hi[4], lo[4];
#pragma unroll
    for (int j = 0; j < 4; j++) packhl(xr[2 * j], xr[2 * j + 1], hi[j], lo[j]);
    *(uint4*)(smem + buf * BUFB + aso) = make_uint4(hi[0], hi[1], hi[2], hi[3]);
    *(uint4*)(smem + buf * BUFB + AB + aso) = make_uint4(lo[0], lo[1], lo[2], lo[3]);
  };
  auto issueW = [&](int ch, int buf) {
    const uint32_t base = sb + buf * BUFB;
    const int k0 = ch * 32;
#pragma unroll
    for (int t = 0; t < 4; t++) {
      int idx = tid + t * 256;
      int row = idx >> 2, seg = idx & 3;
      size_t g = (size_t)row * CH + k0 + seg * 8;
      uint32_t so = row * 80 + seg * 16;
      CP16(base + 2 * AB + so, Wh + g);
      CP16(base + 2 * AB + WB + so, Wl + g);
    }
  };

  loadA(0);
  issueW(0, 0); CP_COMMIT();
#pragma unroll
  for (int ch = 0; ch < 8; ch++) {
    stsA(ch & 1);
    if (ch < 7) { issueW(ch + 1, (ch + 1) & 1); CP_COMMIT(); loadA(ch + 1); CP_WAIT(1); }
    else CP_WAIT(0);
    __syncthreads();
    const uint32_t base = sb + (ch & 1) * BUFB;
#pragma unroll
    for (int kt = 0; kt < 2; kt++) {
      uint32_t ah[2][4], al_[2][4];
#pragma unroll
      for (int mt = 0; mt < 2; mt++) {
        int row = wrow * 32 + mt * 16 + (l & 15);
        int col = kt * 16 + ((l >> 4) << 3);
        uint32_t off = row * 80 + col * 2;
        ldm_x4(ah[mt], base + off);
        ldm_x4(al_[mt], base + AB + off);
      }
#pragma unroll
      for (int ntp = 0; ntp < 4; ntp++) {
        int n = wcol * 64 + ntp * 16 + ((l >> 4) << 3) + (l & 7);
        int col = kt * 16 + ((l >> 3) & 1) * 8;
        uint32_t off = n * 80 + col * 2;
        uint32_t bh4[4], bl4[4];
        ldm_x4(bh4, base + 2 * AB + off);
        ldm_x4(bl4, base + 2 * AB + WB + off);
        MMA_BLOCK(acc, ntp, ah, al_, bh4, bl4);
      }
    }
    __syncthreads();
  }

  // epilogue: bias -> row stats -> LN+ReLU -> hi/lo
  const int qlane = l >> 2;
  const int cbase = wcol * 64 + (l & 3) * 2;
#pragma unroll
  for (int jr = 0; jr < 4; jr++) {
    const int lrow = wrow * 32 + (jr >> 1) * 16 + (jr & 1) * 8 + qlane;
    float s1 = 0.f, s2 = 0.f;
#pragma unroll
    for (int nt = 0; nt < 8; nt++) {
      const int col = cbase + nt * 8;
      float2 bs = *(const float2*)(bias + col);
      float y0 = ACCV(jr, nt, 0) + bs.x;
      float y1 = ACCV(jr, nt, 1) + bs.y;
      ACCV(jr, nt, 0) = y0; ACCV(jr, nt, 1) = y1;
      s1 += y0 + y1; s2 = fmaf(y0, y0, fmaf(y1, y1, s2));
    }
#pragma unroll
    for (int o = 1; o < 4; o <<= 1) {
      s1 += __shfl_xor_sync(0xffffffffu, s1, o);
      s2 += __shfl_xor_sync(0xffffffffu, s2, o);
    }
    if ((l & 3) == 0) { sS1[wcol * 64 + lrow] = s1; sS2[wcol * 64 + lrow] = s2; }
  }
  __syncthreads();
#pragma unroll
  for (int jr = 0; jr < 4; jr++) {
    const int lrow = wrow * 32 + (jr >> 1) * 16 + (jr & 1) * 8 + qlane;
    const int r = m0 + lrow;
    const bool valid = r < NROWS;
    const float s1 = sS1[lrow] + sS1[64 + lrow] + sS1[128 + lrow] + sS1[192 + lrow];
    const float s2 = sS2[lrow] + sS2[64 + lrow] + sS2[128 + lrow] + sS2[192 + lrow];
    const float mu = s1 * (1.f / CH);
    const float rs = rsqrtf(s2 * (1.f / CH) - mu * mu + 1e-5f);
#pragma unroll
    for (int nt = 0; nt < 8; nt++) {
      const int col = cbase + nt * 8;
      float2 gg = *(const float2*)(gamma + col);
      float2 bb = *(const float2*)(beta + col);
      float o0 = fmaxf((ACCV(jr, nt, 0) - mu) * rs * gg.x + bb.x, 0.f);
      float o1 = fmaxf((ACCV(jr, nt, 1) - mu) * rs * gg.y + bb.y, 0.f);
      if (valid) {
        uint32_t hi, lo;
        packhl(o0, o1, hi, lo);
        *(uint32_t*)(Chi + (size_t)r * CH + col) = hi;
        *(uint32_t*)(Clo + (size_t)r * CH + col) = lo;
      }
    }
  }
}

// ---------------------------------------------------------------------------
// fused QKV GEMM: blockIdx.y selects {Q,K,V}. Q,K = 1-term bf16; V = 3-term.
// ---------------------------------------------------------------------------
__global__ void __launch_bounds__(NTHR, 2) gemm_qkv(
    const __nv_bfloat16* __restrict__ Ah, const __nv_bfloat16* __restrict__ Al,
    const __nv_bfloat16* __restrict__ WhB, const __nv_bfloat16* __restrict__ WlB,
    const float* __restrict__ bq, const float* __restrict__ bk, const float* __restrict__ bv,
    __nv_bfloat16* __restrict__ Qh,
    __nv_bfloat16* __restrict__ Kh,
    __nv_bfloat16* __restrict__ Vhh, __nv_bfloat16* __restrict__ Vll,
    float* __restrict__ scal)
{
  extern __shared__ char smem[];
  const uint32_t sb = smem_u32(smem);
  const int tid = threadIdx.x, w = tid >> 5, l = tid & 31;
  const int wrow = w >> 2, wcol = w & 3;
  const int m0 = blockIdx.x * TM;
  const int y = blockIdx.y;           // 0=Q 1=K 2=V
  const bool isQ = (y == 0), isK = (y == 1);
  const bool full = (y == 2);

  float* sCol = (float*)(smem + SCR + 2048);
  float* sRed = (float*)(smem + SCR + 3072);
  if (isK) sCol[tid] = 0.f;

  const __nv_bfloat16* Wh = WhB + (size_t)y * (CH * CH);
  const __nv_bfloat16* Wl = WlB + (size_t)y * (CH * CH);
  const float* bias = isQ ? bq : (isK ? bk : bv);
  __nv_bfloat16* Chi = isQ ? Qh : (isK ? Kh : Vhh);

  float acc[2][8][4];
#pragma unroll
  for (int a = 0; a < 2; a++)
#pragma unroll
    for (int b = 0; b < 8; b++)
#pragma unroll
      for (int c = 0; c < 4; c++) acc[a][b][c] = 0.f;

  auto issue = [&](int ch, int buf) {
    const uint32_t base = sb + buf * BUFB;
    const int k0 = ch * 32;
    {
      int row = tid >> 2, seg = tid & 3;
      int gr = m0 + row; if (gr > NROWS - 1) gr = NROWS - 1;
      size_t g = (size_t)gr * CH + k0 + seg * 8;
      uint32_t so = row * 80 + seg * 16;
      CP16(base + so, Ah + g);
      if (full) CP16(base + AB + so, Al + g);
    }
#pragma unroll
    for (int t = 0; t < 4; t++) {
      int idx = tid + t * 256;
      int row = idx >> 2, seg = idx & 3;
      size_t g = (size_t)row * CH + k0 + seg * 8;
      uint32_t so = row * 80 + seg * 16;
      CP16(base + 2 * AB + so, Wh + g);
      if (full) CP16(base + 2 * AB + WB + so, Wl + g);
    }
  };

  issue(0, 0); CP_COMMIT();
#pragma unroll
  for (int ch = 0; ch < 8; ch++) {
    if (ch < 7) { issue(ch + 1, (ch + 1) & 1); CP_COMMIT(); CP_WAIT(1); }
    else CP_WAIT(0);
    __syncthreads();
    const uint32_t base = sb + (ch & 1) * BUFB;
#pragma unroll
    for (int kt = 0; kt < 2; kt++) {
      uint32_t ah[2][4], al_[2][4];
#pragma unroll
      for (int mt = 0; mt < 2; mt++) {
        int row = wrow * 32 + mt * 16 + (l & 15);
        int col = kt * 16 + ((l >> 4) << 3);
        uint32_t off = row * 80 + col * 2;
        ldm_x4(ah[mt], base + off);
        if (full) ldm_x4(al_[mt], base + AB + off);
      }
#pragma unroll
      for (int ntp = 0; ntp < 4; ntp++) {
        int n = wcol * 64 + ntp * 16 + ((l >> 4) << 3) + (l & 7);
        int col = kt * 16 + ((l >> 3) & 1) * 8;
        uint32_t off = n * 80 + col * 2;
        uint32_t bh4[4], bl4[4];
        ldm_x4(bh4, base + 2 * AB + off);
        if (full) {
          ldm_x4(bl4, base + 2 * AB + WB + off);
          MMA_BLOCK(acc, ntp, ah, al_, bh4, bl4);
        } else {
          MMA_BLOCK1(acc, ntp, ah, bh4);
        }
      }
    }
    __syncthreads();
  }

  // epilogue
  const int qlane = l >> 2;
  const int cbase = wcol * 64 + (l & 3) * 2;
  float nrm = 0.f;
#pragma unroll
  for (int nt = 0; nt < 8; nt++) {
    const int col = cbase + nt * 8;
    float2 bs = *(const float2*)(bias + col);
    float cs0 = 0.f, cs1 = 0.f;
#pragma unroll
    for (int jr = 0; jr < 4; jr++) {
      int r = m0 + wrow * 32 + (jr >> 1) * 16 + (jr & 1) * 8 + qlane;
      bool valid = r < NROWS;
      float v0 = ACCV(jr, nt, 0) + bs.x;
      float v1 = ACCV(jr, nt, 1) + bs.y;
      if (valid) {
        if (y < 2) nrm = fmaf(v0, v0, fmaf(v1, v1, nrm));
        if (isK) { cs0 += v0; cs1 += v1; }
        if (full) {
          uint32_t hi, lo;
          packhl(v0, v1, hi, lo);
          *(uint32_t*)(Chi + (size_t)r * CH + col) = hi;
          *(uint32_t*)(Vll + (size_t)r * CH + col) = lo;
        } else {
          *(uint32_t*)(Chi + (size_t)r * CH + col) = packh(v0, v1);
        }
      }
    }
    if (isK) {
#pragma unroll
      for (int o = 4; o < 32; o <<= 1) {
        cs0 += __shfl_xor_sync(0xffffffffu, cs0, o);
        cs1 += __shfl_xor_sync(0xffffffffu, cs1, o);
      }
      if (qlane == 0) { atomicAdd(&sCol[col], cs0); atomicAdd(&sCol[col + 1], cs1); }
    }
  }
  if (y < 2) {
    float p = wredf(nrm);
    if (l == 0) sRed[w] = p;
    __syncthreads();
    if (tid == 0) {
      float s = 0.f;
#pragma unroll
      for (int i = 0; i < 8; i++) s += sRed[i];
      atomicAdd(scal + (isQ ? 0 : 1), s);
    }
    if (isK) atomicAdd(&scal[4 + tid], sCol[tid]);
  }
}

// ---------------------------------------------------------------------------
// gemm_attn: q@KVS 1-term, dp fused in mainloop, full attn+LN epilogue
// ---------------------------------------------------------------------------
__global__ void __launch_bounds__(NTHR, 2) gemm_attn(
    const __nv_bfloat16* __restrict__ Ah,
    const __nv_bfloat16* __restrict__ Wh,
    float* __restrict__ Cf, __nv_bfloat16* __restrict__ Chi, __nv_bfloat16* __restrict__ Clo,
    const float* __restrict__ gamma, const float* __restrict__ beta,
    const float* __restrict__ scal,
    const __nv_bfloat16* __restrict__ Vh, const __nv_bfloat16* __restrict__ Vl,
    const __nv_bfloat16* __restrict__ Ph, const __nv_bfloat16* __restrict__ Pl)
{
  extern __shared__ char smem[];
  const uint32_t sb = smem_u32(smem);
  const int tid = threadIdx.x, w = tid >> 5, l = tid & 31;
  const int wrow = w >> 2, wcol = w & 3;
  const int m0 = blockIdx.x * TM;

  float* sS1 = (float*)(smem + SCR);
  float* sS2 = (float*)(smem + SCR + 1024);
  float* sDP = (float*)(smem + SCR + 2048);
  float* sKS = (float*)(smem + SCR + 3072);
  sKS[tid] = scal[4 + tid];

  float acc[2][8][4];
#pragma unroll
  for (int a = 0; a < 2; a++)
#pragma unroll
    for (int b = 0; b < 8; b++)
#pragma unroll
      for (int c = 0; c < 4; c++) acc[a][b][c] = 0.f;

  float dpp = 0.f;
  const int dprow = tid >> 2;
  const int dpseg = tid & 3;

  auto issue = [&](int ch, int buf) {
    const uint32_t base = sb + buf * BUFB;
    const int k0 = ch * 32;
    {
      int row = tid >> 2, seg = tid & 3;
      int gr = m0 + row; if (gr > NROWS - 1) gr = NROWS - 1;
      size_t g = (size_t)gr * CH + k0 + seg * 8;
      uint32_t so = row * 80 + seg * 16;
      CP16(base + so, Ah + g);
    }
#pragma unroll
    for (int t = 0; t < 4; t++) {
      int idx = tid + t * 256;
      int row = idx >> 2, seg = idx & 3;
      size_t g = (size_t)row * CH + k0 + seg * 8;
      uint32_t so = row * 80 + seg * 16;
      CP16(base + 2 * AB + so, Wh + g);
    }
  };

  issue(0, 0); CP_COMMIT();
#pragma unroll
  for (int ch = 0; ch < 8; ch++) {
    if (ch < 7) { issue(ch + 1, (ch + 1) & 1); CP_COMMIT(); CP_WAIT(1); }
    else CP_WAIT(0);
    __syncthreads();
    const uint32_t base = sb + (ch & 1) * BUFB;
    {
      const int k0 = ch * 32;
      uint4 qv = *(const uint4*)(smem + (ch & 1) * BUFB + dprow * 80 + dpseg * 16);
      float2 q0 = bf2f2(qv.x), q1 = bf2f2(qv.y), q2 = bf2f2(qv.z), q3 = bf2f2(qv.w);
      const float* ks = sKS + k0 + dpseg * 8;
      dpp = fmaf(q0.x, ks[0], dpp); dpp = fmaf(q0.y, ks[1], dpp);
      dpp = fmaf(q1.x, ks[2], dpp); dpp = fmaf(q1.y, ks[3], dpp);
      dpp = fmaf(q2.x, ks[4], dpp); dpp = fmaf(q2.y, ks[5], dpp);
      dpp = fmaf(q3.x, ks[6], dpp); dpp = fmaf(q3.y, ks[7], dpp);
    }
#pragma unroll
    for (int kt = 0; kt < 2; kt++) {
      uint32_t ah[2][4];
#pragma unroll
      for (int mt = 0; mt < 2; mt++) {
        int row = wrow * 32 + mt * 16 + (l & 15);
        int col = kt * 16 + ((l >> 4) << 3);
        uint32_t off = row * 80 + col * 2;
        ldm_x4(ah[mt], base + off);
      }
#pragma unroll
      for (int ntp = 0; ntp < 4; ntp++) {
        int n = wcol * 64 + ntp * 16 + ((l >> 4) << 3) + (l & 7);
        int col = kt * 16 + ((l >> 3) & 1) * 8;
        uint32_t off = n * 80 + col * 2;
        uint32_t bh4[4];
        ldm_x4(bh4, base + 2 * AB + off);
        MMA_BLOCK1(acc, ntp, ah, bh4);
      }
    }
    __syncthreads();
  }
  dpp += __shfl_xor_sync(0xffffffffu, dpp, 1);
  dpp += __shfl_xor_sync(0xffffffffu, dpp, 2);
  if (dpseg == 0) sDP[dprow] = dpp;
  __syncthreads();

  const int qlane = l >> 2;
  const int cbase = wcol * 64 + (l & 3) * 2;
  const float nF = (float)NROWS;
  const float cN = rsqrtf(scal[0] * scal[1]);
#pragma unroll
  for (int jr = 0; jr < 4; jr++) {
    const int lrow = wrow * 32 + (jr >> 1) * 16 + (jr & 1) * 8 + qlane;
    const int r = m0 + lrow;
    const bool valid = r < NROWS;
    const float invr = 1.f / fmaf(cN, sDP[lrow], nF);
    float s1 = 0.f, s2 = 0.f;
#pragma unroll
    for (int nt = 0; nt < 8; nt++) {
      const int col = cbase + nt * 8;
      uint32_t uvh = 0, uvl = 0, uph = 0, upl = 0;
      if (valid) {
        uvh = *(const uint32_t*)(Vh + (size_t)r * CH + col);
        uvl = *(const uint32_t*)(Vl + (size_t)r * CH + col);
        uph = *(const uint32_t*)(Ph + (size_t)r * CH + col);
        upl = *(const uint32_t*)(Pl + (size_t)r * CH + col);
      }
      float2 a0 = bf2f2(uvh), a1 = bf2f2(uvl);
      float2 b0 = bf2f2(uph), b1 = bf2f2(upl);
      float vvx = a0.x + a1.x, vvy = a0.y + a1.y;
      float ppx = b0.x + b1.x, ppy = b0.y + b1.y;
      float h0 = 0.5f * (fmaf(cN, ACCV(jr, nt, 0), nF * vvx) * invr + ppx);
      float h1 = 0.5f * (fmaf(cN, ACCV(jr, nt, 1), nF * vvy) * invr + ppy);
      ACCV(jr, nt, 0) = h0; ACCV(jr, nt, 1) = h1;
      s1 += h0 + h1; s2 = fmaf(h0, h0, fmaf(h1, h1, s2));
    }
#pragma unroll
    for (int o = 1; o < 4; o <<= 1) {
      s1 += __shfl_xor_sync(0xffffffffu, s1, o);
      s2 += __shfl_xor_sync(0xffffffffu, s2, o);
    }
    if ((l & 3) == 0) { sS1[wcol * 64 + lrow] = s1; sS2[wcol * 64 + lrow] = s2; }
  }
  __syncthreads();
#pragma unroll
  for (int jr = 0; jr < 4; jr++) {
    const int lrow = wrow * 32 + (jr >> 1) * 16 + (jr & 1) * 8 + qlane;
    const int r = m0 + lrow;
    const bool valid = r < NROWS;
    const float s1 = sS1[lrow] + sS1[64 + lrow] + sS1[128 + lrow] + sS1[192 + lrow];
    const float s2 = sS2[lrow] + sS2[64 + lrow] + sS2[128 + lrow] + sS2[192 + lrow];
    const float mu = s1 * (1.f / CH);
    const float rs = rsqrtf(s2 * (1.f / CH) - mu * mu + 1e-5f);
#pragma unroll
    for (int nt = 0; nt < 8; nt++) {
      const int col = cbase + nt * 8;
      float2 gg = *(const float2*)(gamma + col);
      float2 bb = *(const float2*)(beta + col);
      float o0 = fmaxf((ACCV(jr, nt, 0) - mu) * rs * gg.x + bb.x, 0.f);
      float o1 = fmaxf((ACCV(jr, nt, 1) - mu) * rs * gg.y + bb.y, 0.f);
      if (valid) {
        if (Cf) *(float2*)(Cf + (size_t)r * CH + col) = make_float2(o0, o1);
        if (Chi) {
          uint32_t hi, lo;
          packhl(o0, o1, hi, lo);
          *(uint32_t*)(Chi + (size_t)r * CH + col) = hi;
          *(uint32_t*)(Clo + (size_t)r * CH + col) = lo;
        }
      }
    }
  }
}

// ---------------------------------------------------------------------------
// MMA kvs (1-term bf16): part[s][m][d] quarters (m 128 x d 128). bf16 partials.
// ---------------------------------------------------------------------------
__global__ void __launch_bounds__(NTHR, 2) gemm_kvs(
    const __nv_bfloat16* __restrict__ Kh,
    const __nv_bfloat16* __restrict__ Vh,
    __nv_bfloat16* __restrict__ part)
{
  extern __shared__ char smem[];
  const uint32_t sb = smem_u32(smem);
  const int tid = threadIdx.x, w = tid >> 5, l = tid & 31;
  const int wrow = w >> 1, wcol = w & 1;
  const int m0 = blockIdx.x * 128;
  const int d0g = blockIdx.y * 128;
  const int n0 = blockIdx.z * (SLICE_CHUNKS * 32);

  float acc[2][8][4];
#pragma unroll
  for (int a = 0; a < 2; a++)
#pragma unroll
    for (int b = 0; b < 8; b++)
#pragma unroll
      for (int c = 0; c < 4; c++) acc[a][b][c] = 0.f;

  auto issue = [&](int ch, int buf) {
    const uint32_t base = sb + buf * KBUF;
    const int nb = n0 + ch * 32;
#pragma unroll
    for (int t = 0; t < 2; t++) {
      int idx = tid + t * 256;
      int row = idx >> 4, seg = idx & 15;
      int gn = nb + row;
      uint32_t vb = (gn < NROWS) ? 16u : 0u;
      if (gn > NROWS - 1) gn = NROWS - 1;
      uint32_t so = row * KA_STR + seg * 16;
      size_t gk = (size_t)gn * CH + m0 + seg * 8;
      size_t gv = (size_t)gn * CH + d0g + seg * 8;
      CP16Z(base + so, Kh + gk, vb);
      CP16Z(base + KAB + so, Vh + gv, vb);
    }
  };

  issue(0, 0); CP_COMMIT();
  issue(1, 1); CP_COMMIT();
  for (int ch = 0; ch < SLICE_CHUNKS; ch++) {
    if (ch + 1 < SLICE_CHUNKS) CP_WAIT(1); else CP_WAIT(0);
    __syncthreads();
    if (ch + 2 < SLICE_CHUNKS) { issue(ch + 2, (ch + 2) % 3); CP_COMMIT(); }
    const uint32_t base = sb + (ch % 3) * KBUF;
#pragma unroll
    for (int kt = 0; kt < 2; kt++) {
      const int k0 = kt * 16;
      uint32_t ah[2][4];
#pragma unroll
      for (int mt = 0; mt < 2; mt++) {
        int krow = k0 + (l & 7) + ((l >> 4) << 3);
        int mcol = wrow * 32 + mt * 16 + ((l >> 3) & 1) * 8;
        uint32_t off = krow * KA_STR + mcol * 2;
        ldm_x4t(ah[mt], base + off);
      }
#pragma unroll
      for (int ntp = 0; ntp < 4; ntp++) {
        int dd = wcol * 64 + ntp * 16 + ((l >> 4) << 3);
        int krow = k0 + (l & 7) + ((l >> 3) & 1) * 8;
        uint32_t off = krow * KA_STR + dd * 2;
        uint32_t bh4[4];
        ldm_x4t(bh4, base + KAB + off);
        MMA_BLOCK1(acc, ntp, ah, bh4);
      }
    }
    __syncthreads();
  }

  __nv_bfloat16* dst = part + (size_t)blockIdx.z * (CH * CH);
  const int qlane = l >> 2;
  const int cbase = wcol * 64 + (l & 3) * 2;
#pragma unroll
  for (int jr = 0; jr < 4; jr++) {
    int m = m0 + wrow * 32 + (jr >> 1) * 16 + (jr & 1) * 8 + qlane;
#pragma unroll
    for (int nt = 0; nt < 8; nt++) {
      int d = d0g + cbase + nt * 8;
      *(uint32_t*)(dst + (size_t)m * CH + d) = packh(ACCV(jr, nt, 0), ACCV(jr, nt, 1));
    }
  }
}

// sum bf16 slices; write TRANSPOSED hi bf16
__global__ void kvs_reduce(const __nv_bfloat16* __restrict__ part,
                           __nv_bfloat16* __restrict__ bth) {
  int idx = blockIdx.x * blockDim.x + threadIdx.x;
  if (idx < CH * CH) {
    int m = idx >> 8, d = idx & 255;
    float s = 0.f;
#pragma unroll
    for (int ss = 0; ss < NSLICE; ss++)
      s += __bfloat162float(part[(size_t)ss * CH * CH + idx]);
    bth[d * CH + m] = __float2bfloat16(s);
  }
}

// ---------------------------------------------------------------------------
extern "C" void kernel_launch(void* const* d_in, const int* in_sizes, int n_in,
                              void* d_out, int out_size) {
  (void)in_sizes; (void)n_in; (void)out_size;
  const float* x    = (const float*)d_in[0];
  const float* fc_w = (const float*)d_in[1];
  const float* fc_b = (const float*)d_in[2];
  const float* Wq_w = (const float*)d_in[3];
  const float* Wq_b = (const float*)d_in[4];
  const float* Wk_w = (const float*)d_in[5];
  const float* Wk_b = (const float*)d_in[6];
  const float* Wv_w = (const float*)d_in[7];
  const float* Wv_b = (const float*)d_in[8];
  const float* ln_g = (const float*)d_in[9];
  const float* ln_b = (const float*)d_in[10];
  float* out = (float*)d_out;

  float *scal;
  __nv_bfloat16 *part, *ahh, *ahl, *bhh, *bhl, *qh, *kh, *vh, *vl, *wh, *wl, *bth;
  cudaGetSymbolAddress((void**)&part, g_part);
  cudaGetSymbolAddress((void**)&scal, g_scal);
  cudaGetSymbolAddress((void**)&ahh, g_ahh); cudaGetSymbolAddress((void**)&ahl, g_ahl);
  cudaGetSymbolAddress((void**)&bhh, g_bhh); cudaGetSymbolAddress((void**)&bhl, g_bhl);
  cudaGetSymbolAddress((void**)&qh, g_qh);
  cudaGetSymbolAddress((void**)&kh, g_kh);
  cudaGetSymbolAddress((void**)&vh, g_vh);  cudaGetSymbolAddress((void**)&vl, g_vl);
  cudaGetSymbolAddress((void**)&wh, g_wh);  cudaGetSymbolAddress((void**)&wl, g_wl);
  cudaGetSymbolAddress((void**)&bth, g_bth);

  cudaFuncSetAttribute(gemm_fc,   cudaFuncAttributeMaxDynamicSharedMemorySize, SMEM_SZ);
  cudaFuncSetAttribute(gemm_attn, cudaFuncAttributeMaxDynamicSharedMemorySize, SMEM_SZ);
  cudaFuncSetAttribute(gemm_qkv,  cudaFuncAttributeMaxDynamicSharedMemorySize, SMEM_SZ);
  cudaFuncSetAttribute(gemm_kvs,  cudaFuncAttributeMaxDynamicSharedMemorySize, KSMEM);

  const int WSZ = CH * CH;
  split7_kernel<<<dim3(WSZ / 256, 7), 256>>>(fc_w, Wq_w, Wk_w, Wv_w, wh, wl);

  gemm_fc<<<TGRID, NTHR, SMEM_SZ>>>(x, wh, wl, fc_b, ahh, ahl, ln_g, ln_b);

  for (int L = 0; L < 2; L++) {
    const __nv_bfloat16* hh = L ? bhh : ahh;
    const __nv_bfloat16* hl = L ? bhl : ahl;
    float* ob = L ? out : nullptr;
    __nv_bfloat16* obh = L ? nullptr : bhh;
    __nv_bfloat16* obl = L ? nullptr : bhl;
    const size_t bo = (size_t)L * CH;
    const int wo = 1 + 3 * L;

    zero_kernel<<<1, CH + 4>>>(scal, CH + 4);
    gemm_qkv<<<dim3(TGRID, 3), NTHR, SMEM_SZ>>>(
        hh, hl, wh + (size_t)wo * WSZ, wl + (size_t)wo * WSZ,
        Wq_b + bo, Wk_b + bo, Wv_b + bo,
        qh, kh, vh, vl, scal);
    gemm_kvs<<<dim3(2, 2, NSLICE), NTHR, KSMEM>>>(kh, vh, part);
    kvs_reduce<<<64, 1024>>>(part, bth);
    gemm_attn<<<TGRID, NTHR, SMEM_SZ>>>(
        qh, bth, ob, obh, obl,
        ln_g + (size_t)(L + 1) * CH, ln_b + (size_t)(L + 1) * CH,
        scal, vh, vl, hh, hl);
  }
}